// round 4
// baseline (speedup 1.0000x reference)
#include <cuda_runtime.h>
#include <cstdint>

// ---------------------------------------------------------------------------
// GroupVectorAttention — bf16 3-term split GEMMs (mma.m16n8k16, sm_80 PTX)
// + analytic BN1 folding. Error ~1e-5 (vs tf32's 8.4e-4), pipeline rebuilt:
// double-buffered A and B, one __syncthreads per K-chunk, pre-packed weights.
// ---------------------------------------------------------------------------

#define EPSV 1e-5f

static constexpr int Bb = 4, Nn = 4096, Mm = 16, Cd = 256;
static constexpr int R_ = Bb * Nn * Mm;       // 262144
static constexpr int BNp = Bb * Nn;           // 16384
static constexpr int STAT_BLOCKS = 256;
static constexpr int ATTN_BLOCKS = 512;

// smem (uint32 units): A 2x4096 | B 2x4096 | fp32 extras
static constexpr int SOFF_B = 8192;           // uint32 idx
static constexpr int SOFF_FX = 16384;         // fp32 extras base
static constexpr int FX_BIAS = 0, FX_W1F = 256, FX_B1F = 1024;
static constexpr int FX_S2 = 1280, FX_T2 = 1536, FX_DIFF = 1792; // 512 floats
static constexpr int DYN_SMEM = (16384 + 2304) * 4;              // 74752 B

// ------------------------- device scratch (static) -------------------------
__device__ float g_part1[STAT_BLOCKS * 12];
__device__ float g_w1f[2][Cd * 3];
__device__ float g_b1f[2][Cd];
__device__ float g_q[BNp * Cd];
__device__ float g_dm[(size_t)R_ * Cd];
__device__ float g_db[(size_t)R_ * Cd];
__device__ float g_k [(size_t)R_ * Cd];
__device__ float g_v [(size_t)R_ * Cd];
__device__ float g_we[(size_t)R_ * Cd];
__device__ float g_part2[ATTN_BLOCKS * 512];
__device__ float g_s2[Cd], g_t2[Cd];
// packed hi/lo bf16 weights: [mat(6)][nb(2)][chunk(8)][128 rows][32 u32]
__device__ uint32_t g_Bpk[6 * 2 * 8 * 4096];

// ----------------------------- PTX helpers ---------------------------------
__device__ __forceinline__ uint32_t smem_u32(const void* p) {
    uint32_t a;
    asm("{ .reg .u64 t; cvta.to.shared.u64 t, %1; cvt.u32.u64 %0, t; }"
        : "=r"(a) : "l"(p));
    return a;
}
__device__ __forceinline__ void cp16(uint32_t dst, const void* src) {
    asm volatile("cp.async.cg.shared.global [%0], [%1], 16;"
                 :: "r"(dst), "l"(src) : "memory");
}
__device__ __forceinline__ void cp_commit() {
    asm volatile("cp.async.commit_group;" ::: "memory");
}
template <int N>
__device__ __forceinline__ void cp_wait() {
    asm volatile("cp.async.wait_group %0;" :: "n"(N) : "memory");
}
__device__ __forceinline__ void mma_bf16(float* c, const uint32_t* a,
                                         const uint32_t* b) {
    asm volatile("mma.sync.aligned.m16n8k16.row.col.f32.bf16.bf16.f32 "
                 "{%0,%1,%2,%3}, {%4,%5,%6,%7}, {%8,%9}, {%0,%1,%2,%3};"
                 : "+f"(c[0]), "+f"(c[1]), "+f"(c[2]), "+f"(c[3])
                 : "r"(a[0]), "r"(a[1]), "r"(a[2]), "r"(a[3]),
                   "r"(b[0]), "r"(b[1]));
}
// pack (x0,x1) -> bf16x2 hi, and residual bf16x2 lo  (low half = x0)
__device__ __forceinline__ void cvt_hilo(float x0, float x1,
                                         uint32_t& hi, uint32_t& lo) {
    asm("cvt.rn.satfinite.bf16x2.f32 %0, %1, %2;" : "=r"(hi) : "f"(x1), "f"(x0));
    float h0 = __uint_as_float(hi << 16);
    float h1 = __uint_as_float(hi & 0xffff0000u);
    float r0 = x0 - h0, r1 = x1 - h1;
    asm("cvt.rn.satfinite.bf16x2.f32 %0, %1, %2;" : "=r"(lo) : "f"(r1), "f"(r0));
}
// packed layout: pair p (elements 2p,2p+1) of row n at u32 offset
//   n*32 + ((p ^ ((n&3)<<2)) << 1)   -> {hi, lo}
__device__ __forceinline__ int pk(int n, int p) {
    return n * 32 + (((p) ^ ((n & 3) << 2)) << 1);
}

// ------------------------------- K1: stats --------------------------------
__global__ void diffstats_kernel(const float* __restrict__ pts,
                                 const float* __restrict__ nbr) {
    float s[12];
#pragma unroll
    for (int i = 0; i < 12; i++) s[i] = 0.f;
    int tid = threadIdx.x;
    for (int r = blockIdx.x * blockDim.x + tid; r < R_; r += gridDim.x * blockDim.x) {
        int bn = r >> 4;
        float d[3];
#pragma unroll
        for (int j = 0; j < 3; j++) d[j] = pts[bn * 3 + j] - nbr[(size_t)r * 3 + j];
#pragma unroll
        for (int j = 0; j < 3; j++) s[j] += d[j];
#pragma unroll
        for (int j = 0; j < 3; j++)
#pragma unroll
            for (int k = 0; k < 3; k++) s[3 + j * 3 + k] += d[j] * d[k];
    }
    __shared__ float red[256];
    for (int comp = 0; comp < 12; comp++) {
        red[tid] = s[comp];
        __syncthreads();
        for (int off = 128; off > 0; off >>= 1) {
            if (tid < off) red[tid] += red[tid + off];
            __syncthreads();
        }
        if (tid == 0) g_part1[blockIdx.x * 12 + comp] = red[0];
        __syncthreads();
    }
}

// ------------------------------ K2: BN1 fold -------------------------------
__global__ void fold_kernel(const float* __restrict__ dm_w1, const float* __restrict__ dm_b1,
                            const float* __restrict__ dm_g,  const float* __restrict__ dm_be,
                            const float* __restrict__ db_w1, const float* __restrict__ db_b1,
                            const float* __restrict__ db_g,  const float* __restrict__ db_be) {
    __shared__ float st[12];
    __shared__ float mu[3], cov[9];
    int tid = threadIdx.x;
    if (tid < 12) {
        float a = 0.f;
        for (int b = 0; b < STAT_BLOCKS; b++) a += g_part1[b * 12 + tid];
        st[tid] = a / (float)R_;
    }
    __syncthreads();
    if (tid < 3) mu[tid] = st[tid];
    if (tid < 9) {
        int j = tid / 3, k = tid % 3;
        cov[tid] = st[3 + tid] - st[j] * st[k];
    }
    __syncthreads();
    int c = tid;
    for (int which = 0; which < 2; which++) {
        const float* w1 = which ? db_w1 : dm_w1;
        const float* b1 = which ? db_b1 : dm_b1;
        const float* gg = which ? db_g  : dm_g;
        const float* be = which ? db_be : dm_be;
        float w0 = w1[c * 3], w1v = w1[c * 3 + 1], w2v = w1[c * 3 + 2];
        float var = w0 * w0 * cov[0] + w1v * w1v * cov[4] + w2v * w2v * cov[8]
                  + 2.f * (w0 * w1v * cov[1] + w0 * w2v * cov[2] + w1v * w2v * cov[5]);
        float mdot = w0 * mu[0] + w1v * mu[1] + w2v * mu[2];
        float m = mdot + b1[c];
        float s = gg[c] * rsqrtf(var + EPSV);
        g_w1f[which][c * 3]     = w0 * s;
        g_w1f[which][c * 3 + 1] = w1v * s;
        g_w1f[which][c * 3 + 2] = w2v * s;
        g_b1f[which][c] = be[c] + s * (b1[c] - m);
    }
}

// ----------------------- weight prep: fp32 -> packed hi/lo bf16 -------------
__global__ void prep_weights(const float* __restrict__ q_w, const float* __restrict__ k_w,
                             const float* __restrict__ v_w, const float* __restrict__ dm_w2,
                             const float* __restrict__ db_w2, const float* __restrict__ lin_w) {
    int c = blockIdx.x, nb = blockIdx.y, mat = blockIdx.z;
    const float* W = mat == 0 ? q_w : mat == 1 ? k_w : mat == 2 ? v_w :
                     mat == 3 ? dm_w2 : mat == 4 ? db_w2 : lin_w;
    uint32_t* dst = g_Bpk + (((size_t)mat * 2 + nb) * 8 + c) * 4096;
    for (int e = threadIdx.x; e < 2048; e += 256) {
        int n = e >> 4, p = e & 15;
        const float* src = W + (size_t)(nb * 128 + n) * 256 + c * 32 + p * 2;
        uint32_t hi, lo;
        cvt_hilo(src[0], src[1], hi, lo);
        int off = pk(n, p);
        dst[off] = hi; dst[off + 1] = lo;
    }
}

// ----------------------- GEMM: bf16 split (m16n8k16 x3) --------------------
// CTA 128 rows x 128 cols (grid.y = nb), K=256 in 8 chunks of 32.
// 8 warps 2(row)x4(col); warp tile 64x32.
enum { AMODE_DIRECT = 0, AMODE_POS = 1, AMODE_BNRELU = 2 };

template <int AMODE>
__device__ __forceinline__ void load_aF(
    int tid, int rowBase, int kb,
    const float* __restrict__ A,
    const float* w1f_s, const float* b1f_s,
    const float* s2_s, const float* t2_s, const float* diff_s,
    float4 aF[4]) {
#pragma unroll
    for (int i = 0; i < 4; i++) {
        int f = tid + i * 256, row = f >> 3, kq = f & 7;
        float4 v;
        if (AMODE == AMODE_POS) {
            float d0 = diff_s[row * 4], d1 = diff_s[row * 4 + 1], d2 = diff_s[row * 4 + 2];
            float t[4];
#pragma unroll
            for (int j = 0; j < 4; j++) {
                int k = kb + kq * 4 + j;
                float h = fmaf(d0, w1f_s[k * 3],
                          fmaf(d1, w1f_s[k * 3 + 1],
                          fmaf(d2, w1f_s[k * 3 + 2], b1f_s[k])));
                t[j] = fmaxf(h, 0.f);
            }
            v = make_float4(t[0], t[1], t[2], t[3]);
        } else {
            v = *(const float4*)&A[(size_t)(rowBase + row) * 256 + kb + kq * 4];
            if (AMODE == AMODE_BNRELU) {
                int k = kb + kq * 4;
                v.x = fmaxf(fmaf(v.x, s2_s[k],     t2_s[k]),     0.f);
                v.y = fmaxf(fmaf(v.y, s2_s[k + 1], t2_s[k + 1]), 0.f);
                v.z = fmaxf(fmaf(v.z, s2_s[k + 2], t2_s[k + 2]), 0.f);
                v.w = fmaxf(fmaf(v.w, s2_s[k + 3], t2_s[k + 3]), 0.f);
            }
        }
        aF[i] = v;
    }
}

template <int AMODE>
__global__ void __launch_bounds__(256, 2)
gemm_mma(const float* __restrict__ A, const uint32_t* __restrict__ Bpk,
         const float* __restrict__ bias, float* __restrict__ Out,
         const float* __restrict__ pts, const float* __restrict__ nbr, int which) {
    extern __shared__ uint32_t sm[];
    float* fx     = (float*)(sm + SOFF_FX);
    float* bias_s = fx + FX_BIAS;
    float* w1f_s  = fx + FX_W1F;
    float* b1f_s  = fx + FX_B1F;
    float* s2_s   = fx + FX_S2;
    float* t2_s   = fx + FX_T2;
    float* diff_s = fx + FX_DIFF;

    int tid = threadIdx.x;
    int rowBase = blockIdx.x * 128;

    bias_s[tid] = bias[tid];
    if (AMODE == AMODE_POS) {
        const float* w1f = g_w1f[which];
        for (int i = tid; i < 768; i += 256) w1f_s[i] = w1f[i];
        b1f_s[tid] = g_b1f[which][tid];
        if (tid < 128) {
            int r = rowBase + tid, bn = r >> 4;
            diff_s[tid * 4 + 0] = pts[bn * 3 + 0] - nbr[(size_t)r * 3 + 0];
            diff_s[tid * 4 + 1] = pts[bn * 3 + 1] - nbr[(size_t)r * 3 + 1];
            diff_s[tid * 4 + 2] = pts[bn * 3 + 2] - nbr[(size_t)r * 3 + 2];
        }
    }
    if (AMODE == AMODE_BNRELU) {
        s2_s[tid] = g_s2[tid];
        t2_s[tid] = g_t2[tid];
    }
    __syncthreads();

    uint32_t smemB_addr = smem_u32(sm + SOFF_B);
    const uint32_t* BpkNb = Bpk + (size_t)blockIdx.y * 32768;

    auto cp_b = [&](int stage, int c) {
        const uint32_t* src = BpkNb + c * 4096;
        uint32_t dstb = smemB_addr + (uint32_t)stage * 16384u;
#pragma unroll
        for (int i = 0; i < 4; i++) {
            int e = tid + i * 256;
            cp16(dstb + (uint32_t)e * 16u, src + e * 4);
        }
        cp_commit();
    };
    auto sts_a = [&](int stage, const float4* aF) {
#pragma unroll
        for (int i = 0; i < 4; i++) {
            int f = tid + i * 256, row = f >> 3, kq = f & 7;
            uint32_t h0, l0, h1, l1;
            cvt_hilo(aF[i].x, aF[i].y, h0, l0);
            cvt_hilo(aF[i].z, aF[i].w, h1, l1);
            int off = row * 32 + ((((2 * kq) ^ ((row & 3) << 2))) << 1);
            *(uint4*)&sm[stage * 4096 + off] = make_uint4(h0, l0, h1, l1);
        }
    };

    // prologue
    float4 aF[4];
    load_aF<AMODE>(tid, rowBase, 0, A, w1f_s, b1f_s, s2_s, t2_s, diff_s, aF);
    sts_a(0, aF);
    cp_b(0, 0);
    cp_b(1, 1);
    cp_wait<1>();
    __syncthreads();

    int lane = tid & 31, w = tid >> 5;
    int wm = w & 1, wn = w >> 1;
    int la3 = lane & 3, lg = lane >> 2;
    int sw = (lg & 3) << 2;

    float acc[4][4][4];
#pragma unroll
    for (int mt = 0; mt < 4; mt++)
#pragma unroll
        for (int nt = 0; nt < 4; nt++)
#pragma unroll
            for (int r = 0; r < 4; r++) acc[mt][nt][r] = 0.f;

    for (int c = 0; c < 8; c++) {
        int stage = c & 1;
        if (c < 7)
            load_aF<AMODE>(tid, rowBase, (c + 1) * 32, A,
                           w1f_s, b1f_s, s2_s, t2_s, diff_s, aF);
        const uint32_t* As = sm + stage * 4096;
        const uint32_t* Bs = sm + SOFF_B + stage * 4096;
#pragma unroll
        for (int ks = 0; ks < 2; ks++) {
            int p0 = ks * 8 + la3;
            int o0 = ((p0 ^ sw) << 1), o4 = (((p0 + 4) ^ sw) << 1);
            uint32_t bh[4][2], bl[4][2];
#pragma unroll
            for (int nt = 0; nt < 4; nt++) {
                int nb32 = (wn * 32 + nt * 8 + lg) * 32;
                uint2 t0 = *(const uint2*)&Bs[nb32 + o0];
                uint2 t1 = *(const uint2*)&Bs[nb32 + o4];
                bh[nt][0] = t0.x; bl[nt][0] = t0.y;
                bh[nt][1] = t1.x; bl[nt][1] = t1.y;
            }
#pragma unroll
            for (int mt = 0; mt < 4; mt++) {
                int r32 = (wm * 64 + mt * 16 + lg) * 32;
                uint2 A0 = *(const uint2*)&As[r32 + o0];
                uint2 A1 = *(const uint2*)&As[r32 + 256 + o0];
                uint2 A2 = *(const uint2*)&As[r32 + o4];
                uint2 A3 = *(const uint2*)&As[r32 + 256 + o4];
                uint32_t ah[4] = {A0.x, A1.x, A2.x, A3.x};
                uint32_t al[4] = {A0.y, A1.y, A2.y, A3.y};
#pragma unroll
                for (int nt = 0; nt < 4; nt++) mma_bf16(acc[mt][nt], ah, bh[nt]);
#pragma unroll
                for (int nt = 0; nt < 4; nt++) mma_bf16(acc[mt][nt], ah, bl[nt]);
#pragma unroll
                for (int nt = 0; nt < 4; nt++) mma_bf16(acc[mt][nt], al, bh[nt]);
            }
        }
        if (c < 7) {
            sts_a(stage ^ 1, aF);
            cp_wait<0>();
            __syncthreads();
            if (c + 2 < 8) cp_b(stage, c + 2);
        }
    }

    // epilogue
    int nOff = blockIdx.y * 128;
#pragma unroll
    for (int mt = 0; mt < 4; mt++) {
        int row0 = rowBase + wm * 64 + mt * 16 + lg;
#pragma unroll
        for (int nt = 0; nt < 4; nt++) {
            int col = nOff + wn * 32 + nt * 8 + 2 * la3;
            float b0 = bias_s[col];
            float b1 = bias_s[col + 1];
            float2 v0 = {acc[mt][nt][0] + b0, acc[mt][nt][1] + b1};
            float2 v1 = {acc[mt][nt][2] + b0, acc[mt][nt][3] + b1};
            *(float2*)&Out[(size_t)row0 * 256 + col] = v0;
            *(float2*)&Out[(size_t)(row0 + 8) * 256 + col] = v1;
        }
    }
}

// ----------------------- K8: attention elementwise --------------------------
__global__ void __launch_bounds__(256) attn_kernel(const float* __restrict__ convw) {
    __shared__ float cw[1024];
    __shared__ float va[8][264];
    __shared__ float red[8][256];
    int tid = threadIdx.x, w = tid >> 5, l = tid & 31;
    for (int i = tid; i < 1024; i += 256) cw[i] = convw[i];
    __syncthreads();

    float cwr[32];
#pragma unroll
    for (int i = 0; i < 32; i++) cwr[i] = cw[(l >> 2) * 128 + (l & 3) * 32 + i];

    float sum0[4] = {0, 0, 0, 0}, sum1[4] = {0, 0, 0, 0};
    float sq0[4]  = {0, 0, 0, 0}, sq1[4]  = {0, 0, 0, 0};

    int base = blockIdx.x * 512 + w * 64;
    int g0 = (l >> 3), i0 = (l & 7) * 4;

    for (int it = 0; it < 64; it++) {
        int r = base + it;
        const float4* dm4 = (const float4*)(g_dm + (size_t)r * 256);
        const float4* db4 = (const float4*)(g_db + (size_t)r * 256);
        const float4* k4  = (const float4*)(g_k  + (size_t)r * 256);
        const float4* v4  = (const float4*)(g_v  + (size_t)r * 256);
        const float4* q4  = (const float4*)(g_q  + (size_t)(r >> 4) * 256);

        float4 dmv0 = dm4[l], dmv1 = dm4[32 + l];
        float4 dbv0 = db4[l], dbv1 = db4[32 + l];
        float4 kv0  = k4[l],  kv1  = k4[32 + l];
        float4 vv0  = v4[l],  vv1  = v4[32 + l];
        float4 qv0  = q4[l],  qv1  = q4[32 + l];

        float va0[4], va1[4];
        va0[0] = fmaf(dmv0.x, qv0.x - kv0.x, dbv0.x);
        va0[1] = fmaf(dmv0.y, qv0.y - kv0.y, dbv0.y);
        va0[2] = fmaf(dmv0.z, qv0.z - kv0.z, dbv0.z);
        va0[3] = fmaf(dmv0.w, qv0.w - kv0.w, dbv0.w);
        va1[0] = fmaf(dmv1.x, qv1.x - kv1.x, dbv1.x);
        va1[1] = fmaf(dmv1.y, qv1.y - kv1.y, dbv1.y);
        va1[2] = fmaf(dmv1.z, qv1.z - kv1.z, dbv1.z);
        va1[3] = fmaf(dmv1.w, qv1.w - kv1.w, dbv1.w);
#pragma unroll
        for (int t = 0; t < 4; t++) {
            va[w][g0 * 33 + i0 + t]       = va0[t];
            va[w][(4 + g0) * 33 + i0 + t] = va1[t];
        }
        __syncwarp();

        float acc = 0.f;
#pragma unroll
        for (int i = 0; i < 32; i++) acc = fmaf(va[w][(l >> 2) * 33 + i], cwr[i], acc);

        float mx = acc;
#pragma unroll
        for (int off = 16; off > 0; off >>= 1)
            mx = fmaxf(mx, __shfl_xor_sync(0xffffffffu, mx, off));
        float e = expf(acc - mx);
        float ssum = e;
#pragma unroll
        for (int off = 16; off > 0; off >>= 1)
            ssum += __shfl_xor_sync(0xffffffffu, ssum, off);
        float ome = e / ssum;

        float o0 = __shfl_sync(0xffffffffu, ome, l >> 1);
        float o1 = __shfl_sync(0xffffffffu, ome, 16 + (l >> 1));

        float4 we0 = {o0 * vv0.x, o0 * vv0.y, o0 * vv0.z, o0 * vv0.w};
        float4 we1 = {o1 * vv1.x, o1 * vv1.y, o1 * vv1.z, o1 * vv1.w};
        float4* we4 = (float4*)(g_we + (size_t)r * 256);
        we4[l]      = we0;
        we4[32 + l] = we1;

        sum0[0] += we0.x; sum0[1] += we0.y; sum0[2] += we0.z; sum0[3] += we0.w;
        sum1[0] += we1.x; sum1[1] += we1.y; sum1[2] += we1.z; sum1[3] += we1.w;
        sq0[0] += we0.x * we0.x; sq0[1] += we0.y * we0.y;
        sq0[2] += we0.z * we0.z; sq0[3] += we0.w * we0.w;
        sq1[0] += we1.x * we1.x; sq1[1] += we1.y * we1.y;
        sq1[2] += we1.z * we1.z; sq1[3] += we1.w * we1.w;
        __syncwarp();
    }

#pragma unroll
    for (int t = 0; t < 4; t++) {
        red[w][4 * l + t]       = sum0[t];
        red[w][128 + 4 * l + t] = sum1[t];
    }
    __syncthreads();
    {
        float a = 0.f;
#pragma unroll
        for (int ww = 0; ww < 8; ww++) a += red[ww][tid];
        g_part2[blockIdx.x * 512 + tid] = a;
    }
    __syncthreads();
#pragma unroll
    for (int t = 0; t < 4; t++) {
        red[w][4 * l + t]       = sq0[t];
        red[w][128 + 4 * l + t] = sq1[t];
    }
    __syncthreads();
    {
        float a = 0.f;
#pragma unroll
        for (int ww = 0; ww < 8; ww++) a += red[ww][tid];
        g_part2[blockIdx.x * 512 + 256 + tid] = a;
    }
}

// --------------------------- K9: BN2 finalize -------------------------------
__global__ void finalize2_kernel(const float* __restrict__ bn_g,
                                 const float* __restrict__ bn_b) {
    int c = threadIdx.x;
    float s = 0.f, sq = 0.f;
    for (int b = 0; b < ATTN_BLOCKS; b++) {
        s  += g_part2[b * 512 + c];
        sq += g_part2[b * 512 + 256 + c];
    }
    float mean = s / (float)R_;
    float var = sq / (float)R_ - mean * mean;
    float sc = bn_g[c] * rsqrtf(var + EPSV);
    g_s2[c] = sc;
    g_t2[c] = bn_b[c] - mean * sc;
}

// ------------------------------- launch -------------------------------------
extern "C" void kernel_launch(void* const* d_in, const int* in_sizes, int n_in,
                              void* d_out, int out_size) {
    const float* pts   = (const float*)d_in[0];
    const float* pf    = (const float*)d_in[1];
    const float* nbr   = (const float*)d_in[2];
    const float* nf    = (const float*)d_in[3];
    const float* dm_w1 = (const float*)d_in[4];
    const float* dm_b1 = (const float*)d_in[5];
    const float* dm_w2 = (const float*)d_in[6];
    const float* dm_b2 = (const float*)d_in[7];
    const float* dm_g  = (const float*)d_in[8];
    const float* dm_be = (const float*)d_in[9];
    const float* db_w1 = (const float*)d_in[10];
    const float* db_b1 = (const float*)d_in[11];
    const float* db_w2 = (const float*)d_in[12];
    const float* db_b2 = (const float*)d_in[13];
    const float* db_g  = (const float*)d_in[14];
    const float* db_be = (const float*)d_in[15];
    const float* q_w   = (const float*)d_in[16];
    const float* q_b   = (const float*)d_in[17];
    const float* k_w   = (const float*)d_in[18];
    const float* k_b   = (const float*)d_in[19];
    const float* v_w   = (const float*)d_in[20];
    const float* v_b   = (const float*)d_in[21];
    const float* convw = (const float*)d_in[22];
    const float* bn_g  = (const float*)d_in[23];
    const float* bn_b  = (const float*)d_in[24];
    const float* lin_w = (const float*)d_in[25];
    const float* lin_b = (const float*)d_in[26];
    float* out = (float*)d_out;

    void *p_q, *p_dm, *p_db, *p_k, *p_v, *p_we, *p_bpk;
    cudaGetSymbolAddress(&p_q,  g_q);
    cudaGetSymbolAddress(&p_dm, g_dm);
    cudaGetSymbolAddress(&p_db, g_db);
    cudaGetSymbolAddress(&p_k,  g_k);
    cudaGetSymbolAddress(&p_v,  g_v);
    cudaGetSymbolAddress(&p_we, g_we);
    cudaGetSymbolAddress(&p_bpk, g_Bpk);
    const uint32_t* Bpk = (const uint32_t*)p_bpk;

    cudaFuncSetAttribute(gemm_mma<AMODE_DIRECT>,
                         cudaFuncAttributeMaxDynamicSharedMemorySize, DYN_SMEM);
    cudaFuncSetAttribute(gemm_mma<AMODE_POS>,
                         cudaFuncAttributeMaxDynamicSharedMemorySize, DYN_SMEM);
    cudaFuncSetAttribute(gemm_mma<AMODE_BNRELU>,
                         cudaFuncAttributeMaxDynamicSharedMemorySize, DYN_SMEM);

    prep_weights<<<dim3(8, 2, 6), 256>>>(q_w, k_w, v_w, dm_w2, db_w2, lin_w);
    diffstats_kernel<<<STAT_BLOCKS, 256>>>(pts, nbr);
    fold_kernel<<<1, 256>>>(dm_w1, dm_b1, dm_g, dm_be, db_w1, db_b1, db_g, db_be);

    dim3 gq(BNp / 128, 2);
    dim3 gr(R_ / 128, 2);
    gemm_mma<AMODE_DIRECT><<<gq, 256, DYN_SMEM>>>(
        pf, Bpk + 0 * 65536, q_b, (float*)p_q, nullptr, nullptr, 0);
    gemm_mma<AMODE_POS><<<gr, 256, DYN_SMEM>>>(
        nullptr, Bpk + 3 * 65536, dm_b2, (float*)p_dm, pts, nbr, 0);
    gemm_mma<AMODE_POS><<<gr, 256, DYN_SMEM>>>(
        nullptr, Bpk + 4 * 65536, db_b2, (float*)p_db, pts, nbr, 1);
    gemm_mma<AMODE_DIRECT><<<gr, 256, DYN_SMEM>>>(
        nf, Bpk + 1 * 65536, k_b, (float*)p_k, nullptr, nullptr, 0);
    gemm_mma<AMODE_DIRECT><<<gr, 256, DYN_SMEM>>>(
        nf, Bpk + 2 * 65536, v_b, (float*)p_v, nullptr, nullptr, 0);

    attn_kernel<<<ATTN_BLOCKS, 256>>>(convw);
    finalize2_kernel<<<1, 256>>>(bn_g, bn_b);

    gemm_mma<AMODE_BNRELU><<<gr, 256, DYN_SMEM>>>(
        (const float*)p_we, Bpk + 5 * 65536, lin_b, out, nullptr, nullptr, 0);
}

// round 5
// speedup vs baseline: 1.6861x; 1.6861x over previous
#include <cuda_runtime.h>
#include <cstdint>

// ---------------------------------------------------------------------------
// GroupVectorAttention — fp16 mma.m16n8k16 GEMMs (RNA-rounded, deterministic
// rel_err ~4e-4) + analytic BN1 folding. Single __syncthreads per K-chunk,
// double-buffered A (reg->smem) and B (cp.async from pre-packed fp16 images).
// ---------------------------------------------------------------------------

#define EPSV 1e-5f

static constexpr int Bb = 4, Nn = 4096, Mm = 16, Cd = 256;
static constexpr int R_ = Bb * Nn * Mm;       // 262144
static constexpr int BNp = Bb * Nn;           // 16384
static constexpr int STAT_BLOCKS = 256;
static constexpr int ATTN_BLOCKS = 512;

// smem u32 layout: A stages 2x2048 | B stages 2x2048 | fp32 extras
static constexpr int SOFF_B  = 4096;          // u32 idx
static constexpr int SOFF_FX = 8192;          // fp32 extras base (u32 idx)
static constexpr int FX_BIAS = 0, FX_W1F = 256, FX_B1F = 1024;
static constexpr int FX_S2 = 1280, FX_T2 = 1536, FX_DIFF = 1792; // 512 floats
static constexpr int DYN_SMEM = (8192 + 2304) * 4;               // 41984 B

// ------------------------- device scratch (static) -------------------------
__device__ float g_part1[STAT_BLOCKS * 12];
__device__ float g_w1f[2][Cd * 3];
__device__ float g_b1f[2][Cd];
__device__ float g_q[BNp * Cd];
__device__ float g_dm[(size_t)R_ * Cd];
__device__ float g_db[(size_t)R_ * Cd];
__device__ float g_k [(size_t)R_ * Cd];
__device__ float g_v [(size_t)R_ * Cd];
__device__ float g_we[(size_t)R_ * Cd];
__device__ float g_part2[ATTN_BLOCKS * 512];
__device__ float g_s2[Cd], g_t2[Cd];
// packed fp16 weight images: [mat(6)][nb(2)][chunk(8)][2048 u32]
__device__ uint32_t g_Bpk[6 * 2 * 8 * 2048];

// ----------------------------- PTX helpers ---------------------------------
__device__ __forceinline__ uint32_t smem_u32(const void* p) {
    uint32_t a;
    asm("{ .reg .u64 t; cvta.to.shared.u64 t, %1; cvt.u32.u64 %0, t; }"
        : "=r"(a) : "l"(p));
    return a;
}
__device__ __forceinline__ void cp16(uint32_t dst, const void* src) {
    asm volatile("cp.async.cg.shared.global [%0], [%1], 16;"
                 :: "r"(dst), "l"(src) : "memory");
}
__device__ __forceinline__ void cp_commit() {
    asm volatile("cp.async.commit_group;" ::: "memory");
}
template <int N>
__device__ __forceinline__ void cp_wait() {
    asm volatile("cp.async.wait_group %0;" :: "n"(N) : "memory");
}
__device__ __forceinline__ void mma_f16(float* c, const uint32_t* a,
                                        uint32_t b0, uint32_t b1) {
    asm volatile("mma.sync.aligned.m16n8k16.row.col.f32.f16.f16.f32 "
                 "{%0,%1,%2,%3}, {%4,%5,%6,%7}, {%8,%9}, {%0,%1,%2,%3};"
                 : "+f"(c[0]), "+f"(c[1]), "+f"(c[2]), "+f"(c[3])
                 : "r"(a[0]), "r"(a[1]), "r"(a[2]), "r"(a[3]),
                   "r"(b0), "r"(b1));
}
// pack (lo,hi) floats -> fp16x2 (RN)
__device__ __forceinline__ uint32_t f16pk(float lo, float hi) {
    uint32_t r;
    asm("cvt.rn.f16x2.f32 %0, %1, %2;" : "=r"(r) : "f"(hi), "f"(lo));
    return r;
}
// packed layout: k-pair p (k=2p,2p+1) of row n at u32 idx
//   n*16 + 4*((p&3) ^ (n&3)) + 2*(p>>3) + ((p>>2)&1)
__device__ __forceinline__ int pkidx(int n, int p) {
    return n * 16 + 4 * ((p & 3) ^ (n & 3)) + 2 * (p >> 3) + ((p >> 2) & 1);
}

// ------------------------------- K1: stats --------------------------------
__global__ void diffstats_kernel(const float* __restrict__ pts,
                                 const float* __restrict__ nbr) {
    float s[12];
#pragma unroll
    for (int i = 0; i < 12; i++) s[i] = 0.f;
    int tid = threadIdx.x;
    for (int r = blockIdx.x * blockDim.x + tid; r < R_; r += gridDim.x * blockDim.x) {
        int bn = r >> 4;
        float d[3];
#pragma unroll
        for (int j = 0; j < 3; j++) d[j] = pts[bn * 3 + j] - nbr[(size_t)r * 3 + j];
#pragma unroll
        for (int j = 0; j < 3; j++) s[j] += d[j];
#pragma unroll
        for (int j = 0; j < 3; j++)
#pragma unroll
            for (int k = 0; k < 3; k++) s[3 + j * 3 + k] += d[j] * d[k];
    }
    __shared__ float red[256];
    for (int comp = 0; comp < 12; comp++) {
        red[tid] = s[comp];
        __syncthreads();
        for (int off = 128; off > 0; off >>= 1) {
            if (tid < off) red[tid] += red[tid + off];
            __syncthreads();
        }
        if (tid == 0) g_part1[blockIdx.x * 12 + comp] = red[0];
        __syncthreads();
    }
}

// ------------------------------ K2: BN1 fold -------------------------------
__global__ void fold_kernel(const float* __restrict__ dm_w1, const float* __restrict__ dm_b1,
                            const float* __restrict__ dm_g,  const float* __restrict__ dm_be,
                            const float* __restrict__ db_w1, const float* __restrict__ db_b1,
                            const float* __restrict__ db_g,  const float* __restrict__ db_be) {
    __shared__ float st[12];
    __shared__ float mu[3], cov[9];
    int tid = threadIdx.x;
    if (tid < 12) {
        float a = 0.f;
        for (int b = 0; b < STAT_BLOCKS; b++) a += g_part1[b * 12 + tid];
        st[tid] = a / (float)R_;
    }
    __syncthreads();
    if (tid < 3) mu[tid] = st[tid];
    if (tid < 9) {
        int j = tid / 3, k = tid % 3;
        cov[tid] = st[3 + tid] - st[j] * st[k];
    }
    __syncthreads();
    int c = tid;
    for (int which = 0; which < 2; which++) {
        const float* w1 = which ? db_w1 : dm_w1;
        const float* b1 = which ? db_b1 : dm_b1;
        const float* gg = which ? db_g  : dm_g;
        const float* be = which ? db_be : dm_be;
        float w0 = w1[c * 3], w1v = w1[c * 3 + 1], w2v = w1[c * 3 + 2];
        float var = w0 * w0 * cov[0] + w1v * w1v * cov[4] + w2v * w2v * cov[8]
                  + 2.f * (w0 * w1v * cov[1] + w0 * w2v * cov[2] + w1v * w2v * cov[5]);
        float mdot = w0 * mu[0] + w1v * mu[1] + w2v * mu[2];
        float m = mdot + b1[c];
        float s = gg[c] * rsqrtf(var + EPSV);
        g_w1f[which][c * 3]     = w0 * s;
        g_w1f[which][c * 3 + 1] = w1v * s;
        g_w1f[which][c * 3 + 2] = w2v * s;
        g_b1f[which][c] = be[c] + s * (b1[c] - m);
    }
}

// ----------------------- weight prep: fp32 -> packed fp16 -------------------
__global__ void prep_weights(const float* __restrict__ q_w, const float* __restrict__ k_w,
                             const float* __restrict__ v_w, const float* __restrict__ dm_w2,
                             const float* __restrict__ db_w2, const float* __restrict__ lin_w) {
    int c = blockIdx.x, nb = blockIdx.y, mat = blockIdx.z;
    const float* W = mat == 0 ? q_w : mat == 1 ? k_w : mat == 2 ? v_w :
                     mat == 3 ? dm_w2 : mat == 4 ? db_w2 : lin_w;
    uint32_t* dst = g_Bpk + (((size_t)mat * 2 + nb) * 8 + c) * 2048;
    int tid = threadIdx.x;
    int n = tid >> 1, q = tid & 1;                 // row n, k-half q
    const float* src = W + (size_t)(nb * 128 + n) * 256 + c * 32 + q * 16;
    float cc[16];
#pragma unroll
    for (int j = 0; j < 16; j += 4) {
        float4 v = *(const float4*)&src[j];
        cc[j] = v.x; cc[j + 1] = v.y; cc[j + 2] = v.z; cc[j + 3] = v.w;
    }
#pragma unroll
    for (int t = 0; t < 4; t++)
#pragma unroll
        for (int u = 0; u < 2; u++) {
            int p = 8 * q + t + 4 * u;             // pair index (k=2p)
            dst[pkidx(n, p)] = f16pk(cc[2 * t + 8 * u], cc[2 * t + 8 * u + 1]);
        }
}

// ----------------------- GEMM: fp16 mma.m16n8k16 ----------------------------
// CTA 128 rows x 128 cols (grid.y = nb), K=256 in 8 chunks of 32.
// 8 warps 2(row)x4(col); warp tile 64x32; single sync per chunk.
enum { AMODE_DIRECT = 0, AMODE_POS = 1, AMODE_BNRELU = 2 };

template <int AMODE>
__device__ __forceinline__ void load_aU(
    int tid, int rowBase, int kb,
    const float* __restrict__ A,
    const float* w1f_s, const float* b1f_s,
    const float* s2_s, const float* t2_s, const float* diff_s,
    uint2 aU[4]) {
#pragma unroll
    for (int i = 0; i < 4; i++) {
        int f = tid + i * 256, row = f >> 3, kq = f & 7;
        float4 v;
        if (AMODE == AMODE_POS) {
            float d0 = diff_s[row * 4], d1 = diff_s[row * 4 + 1], d2 = diff_s[row * 4 + 2];
            float t[4];
#pragma unroll
            for (int j = 0; j < 4; j++) {
                int k = kb + kq * 4 + j;
                float h = fmaf(d0, w1f_s[k * 3],
                          fmaf(d1, w1f_s[k * 3 + 1],
                          fmaf(d2, w1f_s[k * 3 + 2], b1f_s[k])));
                t[j] = fmaxf(h, 0.f);
            }
            v = make_float4(t[0], t[1], t[2], t[3]);
        } else {
            v = *(const float4*)&A[(size_t)(rowBase + row) * 256 + kb + kq * 4];
            if (AMODE == AMODE_BNRELU) {
                int k = kb + kq * 4;
                v.x = fmaxf(fmaf(v.x, s2_s[k],     t2_s[k]),     0.f);
                v.y = fmaxf(fmaf(v.y, s2_s[k + 1], t2_s[k + 1]), 0.f);
                v.z = fmaxf(fmaf(v.z, s2_s[k + 2], t2_s[k + 2]), 0.f);
                v.w = fmaxf(fmaf(v.w, s2_s[k + 3], t2_s[k + 3]), 0.f);
            }
        }
        aU[i].x = f16pk(v.x, v.y);     // pair 2*kq   (k = 4kq, 4kq+1)
        aU[i].y = f16pk(v.z, v.w);     // pair 2*kq+1 (k = 4kq+2, 4kq+3)
    }
}

template <int AMODE>
__global__ void __launch_bounds__(256, 2)
gemm_mma(const float* __restrict__ A, const uint32_t* __restrict__ Bpk,
         const float* __restrict__ bias, float* __restrict__ Out,
         const float* __restrict__ pts, const float* __restrict__ nbr, int which) {
    extern __shared__ uint32_t sm[];
    float* fx     = (float*)(sm + SOFF_FX);
    float* bias_s = fx + FX_BIAS;
    float* w1f_s  = fx + FX_W1F;
    float* b1f_s  = fx + FX_B1F;
    float* s2_s   = fx + FX_S2;
    float* t2_s   = fx + FX_T2;
    float* diff_s = fx + FX_DIFF;

    int tid = threadIdx.x;
    int rowBase = blockIdx.x * 128;

    bias_s[tid] = bias[tid];
    if (AMODE == AMODE_POS) {
        const float* w1f = g_w1f[which];
        for (int i = tid; i < 768; i += 256) w1f_s[i] = w1f[i];
        b1f_s[tid] = g_b1f[which][tid];
        if (tid < 128) {
            int r = rowBase + tid, bn = r >> 4;
            diff_s[tid * 4 + 0] = pts[bn * 3 + 0] - nbr[(size_t)r * 3 + 0];
            diff_s[tid * 4 + 1] = pts[bn * 3 + 1] - nbr[(size_t)r * 3 + 1];
            diff_s[tid * 4 + 2] = pts[bn * 3 + 2] - nbr[(size_t)r * 3 + 2];
        }
    }
    if (AMODE == AMODE_BNRELU) {
        s2_s[tid] = g_s2[tid];
        t2_s[tid] = g_t2[tid];
    }
    __syncthreads();

    uint32_t smemB_addr = smem_u32(sm + SOFF_B);
    const uint32_t* BpkNb = Bpk + (size_t)blockIdx.y * 16384;

    auto cp_b = [&](int stage, int c) {
        const uint32_t* src = BpkNb + c * 2048;
        uint32_t dstb = smemB_addr + (uint32_t)stage * 8192u;
#pragma unroll
        for (int i = 0; i < 2; i++) {
            int e = tid + i * 256;
            cp16(dstb + (uint32_t)e * 16u, src + e * 4);
        }
        cp_commit();
    };
    // per-thread sts indices (pairs 2kq, 2kq+1 of row)
    auto sts_a = [&](int stage, const uint2* aU) {
        uint32_t* dst = sm + stage * 2048;
#pragma unroll
        for (int i = 0; i < 4; i++) {
            int f = tid + i * 256, row = f >> 3, kq = f & 7;
            int p0 = 2 * kq;
            dst[pkidx(row, p0)]     = aU[i].x;
            dst[pkidx(row, p0 + 1)] = aU[i].y;
        }
    };

    // prologue
    cp_b(0, 0);
    cp_b(1, 1);
    uint2 aU[4];
    load_aU<AMODE>(tid, rowBase, 0, A, w1f_s, b1f_s, s2_s, t2_s, diff_s, aU);
    sts_a(0, aU);
    cp_wait<0>();
    __syncthreads();

    int lane = tid & 31, w = tid >> 5;
    int wm = w & 1, wn = w >> 1;
    int la3 = lane & 3, lg = lane >> 2;
    int axor = 4 * (la3 ^ (lg & 3));

    float acc[4][4][4];
#pragma unroll
    for (int mt = 0; mt < 4; mt++)
#pragma unroll
        for (int nt = 0; nt < 4; nt++)
#pragma unroll
            for (int r = 0; r < 4; r++) acc[mt][nt][r] = 0.f;

    const int aBase = (wm * 64 + lg) * 16 + axor;
    const int bBase = (wn * 32 + lg) * 16 + axor;

    for (int c = 0; c < 8; c++) {
        int st = c & 1;
        if (c < 7)
            load_aU<AMODE>(tid, rowBase, (c + 1) * 32, A,
                           w1f_s, b1f_s, s2_s, t2_s, diff_s, aU);
        const uint32_t* As = sm + st * 2048;
        const uint32_t* Bs = sm + SOFF_B + st * 2048;

        uint4 Vb[4];
#pragma unroll
        for (int nt = 0; nt < 4; nt++)
            Vb[nt] = *(const uint4*)&Bs[bBase + nt * 128];
#pragma unroll
        for (int mt = 0; mt < 4; mt++) {
            uint4 U0 = *(const uint4*)&As[aBase + mt * 256];
            uint4 U1 = *(const uint4*)&As[aBase + mt * 256 + 128];
            uint32_t a0[4] = {U0.x, U1.x, U0.y, U1.y};   // ks = 0
            uint32_t a1[4] = {U0.z, U1.z, U0.w, U1.w};   // ks = 1
#pragma unroll
            for (int nt = 0; nt < 4; nt++)
                mma_f16(acc[mt][nt], a0, Vb[nt].x, Vb[nt].y);
#pragma unroll
            for (int nt = 0; nt < 4; nt++)
                mma_f16(acc[mt][nt], a1, Vb[nt].z, Vb[nt].w);
        }
        if (c < 7) sts_a(st ^ 1, aU);
        cp_wait<0>();
        __syncthreads();
        if (c + 2 < 8) cp_b(st, c + 2);
    }

    // epilogue
    int nOff = blockIdx.y * 128;
#pragma unroll
    for (int mt = 0; mt < 4; mt++) {
        int row0 = rowBase + wm * 64 + mt * 16 + lg;
#pragma unroll
        for (int nt = 0; nt < 4; nt++) {
            int col = nOff + wn * 32 + nt * 8 + 2 * la3;
            float b0 = bias_s[col];
            float b1 = bias_s[col + 1];
            float2 v0 = {acc[mt][nt][0] + b0, acc[mt][nt][1] + b1};
            float2 v1 = {acc[mt][nt][2] + b0, acc[mt][nt][3] + b1};
            *(float2*)&Out[(size_t)row0 * 256 + col] = v0;
            *(float2*)&Out[(size_t)(row0 + 8) * 256 + col] = v1;
        }
    }
}

// ----------------------- K8: attention elementwise --------------------------
__global__ void __launch_bounds__(256) attn_kernel(const float* __restrict__ convw) {
    __shared__ float cw[1024];
    __shared__ float va[8][264];
    __shared__ float red[8][256];
    int tid = threadIdx.x, w = tid >> 5, l = tid & 31;
    for (int i = tid; i < 1024; i += 256) cw[i] = convw[i];
    __syncthreads();

    float cwr[32];
#pragma unroll
    for (int i = 0; i < 32; i++) cwr[i] = cw[(l >> 2) * 128 + (l & 3) * 32 + i];

    float sum0[4] = {0, 0, 0, 0}, sum1[4] = {0, 0, 0, 0};
    float sq0[4]  = {0, 0, 0, 0}, sq1[4]  = {0, 0, 0, 0};

    int base = blockIdx.x * 512 + w * 64;
    int g0 = (l >> 3), i0 = (l & 7) * 4;

    for (int it = 0; it < 64; it++) {
        int r = base + it;
        const float4* dm4 = (const float4*)(g_dm + (size_t)r * 256);
        const float4* db4 = (const float4*)(g_db + (size_t)r * 256);
        const float4* k4  = (const float4*)(g_k  + (size_t)r * 256);
        const float4* v4  = (const float4*)(g_v  + (size_t)r * 256);
        const float4* q4  = (const float4*)(g_q  + (size_t)(r >> 4) * 256);

        float4 dmv0 = dm4[l], dmv1 = dm4[32 + l];
        float4 dbv0 = db4[l], dbv1 = db4[32 + l];
        float4 kv0  = k4[l],  kv1  = k4[32 + l];
        float4 vv0  = v4[l],  vv1  = v4[32 + l];
        float4 qv0  = q4[l],  qv1  = q4[32 + l];

        float va0[4], va1[4];
        va0[0] = fmaf(dmv0.x, qv0.x - kv0.x, dbv0.x);
        va0[1] = fmaf(dmv0.y, qv0.y - kv0.y, dbv0.y);
        va0[2] = fmaf(dmv0.z, qv0.z - kv0.z, dbv0.z);
        va0[3] = fmaf(dmv0.w, qv0.w - kv0.w, dbv0.w);
        va1[0] = fmaf(dmv1.x, qv1.x - kv1.x, dbv1.x);
        va1[1] = fmaf(dmv1.y, qv1.y - kv1.y, dbv1.y);
        va1[2] = fmaf(dmv1.z, qv1.z - kv1.z, dbv1.z);
        va1[3] = fmaf(dmv1.w, qv1.w - kv1.w, dbv1.w);
#pragma unroll
        for (int t = 0; t < 4; t++) {
            va[w][g0 * 33 + i0 + t]       = va0[t];
            va[w][(4 + g0) * 33 + i0 + t] = va1[t];
        }
        __syncwarp();

        float acc = 0.f;
#pragma unroll
        for (int i = 0; i < 32; i++) acc = fmaf(va[w][(l >> 2) * 33 + i], cwr[i], acc);

        float mx = acc;
#pragma unroll
        for (int off = 16; off > 0; off >>= 1)
            mx = fmaxf(mx, __shfl_xor_sync(0xffffffffu, mx, off));
        float e = expf(acc - mx);
        float ssum = e;
#pragma unroll
        for (int off = 16; off > 0; off >>= 1)
            ssum += __shfl_xor_sync(0xffffffffu, ssum, off);
        float ome = e / ssum;

        float o0 = __shfl_sync(0xffffffffu, ome, l >> 1);
        float o1 = __shfl_sync(0xffffffffu, ome, 16 + (l >> 1));

        float4 we0 = {o0 * vv0.x, o0 * vv0.y, o0 * vv0.z, o0 * vv0.w};
        float4 we1 = {o1 * vv1.x, o1 * vv1.y, o1 * vv1.z, o1 * vv1.w};
        float4* we4 = (float4*)(g_we + (size_t)r * 256);
        we4[l]      = we0;
        we4[32 + l] = we1;

        sum0[0] += we0.x; sum0[1] += we0.y; sum0[2] += we0.z; sum0[3] += we0.w;
        sum1[0] += we1.x; sum1[1] += we1.y; sum1[2] += we1.z; sum1[3] += we1.w;
        sq0[0] += we0.x * we0.x; sq0[1] += we0.y * we0.y;
        sq0[2] += we0.z * we0.z; sq0[3] += we0.w * we0.w;
        sq1[0] += we1.x * we1.x; sq1[1] += we1.y * we1.y;
        sq1[2] += we1.z * we1.z; sq1[3] += we1.w * we1.w;
        __syncwarp();
    }

#pragma unroll
    for (int t = 0; t < 4; t++) {
        red[w][4 * l + t]       = sum0[t];
        red[w][128 + 4 * l + t] = sum1[t];
    }
    __syncthreads();
    {
        float a = 0.f;
#pragma unroll
        for (int ww = 0; ww < 8; ww++) a += red[ww][tid];
        g_part2[blockIdx.x * 512 + tid] = a;
    }
    __syncthreads();
#pragma unroll
    for (int t = 0; t < 4; t++) {
        red[w][4 * l + t]       = sq0[t];
        red[w][128 + 4 * l + t] = sq1[t];
    }
    __syncthreads();
    {
        float a = 0.f;
#pragma unroll
        for (int ww = 0; ww < 8; ww++) a += red[ww][tid];
        g_part2[blockIdx.x * 512 + 256 + tid] = a;
    }
}

// --------------------------- K9: BN2 finalize -------------------------------
__global__ void finalize2_kernel(const float* __restrict__ bn_g,
                                 const float* __restrict__ bn_b) {
    int c = threadIdx.x;
    float s = 0.f, sq = 0.f;
    for (int b = 0; b < ATTN_BLOCKS; b++) {
        s  += g_part2[b * 512 + c];
        sq += g_part2[b * 512 + 256 + c];
    }
    float mean = s / (float)R_;
    float var = sq / (float)R_ - mean * mean;
    float sc = bn_g[c] * rsqrtf(var + EPSV);
    g_s2[c] = sc;
    g_t2[c] = bn_b[c] - mean * sc;
}

// ------------------------------- launch -------------------------------------
extern "C" void kernel_launch(void* const* d_in, const int* in_sizes, int n_in,
                              void* d_out, int out_size) {
    const float* pts   = (const float*)d_in[0];
    const float* pf    = (const float*)d_in[1];
    const float* nbr   = (const float*)d_in[2];
    const float* nf    = (const float*)d_in[3];
    const float* dm_w1 = (const float*)d_in[4];
    const float* dm_b1 = (const float*)d_in[5];
    const float* dm_w2 = (const float*)d_in[6];
    const float* dm_b2 = (const float*)d_in[7];
    const float* dm_g  = (const float*)d_in[8];
    const float* dm_be = (const float*)d_in[9];
    const float* db_w1 = (const float*)d_in[10];
    const float* db_b1 = (const float*)d_in[11];
    const float* db_w2 = (const float*)d_in[12];
    const float* db_b2 = (const float*)d_in[13];
    const float* db_g  = (const float*)d_in[14];
    const float* db_be = (const float*)d_in[15];
    const float* q_w   = (const float*)d_in[16];
    const float* q_b   = (const float*)d_in[17];
    const float* k_w   = (const float*)d_in[18];
    const float* k_b   = (const float*)d_in[19];
    const float* v_w   = (const float*)d_in[20];
    const float* v_b   = (const float*)d_in[21];
    const float* convw = (const float*)d_in[22];
    const float* bn_g  = (const float*)d_in[23];
    const float* bn_b  = (const float*)d_in[24];
    const float* lin_w = (const float*)d_in[25];
    const float* lin_b = (const float*)d_in[26];
    float* out = (float*)d_out;

    void *p_q, *p_dm, *p_db, *p_k, *p_v, *p_we, *p_bpk;
    cudaGetSymbolAddress(&p_q,  g_q);
    cudaGetSymbolAddress(&p_dm, g_dm);
    cudaGetSymbolAddress(&p_db, g_db);
    cudaGetSymbolAddress(&p_k,  g_k);
    cudaGetSymbolAddress(&p_v,  g_v);
    cudaGetSymbolAddress(&p_we, g_we);
    cudaGetSymbolAddress(&p_bpk, g_Bpk);
    const uint32_t* Bpk = (const uint32_t*)p_bpk;

    cudaFuncSetAttribute(gemm_mma<AMODE_DIRECT>,
                         cudaFuncAttributeMaxDynamicSharedMemorySize, DYN_SMEM);
    cudaFuncSetAttribute(gemm_mma<AMODE_POS>,
                         cudaFuncAttributeMaxDynamicSharedMemorySize, DYN_SMEM);
    cudaFuncSetAttribute(gemm_mma<AMODE_BNRELU>,
                         cudaFuncAttributeMaxDynamicSharedMemorySize, DYN_SMEM);

    prep_weights<<<dim3(8, 2, 6), 256>>>(q_w, k_w, v_w, dm_w2, db_w2, lin_w);
    diffstats_kernel<<<STAT_BLOCKS, 256>>>(pts, nbr);
    fold_kernel<<<1, 256>>>(dm_w1, dm_b1, dm_g, dm_be, db_w1, db_b1, db_g, db_be);

    dim3 gq(BNp / 128, 2);
    dim3 gr(R_ / 128, 2);
    gemm_mma<AMODE_DIRECT><<<gq, 256, DYN_SMEM>>>(
        pf, Bpk + 0 * 32768, q_b, (float*)p_q, nullptr, nullptr, 0);
    gemm_mma<AMODE_POS><<<gr, 256, DYN_SMEM>>>(
        nullptr, Bpk + 3 * 32768, dm_b2, (float*)p_dm, pts, nbr, 0);
    gemm_mma<AMODE_POS><<<gr, 256, DYN_SMEM>>>(
        nullptr, Bpk + 4 * 32768, db_b2, (float*)p_db, pts, nbr, 1);
    gemm_mma<AMODE_DIRECT><<<gr, 256, DYN_SMEM>>>(
        nf, Bpk + 1 * 32768, k_b, (float*)p_k, nullptr, nullptr, 0);
    gemm_mma<AMODE_DIRECT><<<gr, 256, DYN_SMEM>>>(
        nf, Bpk + 2 * 32768, v_b, (float*)p_v, nullptr, nullptr, 0);

    attn_kernel<<<ATTN_BLOCKS, 256>>>(convw);
    finalize2_kernel<<<1, 256>>>(bn_g, bn_b);

    gemm_mma<AMODE_BNRELU><<<gr, 256, DYN_SMEM>>>(
        (const float*)p_we, Bpk + 5 * 32768, lin_b, out, nullptr, nullptr, 0);
}

// round 6
// speedup vs baseline: 1.9014x; 1.1276x over previous
#include <cuda_runtime.h>
#include <cstdint>

// ---------------------------------------------------------------------------
// GroupVectorAttention — fp16 mma.m16n8k16 GEMMs + fp16-packed intermediates.
// All inter-kernel tensors (q, dm, db, k, v, we) stored as f16x2 — halves the
// ~3.2GB of fp32 intermediate DRAM traffic that dominated R5's profile.
// ---------------------------------------------------------------------------

#define EPSV 1e-5f

static constexpr int Bb = 4, Nn = 4096, Mm = 16, Cd = 256;
static constexpr int R_ = Bb * Nn * Mm;       // 262144
static constexpr int BNp = Bb * Nn;           // 16384
static constexpr int STAT_BLOCKS = 256;
static constexpr int ATTN_BLOCKS = 512;

// smem u32 layout: A stages 2x2048 | B stages 2x2048 | fp32 extras
static constexpr int SOFF_B  = 4096;          // u32 idx
static constexpr int SOFF_FX = 8192;          // fp32 extras base (u32 idx)
static constexpr int FX_BIAS = 0, FX_W1F = 256, FX_B1F = 1024;
static constexpr int FX_S2 = 1280, FX_T2 = 1536, FX_DIFF = 1792; // 512 floats
static constexpr int DYN_SMEM = (8192 + 2304) * 4;               // 41984 B

// ------------------------- device scratch (static) -------------------------
__device__ float g_part1[STAT_BLOCKS * 12];
__device__ float g_w1f[2][Cd * 3];
__device__ float g_b1f[2][Cd];
__device__ uint32_t g_q16[BNp * 128];
__device__ uint32_t g_dm16[(size_t)R_ * 128];
__device__ uint32_t g_db16[(size_t)R_ * 128];
__device__ uint32_t g_k16 [(size_t)R_ * 128];
__device__ uint32_t g_v16 [(size_t)R_ * 128];
__device__ uint32_t g_we16[(size_t)R_ * 128];
__device__ float g_part2[ATTN_BLOCKS * 512];
__device__ float g_s2[Cd], g_t2[Cd];
// packed fp16 weight images: [mat(6)][nb(2)][chunk(8)][2048 u32]
__device__ uint32_t g_Bpk[6 * 2 * 8 * 2048];

// ----------------------------- PTX helpers ---------------------------------
__device__ __forceinline__ uint32_t smem_u32(const void* p) {
    uint32_t a;
    asm("{ .reg .u64 t; cvta.to.shared.u64 t, %1; cvt.u32.u64 %0, t; }"
        : "=r"(a) : "l"(p));
    return a;
}
__device__ __forceinline__ void cp16(uint32_t dst, const void* src) {
    asm volatile("cp.async.cg.shared.global [%0], [%1], 16;"
                 :: "r"(dst), "l"(src) : "memory");
}
__device__ __forceinline__ void cp_commit() {
    asm volatile("cp.async.commit_group;" ::: "memory");
}
template <int N>
__device__ __forceinline__ void cp_wait() {
    asm volatile("cp.async.wait_group %0;" :: "n"(N) : "memory");
}
__device__ __forceinline__ void mma_f16(float* c, const uint32_t* a,
                                        uint32_t b0, uint32_t b1) {
    asm volatile("mma.sync.aligned.m16n8k16.row.col.f32.f16.f16.f32 "
                 "{%0,%1,%2,%3}, {%4,%5,%6,%7}, {%8,%9}, {%0,%1,%2,%3};"
                 : "+f"(c[0]), "+f"(c[1]), "+f"(c[2]), "+f"(c[3])
                 : "r"(a[0]), "r"(a[1]), "r"(a[2]), "r"(a[3]),
                   "r"(b0), "r"(b1));
}
// pack (lo,hi) floats -> fp16x2 (RN)
__device__ __forceinline__ uint32_t f16pk(float lo, float hi) {
    uint32_t r;
    asm("cvt.rn.f16x2.f32 %0, %1, %2;" : "=r"(r) : "f"(hi), "f"(lo));
    return r;
}
// unpack fp16x2 -> 2 floats
__device__ __forceinline__ float2 upk(uint32_t u) {
    float2 f;
    asm("{ .reg .b16 lo, hi; mov.b32 {lo, hi}, %2; "
        "cvt.f32.f16 %0, lo; cvt.f32.f16 %1, hi; }"
        : "=f"(f.x), "=f"(f.y) : "r"(u));
    return f;
}
// packed layout: k-pair p (k=2p,2p+1) of row n at u32 idx
__device__ __forceinline__ int pkidx(int n, int p) {
    return n * 16 + 4 * ((p & 3) ^ (n & 3)) + 2 * (p >> 3) + ((p >> 2) & 1);
}

// ------------------------------- K1: stats --------------------------------
__global__ void diffstats_kernel(const float* __restrict__ pts,
                                 const float* __restrict__ nbr) {
    float s[12];
#pragma unroll
    for (int i = 0; i < 12; i++) s[i] = 0.f;
    int tid = threadIdx.x;
    for (int r = blockIdx.x * blockDim.x + tid; r < R_; r += gridDim.x * blockDim.x) {
        int bn = r >> 4;
        float d[3];
#pragma unroll
        for (int j = 0; j < 3; j++) d[j] = pts[bn * 3 + j] - nbr[(size_t)r * 3 + j];
#pragma unroll
        for (int j = 0; j < 3; j++) s[j] += d[j];
#pragma unroll
        for (int j = 0; j < 3; j++)
#pragma unroll
            for (int k = 0; k < 3; k++) s[3 + j * 3 + k] += d[j] * d[k];
    }
    __shared__ float red[256];
    for (int comp = 0; comp < 12; comp++) {
        red[tid] = s[comp];
        __syncthreads();
        for (int off = 128; off > 0; off >>= 1) {
            if (tid < off) red[tid] += red[tid + off];
            __syncthreads();
        }
        if (tid == 0) g_part1[blockIdx.x * 12 + comp] = red[0];
        __syncthreads();
    }
}

// ------------------------------ K2: BN1 fold -------------------------------
__global__ void fold_kernel(const float* __restrict__ dm_w1, const float* __restrict__ dm_b1,
                            const float* __restrict__ dm_g,  const float* __restrict__ dm_be,
                            const float* __restrict__ db_w1, const float* __restrict__ db_b1,
                            const float* __restrict__ db_g,  const float* __restrict__ db_be) {
    __shared__ float st[12];
    __shared__ float mu[3], cov[9];
    int tid = threadIdx.x;
    if (tid < 12) {
        float a = 0.f;
        for (int b = 0; b < STAT_BLOCKS; b++) a += g_part1[b * 12 + tid];
        st[tid] = a / (float)R_;
    }
    __syncthreads();
    if (tid < 3) mu[tid] = st[tid];
    if (tid < 9) {
        int j = tid / 3, k = tid % 3;
        cov[tid] = st[3 + tid] - st[j] * st[k];
    }
    __syncthreads();
    int c = tid;
    for (int which = 0; which < 2; which++) {
        const float* w1 = which ? db_w1 : dm_w1;
        const float* b1 = which ? db_b1 : dm_b1;
        const float* gg = which ? db_g  : dm_g;
        const float* be = which ? db_be : dm_be;
        float w0 = w1[c * 3], w1v = w1[c * 3 + 1], w2v = w1[c * 3 + 2];
        float var = w0 * w0 * cov[0] + w1v * w1v * cov[4] + w2v * w2v * cov[8]
                  + 2.f * (w0 * w1v * cov[1] + w0 * w2v * cov[2] + w1v * w2v * cov[5]);
        float mdot = w0 * mu[0] + w1v * mu[1] + w2v * mu[2];
        float m = mdot + b1[c];
        float s = gg[c] * rsqrtf(var + EPSV);
        g_w1f[which][c * 3]     = w0 * s;
        g_w1f[which][c * 3 + 1] = w1v * s;
        g_w1f[which][c * 3 + 2] = w2v * s;
        g_b1f[which][c] = be[c] + s * (b1[c] - m);
    }
}

// ----------------------- weight prep: fp32 -> packed fp16 -------------------
__global__ void prep_weights(const float* __restrict__ q_w, const float* __restrict__ k_w,
                             const float* __restrict__ v_w, const float* __restrict__ dm_w2,
                             const float* __restrict__ db_w2, const float* __restrict__ lin_w) {
    int c = blockIdx.x, nb = blockIdx.y, mat = blockIdx.z;
    const float* W = mat == 0 ? q_w : mat == 1 ? k_w : mat == 2 ? v_w :
                     mat == 3 ? dm_w2 : mat == 4 ? db_w2 : lin_w;
    uint32_t* dst = g_Bpk + (((size_t)mat * 2 + nb) * 8 + c) * 2048;
    int tid = threadIdx.x;
    int n = tid >> 1, q = tid & 1;                 // row n, k-half q
    const float* src = W + (size_t)(nb * 128 + n) * 256 + c * 32 + q * 16;
    float cc[16];
#pragma unroll
    for (int j = 0; j < 16; j += 4) {
        float4 v = *(const float4*)&src[j];
        cc[j] = v.x; cc[j + 1] = v.y; cc[j + 2] = v.z; cc[j + 3] = v.w;
    }
#pragma unroll
    for (int t = 0; t < 4; t++)
#pragma unroll
        for (int u = 0; u < 2; u++) {
            int p = 8 * q + t + 4 * u;             // pair index (k=2p)
            dst[pkidx(n, p)] = f16pk(cc[2 * t + 8 * u], cc[2 * t + 8 * u + 1]);
        }
}

// ----------------------- GEMM: fp16 mma.m16n8k16 ----------------------------
// CTA 128 rows x 128 cols (grid.y = nb), K=256 in 8 chunks of 32.
enum { AMODE_DIRECT = 0, AMODE_POS = 1, AMODE_F16BN = 2 };

template <int AMODE>
__device__ __forceinline__ void load_aU(
    int tid, int rowBase, int kb,
    const void* __restrict__ Ap,
    const float* w1f_s, const float* b1f_s,
    const float* s2_s, const float* t2_s, const float* diff_s,
    uint2 aU[4]) {
#pragma unroll
    for (int i = 0; i < 4; i++) {
        int f = tid + i * 256, row = f >> 3, kq = f & 7;
        if (AMODE == AMODE_POS) {
            float d0 = diff_s[row * 4], d1 = diff_s[row * 4 + 1], d2 = diff_s[row * 4 + 2];
            float t[4];
#pragma unroll
            for (int j = 0; j < 4; j++) {
                int k = kb + kq * 4 + j;
                float h = fmaf(d0, w1f_s[k * 3],
                          fmaf(d1, w1f_s[k * 3 + 1],
                          fmaf(d2, w1f_s[k * 3 + 2], b1f_s[k])));
                t[j] = fmaxf(h, 0.f);
            }
            aU[i].x = f16pk(t[0], t[1]);
            aU[i].y = f16pk(t[2], t[3]);
        } else if (AMODE == AMODE_DIRECT) {
            const float* A = (const float*)Ap;
            float4 v = *(const float4*)&A[(size_t)(rowBase + row) * 256 + kb + kq * 4];
            aU[i].x = f16pk(v.x, v.y);
            aU[i].y = f16pk(v.z, v.w);
        } else { // AMODE_F16BN: packed fp16 input + BN2 scale/shift + relu
            const uint32_t* A16 = (const uint32_t*)Ap;
            uint2 u = *(const uint2*)&A16[(size_t)(rowBase + row) * 128 + (kb >> 1) + kq * 2];
            float2 f0 = upk(u.x), f1 = upk(u.y);
            int k = kb + kq * 4;
            float x0 = fmaxf(fmaf(f0.x, s2_s[k],     t2_s[k]),     0.f);
            float x1 = fmaxf(fmaf(f0.y, s2_s[k + 1], t2_s[k + 1]), 0.f);
            float x2 = fmaxf(fmaf(f1.x, s2_s[k + 2], t2_s[k + 2]), 0.f);
            float x3 = fmaxf(fmaf(f1.y, s2_s[k + 3], t2_s[k + 3]), 0.f);
            aU[i].x = f16pk(x0, x1);
            aU[i].y = f16pk(x2, x3);
        }
    }
}

template <int AMODE, bool OUT16>
__global__ void __launch_bounds__(256, 2)
gemm_mma(const void* __restrict__ A, const uint32_t* __restrict__ Bpk,
         const float* __restrict__ bias, void* __restrict__ OutP,
         const float* __restrict__ pts, const float* __restrict__ nbr, int which) {
    extern __shared__ uint32_t sm[];
    float* fx     = (float*)(sm + SOFF_FX);
    float* bias_s = fx + FX_BIAS;
    float* w1f_s  = fx + FX_W1F;
    float* b1f_s  = fx + FX_B1F;
    float* s2_s   = fx + FX_S2;
    float* t2_s   = fx + FX_T2;
    float* diff_s = fx + FX_DIFF;

    int tid = threadIdx.x;
    int rowBase = blockIdx.x * 128;

    bias_s[tid] = bias[tid];
    if (AMODE == AMODE_POS) {
        const float* w1f = g_w1f[which];
        for (int i = tid; i < 768; i += 256) w1f_s[i] = w1f[i];
        b1f_s[tid] = g_b1f[which][tid];
        if (tid < 128) {
            int r = rowBase + tid, bn = r >> 4;
            diff_s[tid * 4 + 0] = pts[bn * 3 + 0] - nbr[(size_t)r * 3 + 0];
            diff_s[tid * 4 + 1] = pts[bn * 3 + 1] - nbr[(size_t)r * 3 + 1];
            diff_s[tid * 4 + 2] = pts[bn * 3 + 2] - nbr[(size_t)r * 3 + 2];
        }
    }
    if (AMODE == AMODE_F16BN) {
        s2_s[tid] = g_s2[tid];
        t2_s[tid] = g_t2[tid];
    }
    __syncthreads();

    uint32_t smemB_addr = smem_u32(sm + SOFF_B);
    const uint32_t* BpkNb = Bpk + (size_t)blockIdx.y * 16384;

    auto cp_b = [&](int stage, int c) {
        const uint32_t* src = BpkNb + c * 2048;
        uint32_t dstb = smemB_addr + (uint32_t)stage * 8192u;
#pragma unroll
        for (int i = 0; i < 2; i++) {
            int e = tid + i * 256;
            cp16(dstb + (uint32_t)e * 16u, src + e * 4);
        }
        cp_commit();
    };
    auto sts_a = [&](int stage, const uint2* aU) {
        uint32_t* dst = sm + stage * 2048;
#pragma unroll
        for (int i = 0; i < 4; i++) {
            int f = tid + i * 256, row = f >> 3, kq = f & 7;
            int p0 = 2 * kq;
            dst[pkidx(row, p0)]     = aU[i].x;
            dst[pkidx(row, p0 + 1)] = aU[i].y;
        }
    };

    // prologue
    cp_b(0, 0);
    cp_b(1, 1);
    uint2 aU[4];
    load_aU<AMODE>(tid, rowBase, 0, A, w1f_s, b1f_s, s2_s, t2_s, diff_s, aU);
    sts_a(0, aU);
    cp_wait<0>();
    __syncthreads();

    int lane = tid & 31, w = tid >> 5;
    int wm = w & 1, wn = w >> 1;
    int la3 = lane & 3, lg = lane >> 2;
    int axor = 4 * (la3 ^ (lg & 3));

    float acc[4][4][4];
#pragma unroll
    for (int mt = 0; mt < 4; mt++)
#pragma unroll
        for (int nt = 0; nt < 4; nt++)
#pragma unroll
            for (int r = 0; r < 4; r++) acc[mt][nt][r] = 0.f;

    const int aBase = (wm * 64 + lg) * 16 + axor;
    const int bBase = (wn * 32 + lg) * 16 + axor;

    for (int c = 0; c < 8; c++) {
        int st = c & 1;
        if (c < 7)
            load_aU<AMODE>(tid, rowBase, (c + 1) * 32, A,
                           w1f_s, b1f_s, s2_s, t2_s, diff_s, aU);
        const uint32_t* As = sm + st * 2048;
        const uint32_t* Bs = sm + SOFF_B + st * 2048;

        uint4 Vb[4];
#pragma unroll
        for (int nt = 0; nt < 4; nt++)
            Vb[nt] = *(const uint4*)&Bs[bBase + nt * 128];
#pragma unroll
        for (int mt = 0; mt < 4; mt++) {
            uint4 U0 = *(const uint4*)&As[aBase + mt * 256];
            uint4 U1 = *(const uint4*)&As[aBase + mt * 256 + 128];
            uint32_t a0[4] = {U0.x, U1.x, U0.y, U1.y};   // ks = 0
            uint32_t a1[4] = {U0.z, U1.z, U0.w, U1.w};   // ks = 1
#pragma unroll
            for (int nt = 0; nt < 4; nt++)
                mma_f16(acc[mt][nt], a0, Vb[nt].x, Vb[nt].y);
#pragma unroll
            for (int nt = 0; nt < 4; nt++)
                mma_f16(acc[mt][nt], a1, Vb[nt].z, Vb[nt].w);
        }
        if (c < 7) sts_a(st ^ 1, aU);
        cp_wait<0>();
        __syncthreads();
        if (c + 2 < 8) cp_b(st, c + 2);
    }

    // epilogue
    int nOff = blockIdx.y * 128;
#pragma unroll
    for (int mt = 0; mt < 4; mt++) {
        int row0 = rowBase + wm * 64 + mt * 16 + lg;
#pragma unroll
        for (int nt = 0; nt < 4; nt++) {
            int col = nOff + wn * 32 + nt * 8 + 2 * la3;
            float b0 = bias_s[col];
            float b1 = bias_s[col + 1];
            float v00 = acc[mt][nt][0] + b0, v01 = acc[mt][nt][1] + b1;
            float v10 = acc[mt][nt][2] + b0, v11 = acc[mt][nt][3] + b1;
            if (OUT16) {
                uint32_t* O16 = (uint32_t*)OutP;
                O16[(size_t)row0 * 128 + (col >> 1)]       = f16pk(v00, v01);
                O16[(size_t)(row0 + 8) * 128 + (col >> 1)] = f16pk(v10, v11);
            } else {
                float* Out = (float*)OutP;
                *(float2*)&Out[(size_t)row0 * 256 + col]       = make_float2(v00, v01);
                *(float2*)&Out[(size_t)(row0 + 8) * 256 + col] = make_float2(v10, v11);
            }
        }
    }
}

// ----------------------- K8: attention elementwise (fp16 in/out) ------------
__global__ void __launch_bounds__(256) attn_kernel(const float* __restrict__ convw) {
    __shared__ float cw[1024];
    __shared__ float va[8][264];
    __shared__ float red[8][256];
    int tid = threadIdx.x, w = tid >> 5, l = tid & 31;
    for (int i = tid; i < 1024; i += 256) cw[i] = convw[i];
    __syncthreads();

    float cwr[32];
#pragma unroll
    for (int i = 0; i < 32; i++) cwr[i] = cw[(l >> 2) * 128 + (l & 3) * 32 + i];

    float sum0[4] = {0, 0, 0, 0}, sum1[4] = {0, 0, 0, 0};
    float sq0[4]  = {0, 0, 0, 0}, sq1[4]  = {0, 0, 0, 0};

    int base = blockIdx.x * 512 + w * 64;
    int g0 = (l >> 3), i0 = (l & 7) * 4;

    for (int it = 0; it < 64; it++) {
        int r = base + it;
        const uint2* dm2 = (const uint2*)(g_dm16 + (size_t)r * 128);
        const uint2* db2 = (const uint2*)(g_db16 + (size_t)r * 128);
        const uint2* k2  = (const uint2*)(g_k16  + (size_t)r * 128);
        const uint2* v2  = (const uint2*)(g_v16  + (size_t)r * 128);
        const uint2* q2  = (const uint2*)(g_q16  + (size_t)(r >> 4) * 128);

        uint2 udm0 = dm2[l], udm1 = dm2[32 + l];
        uint2 udb0 = db2[l], udb1 = db2[32 + l];
        uint2 uk0  = k2[l],  uk1  = k2[32 + l];
        uint2 uv0  = v2[l],  uv1  = v2[32 + l];
        uint2 uq0  = q2[l],  uq1  = q2[32 + l];

        float2 dmA = upk(udm0.x), dmB = upk(udm0.y), dmC = upk(udm1.x), dmD = upk(udm1.y);
        float2 dbA = upk(udb0.x), dbB = upk(udb0.y), dbC = upk(udb1.x), dbD = upk(udb1.y);
        float2 kA  = upk(uk0.x),  kB  = upk(uk0.y),  kC  = upk(uk1.x),  kD  = upk(uk1.y);
        float2 vA  = upk(uv0.x),  vB  = upk(uv0.y),  vC  = upk(uv1.x),  vD  = upk(uv1.y);
        float2 qA  = upk(uq0.x),  qB  = upk(uq0.y),  qC  = upk(uq1.x),  qD  = upk(uq1.y);

        float va0[4], va1[4];
        va0[0] = fmaf(dmA.x, qA.x - kA.x, dbA.x);
        va0[1] = fmaf(dmA.y, qA.y - kA.y, dbA.y);
        va0[2] = fmaf(dmB.x, qB.x - kB.x, dbB.x);
        va0[3] = fmaf(dmB.y, qB.y - kB.y, dbB.y);
        va1[0] = fmaf(dmC.x, qC.x - kC.x, dbC.x);
        va1[1] = fmaf(dmC.y, qC.y - kC.y, dbC.y);
        va1[2] = fmaf(dmD.x, qD.x - kD.x, dbD.x);
        va1[3] = fmaf(dmD.y, qD.y - kD.y, dbD.y);
#pragma unroll
        for (int t = 0; t < 4; t++) {
            va[w][g0 * 33 + i0 + t]       = va0[t];
            va[w][(4 + g0) * 33 + i0 + t] = va1[t];
        }
        __syncwarp();

        float acc = 0.f;
#pragma unroll
        for (int i = 0; i < 32; i++) acc = fmaf(va[w][(l >> 2) * 33 + i], cwr[i], acc);

        float mx = acc;
#pragma unroll
        for (int off = 16; off > 0; off >>= 1)
            mx = fmaxf(mx, __shfl_xor_sync(0xffffffffu, mx, off));
        float e = expf(acc - mx);
        float ssum = e;
#pragma unroll
        for (int off = 16; off > 0; off >>= 1)
            ssum += __shfl_xor_sync(0xffffffffu, ssum, off);
        float ome = e / ssum;

        float o0 = __shfl_sync(0xffffffffu, ome, l >> 1);
        float o1 = __shfl_sync(0xffffffffu, ome, 16 + (l >> 1));

        float we0[4] = {o0 * vA.x, o0 * vA.y, o0 * vB.x, o0 * vB.y};
        float we1[4] = {o1 * vC.x, o1 * vC.y, o1 * vD.x, o1 * vD.y};
        uint2* we2 = (uint2*)(g_we16 + (size_t)r * 128);
        we2[l]      = make_uint2(f16pk(we0[0], we0[1]), f16pk(we0[2], we0[3]));
        we2[32 + l] = make_uint2(f16pk(we1[0], we1[1]), f16pk(we1[2], we1[3]));

#pragma unroll
        for (int t = 0; t < 4; t++) {
            sum0[t] += we0[t]; sum1[t] += we1[t];
            sq0[t]  += we0[t] * we0[t]; sq1[t] += we1[t] * we1[t];
        }
        __syncwarp();
    }

#pragma unroll
    for (int t = 0; t < 4; t++) {
        red[w][4 * l + t]       = sum0[t];
        red[w][128 + 4 * l + t] = sum1[t];
    }
    __syncthreads();
    {
        float a = 0.f;
#pragma unroll
        for (int ww = 0; ww < 8; ww++) a += red[ww][tid];
        g_part2[blockIdx.x * 512 + tid] = a;
    }
    __syncthreads();
#pragma unroll
    for (int t = 0; t < 4; t++) {
        red[w][4 * l + t]       = sq0[t];
        red[w][128 + 4 * l + t] = sq1[t];
    }
    __syncthreads();
    {
        float a = 0.f;
#pragma unroll
        for (int ww = 0; ww < 8; ww++) a += red[ww][tid];
        g_part2[blockIdx.x * 512 + 256 + tid] = a;
    }
}

// --------------------------- K9: BN2 finalize -------------------------------
__global__ void finalize2_kernel(const float* __restrict__ bn_g,
                                 const float* __restrict__ bn_b) {
    int c = threadIdx.x;
    float s = 0.f, sq = 0.f;
    for (int b = 0; b < ATTN_BLOCKS; b++) {
        s  += g_part2[b * 512 + c];
        sq += g_part2[b * 512 + 256 + c];
    }
    float mean = s / (float)R_;
    float var = sq / (float)R_ - mean * mean;
    float sc = bn_g[c] * rsqrtf(var + EPSV);
    g_s2[c] = sc;
    g_t2[c] = bn_b[c] - mean * sc;
}

// ------------------------------- launch -------------------------------------
extern "C" void kernel_launch(void* const* d_in, const int* in_sizes, int n_in,
                              void* d_out, int out_size) {
    const float* pts   = (const float*)d_in[0];
    const float* pf    = (const float*)d_in[1];
    const float* nbr   = (const float*)d_in[2];
    const float* nf    = (const float*)d_in[3];
    const float* dm_w1 = (const float*)d_in[4];
    const float* dm_b1 = (const float*)d_in[5];
    const float* dm_w2 = (const float*)d_in[6];
    const float* dm_b2 = (const float*)d_in[7];
    const float* dm_g  = (const float*)d_in[8];
    const float* dm_be = (const float*)d_in[9];
    const float* db_w1 = (const float*)d_in[10];
    const float* db_b1 = (const float*)d_in[11];
    const float* db_w2 = (const float*)d_in[12];
    const float* db_b2 = (const float*)d_in[13];
    const float* db_g  = (const float*)d_in[14];
    const float* db_be = (const float*)d_in[15];
    const float* q_w   = (const float*)d_in[16];
    const float* q_b   = (const float*)d_in[17];
    const float* k_w   = (const float*)d_in[18];
    const float* k_b   = (const float*)d_in[19];
    const float* v_w   = (const float*)d_in[20];
    const float* v_b   = (const float*)d_in[21];
    const float* convw = (const float*)d_in[22];
    const float* bn_g  = (const float*)d_in[23];
    const float* bn_b  = (const float*)d_in[24];
    const float* lin_w = (const float*)d_in[25];
    const float* lin_b = (const float*)d_in[26];
    float* out = (float*)d_out;

    void *p_q, *p_dm, *p_db, *p_k, *p_v, *p_we, *p_bpk;
    cudaGetSymbolAddress(&p_q,  g_q16);
    cudaGetSymbolAddress(&p_dm, g_dm16);
    cudaGetSymbolAddress(&p_db, g_db16);
    cudaGetSymbolAddress(&p_k,  g_k16);
    cudaGetSymbolAddress(&p_v,  g_v16);
    cudaGetSymbolAddress(&p_we, g_we16);
    cudaGetSymbolAddress(&p_bpk, g_Bpk);
    const uint32_t* Bpk = (const uint32_t*)p_bpk;

    cudaFuncSetAttribute(gemm_mma<AMODE_DIRECT, true>,
                         cudaFuncAttributeMaxDynamicSharedMemorySize, DYN_SMEM);
    cudaFuncSetAttribute(gemm_mma<AMODE_POS, true>,
                         cudaFuncAttributeMaxDynamicSharedMemorySize, DYN_SMEM);
    cudaFuncSetAttribute(gemm_mma<AMODE_F16BN, false>,
                         cudaFuncAttributeMaxDynamicSharedMemorySize, DYN_SMEM);

    prep_weights<<<dim3(8, 2, 6), 256>>>(q_w, k_w, v_w, dm_w2, db_w2, lin_w);
    diffstats_kernel<<<STAT_BLOCKS, 256>>>(pts, nbr);
    fold_kernel<<<1, 256>>>(dm_w1, dm_b1, dm_g, dm_be, db_w1, db_b1, db_g, db_be);

    dim3 gq(BNp / 128, 2);
    dim3 gr(R_ / 128, 2);
    gemm_mma<AMODE_DIRECT, true><<<gq, 256, DYN_SMEM>>>(
        pf, Bpk + 0 * 32768, q_b, p_q, nullptr, nullptr, 0);
    gemm_mma<AMODE_POS, true><<<gr, 256, DYN_SMEM>>>(
        nullptr, Bpk + 3 * 32768, dm_b2, p_dm, pts, nbr, 0);
    gemm_mma<AMODE_POS, true><<<gr, 256, DYN_SMEM>>>(
        nullptr, Bpk + 4 * 32768, db_b2, p_db, pts, nbr, 1);
    gemm_mma<AMODE_DIRECT, true><<<gr, 256, DYN_SMEM>>>(
        nf, Bpk + 1 * 32768, k_b, p_k, nullptr, nullptr, 0);
    gemm_mma<AMODE_DIRECT, true><<<gr, 256, DYN_SMEM>>>(
        nf, Bpk + 2 * 32768, v_b, p_v, nullptr, nullptr, 0);

    attn_kernel<<<ATTN_BLOCKS, 256>>>(convw);
    finalize2_kernel<<<1, 256>>>(bn_g, bn_b);

    gemm_mma<AMODE_F16BN, false><<<gr, 256, DYN_SMEM>>>(
        p_we, Bpk + 5 * 32768, lin_b, out, nullptr, nullptr, 0);
}

// round 7
// speedup vs baseline: 2.0867x; 1.0975x over previous
#include <cuda_runtime.h>
#include <cstdint>

// ---------------------------------------------------------------------------
// GroupVectorAttention — fully fused produce+attention kernel.
// Per 128-row tile (one CTA, ~204KB smem): k-GEMM -> qk=q-k (smem fp16),
// dm-GEMM -> va=dm*qk, db-GEMM -> va+=db, in-smem softmax -> omega,
// v-GEMM -> we=omega*v (only DRAM write) + deterministic BN2 partials.
// Eliminates ~1.1GB of intermediate DRAM traffic vs R6.
// ---------------------------------------------------------------------------

#define EPSV 1e-5f

static constexpr int Bb = 4, Nn = 4096, Mm = 16, Cd = 256;
static constexpr int R_ = Bb * Nn * Mm;       // 262144
static constexpr int BNp = Bb * Nn;           // 16384
static constexpr int STAT_BLOCKS = 256;
static constexpr int NTILES = R_ / 128;       // 2048

// ---- gemm_mma (q / final) smem layout (u32 units) ----
static constexpr int SOFF_B  = 4096;
static constexpr int SOFF_FX = 8192;
static constexpr int FX_BIAS = 0, FX_S2 = 1280, FX_T2 = 1536;
static constexpr int DYN_SMEM = (8192 + 2304) * 4;

// ---- fused kernel smem layout (u32 units) ----
static constexpr int FS_ASTG = 0;                 // 2*2048
static constexpr int FS_BSTG = 4096;              // 2*2048
static constexpr int FS_ANF  = 8192;              // 8*2048
static constexpr int FS_VA   = 24576;             // 128*132
static constexpr int FS_Q    = 41472;             // 1024
static constexpr int FS_OM   = 42496;             // 128*36 (fp32)
static constexpr int FS_FX   = 47104;             // floats:
static constexpr int FXF_KB = 0, FXF_DMB = 256, FXF_DBB = 512, FXF_VB = 768,
                     FXF_CW = 1024, FXF_W1F = 2048, FXF_B1F = 3584,
                     FXF_DIFF = 4096, FXF_RED = 4608;   // 512
static constexpr int FUSED_SMEM = (47104 + 5120) * 4;    // 208896 B

// ------------------------- device scratch (static) -------------------------
__device__ float g_part1[STAT_BLOCKS * 12];
__device__ float g_w1f[2][Cd * 3];
__device__ float g_b1f[2][Cd];
__device__ uint32_t g_q16[BNp * 128];
__device__ uint32_t g_we16[(size_t)R_ * 128];
__device__ float g_part2[(size_t)NTILES * 512];
__device__ float g_part2r[64 * 512];
__device__ float g_s2[Cd], g_t2[Cd];
// packed fp16 weight images: [mat(6)][nb(2)][chunk(8)][2048 u32]
__device__ uint32_t g_Bpk[6 * 2 * 8 * 2048];

// ----------------------------- PTX helpers ---------------------------------
__device__ __forceinline__ uint32_t smem_u32(const void* p) {
    uint32_t a;
    asm("{ .reg .u64 t; cvta.to.shared.u64 t, %1; cvt.u32.u64 %0, t; }"
        : "=r"(a) : "l"(p));
    return a;
}
__device__ __forceinline__ void cp16(uint32_t dst, const void* src) {
    asm volatile("cp.async.cg.shared.global [%0], [%1], 16;"
                 :: "r"(dst), "l"(src) : "memory");
}
__device__ __forceinline__ void cp_commit() {
    asm volatile("cp.async.commit_group;" ::: "memory");
}
template <int N>
__device__ __forceinline__ void cp_wait() {
    asm volatile("cp.async.wait_group %0;" :: "n"(N) : "memory");
}
__device__ __forceinline__ void mma_f16(float* c, const uint32_t* a,
                                        uint32_t b0, uint32_t b1) {
    asm volatile("mma.sync.aligned.m16n8k16.row.col.f32.f16.f16.f32 "
                 "{%0,%1,%2,%3}, {%4,%5,%6,%7}, {%8,%9}, {%0,%1,%2,%3};"
                 : "+f"(c[0]), "+f"(c[1]), "+f"(c[2]), "+f"(c[3])
                 : "r"(a[0]), "r"(a[1]), "r"(a[2]), "r"(a[3]),
                   "r"(b0), "r"(b1));
}
__device__ __forceinline__ uint32_t f16pk(float lo, float hi) {
    uint32_t r;
    asm("cvt.rn.f16x2.f32 %0, %1, %2;" : "=r"(r) : "f"(hi), "f"(lo));
    return r;
}
__device__ __forceinline__ float2 upk(uint32_t u) {
    float2 f;
    asm("{ .reg .b16 lo, hi; mov.b32 {lo, hi}, %2; "
        "cvt.f32.f16 %0, lo; cvt.f32.f16 %1, hi; }"
        : "=f"(f.x), "=f"(f.y) : "r"(u));
    return f;
}
__device__ __forceinline__ int pkidx(int n, int p) {
    return n * 16 + 4 * ((p & 3) ^ (n & 3)) + 2 * (p >> 3) + ((p >> 2) & 1);
}

// ------------------------------- K1: stats --------------------------------
__global__ void diffstats_kernel(const float* __restrict__ pts,
                                 const float* __restrict__ nbr) {
    float s[12];
#pragma unroll
    for (int i = 0; i < 12; i++) s[i] = 0.f;
    int tid = threadIdx.x;
    for (int r = blockIdx.x * blockDim.x + tid; r < R_; r += gridDim.x * blockDim.x) {
        int bn = r >> 4;
        float d[3];
#pragma unroll
        for (int j = 0; j < 3; j++) d[j] = pts[bn * 3 + j] - nbr[(size_t)r * 3 + j];
#pragma unroll
        for (int j = 0; j < 3; j++) s[j] += d[j];
#pragma unroll
        for (int j = 0; j < 3; j++)
#pragma unroll
            for (int k = 0; k < 3; k++) s[3 + j * 3 + k] += d[j] * d[k];
    }
    __shared__ float red[256];
    for (int comp = 0; comp < 12; comp++) {
        red[tid] = s[comp];
        __syncthreads();
        for (int off = 128; off > 0; off >>= 1) {
            if (tid < off) red[tid] += red[tid + off];
            __syncthreads();
        }
        if (tid == 0) g_part1[blockIdx.x * 12 + comp] = red[0];
        __syncthreads();
    }
}

// ------------------------------ K2: BN1 fold -------------------------------
__global__ void fold_kernel(const float* __restrict__ dm_w1, const float* __restrict__ dm_b1,
                            const float* __restrict__ dm_g,  const float* __restrict__ dm_be,
                            const float* __restrict__ db_w1, const float* __restrict__ db_b1,
                            const float* __restrict__ db_g,  const float* __restrict__ db_be) {
    __shared__ float st[12];
    __shared__ float mu[3], cov[9];
    int tid = threadIdx.x;
    if (tid < 12) {
        float a = 0.f;
        for (int b = 0; b < STAT_BLOCKS; b++) a += g_part1[b * 12 + tid];
        st[tid] = a / (float)R_;
    }
    __syncthreads();
    if (tid < 3) mu[tid] = st[tid];
    if (tid < 9) {
        int j = tid / 3, k = tid % 3;
        cov[tid] = st[3 + tid] - st[j] * st[k];
    }
    __syncthreads();
    int c = tid;
    for (int which = 0; which < 2; which++) {
        const float* w1 = which ? db_w1 : dm_w1;
        const float* b1 = which ? db_b1 : dm_b1;
        const float* gg = which ? db_g  : dm_g;
        const float* be = which ? db_be : dm_be;
        float w0 = w1[c * 3], w1v = w1[c * 3 + 1], w2v = w1[c * 3 + 2];
        float var = w0 * w0 * cov[0] + w1v * w1v * cov[4] + w2v * w2v * cov[8]
                  + 2.f * (w0 * w1v * cov[1] + w0 * w2v * cov[2] + w1v * w2v * cov[5]);
        float mdot = w0 * mu[0] + w1v * mu[1] + w2v * mu[2];
        float m = mdot + b1[c];
        float s = gg[c] * rsqrtf(var + EPSV);
        g_w1f[which][c * 3]     = w0 * s;
        g_w1f[which][c * 3 + 1] = w1v * s;
        g_w1f[which][c * 3 + 2] = w2v * s;
        g_b1f[which][c] = be[c] + s * (b1[c] - m);
    }
}

// ----------------------- weight prep: fp32 -> packed fp16 -------------------
__global__ void prep_weights(const float* __restrict__ q_w, const float* __restrict__ k_w,
                             const float* __restrict__ v_w, const float* __restrict__ dm_w2,
                             const float* __restrict__ db_w2, const float* __restrict__ lin_w) {
    int c = blockIdx.x, nb = blockIdx.y, mat = blockIdx.z;
    const float* W = mat == 0 ? q_w : mat == 1 ? k_w : mat == 2 ? v_w :
                     mat == 3 ? dm_w2 : mat == 4 ? db_w2 : lin_w;
    uint32_t* dst = g_Bpk + (((size_t)mat * 2 + nb) * 8 + c) * 2048;
    int tid = threadIdx.x;
    int n = tid >> 1, q = tid & 1;
    const float* src = W + (size_t)(nb * 128 + n) * 256 + c * 32 + q * 16;
    float cc[16];
#pragma unroll
    for (int j = 0; j < 16; j += 4) {
        float4 v = *(const float4*)&src[j];
        cc[j] = v.x; cc[j + 1] = v.y; cc[j + 2] = v.z; cc[j + 3] = v.w;
    }
#pragma unroll
    for (int t = 0; t < 4; t++)
#pragma unroll
        for (int u = 0; u < 2; u++) {
            int p = 8 * q + t + 4 * u;
            dst[pkidx(n, p)] = f16pk(cc[2 * t + 8 * u], cc[2 * t + 8 * u + 1]);
        }
}

// ----------------------- standalone GEMM (q + final) ------------------------
enum { AMODE_DIRECT = 0, AMODE_F16BN = 2 };

template <int AMODE>
__device__ __forceinline__ void load_aU(
    int tid, int rowBase, int kb, const void* __restrict__ Ap,
    const float* s2_s, const float* t2_s, uint2 aU[4]) {
#pragma unroll
    for (int i = 0; i < 4; i++) {
        int f = tid + i * 256, row = f >> 3, kq = f & 7;
        if (AMODE == AMODE_DIRECT) {
            const float* A = (const float*)Ap;
            float4 v = *(const float4*)&A[(size_t)(rowBase + row) * 256 + kb + kq * 4];
            aU[i].x = f16pk(v.x, v.y);
            aU[i].y = f16pk(v.z, v.w);
        } else {
            const uint32_t* A16 = (const uint32_t*)Ap;
            uint2 u = *(const uint2*)&A16[(size_t)(rowBase + row) * 128 + (kb >> 1) + kq * 2];
            float2 f0 = upk(u.x), f1 = upk(u.y);
            int k = kb + kq * 4;
            float x0 = fmaxf(fmaf(f0.x, s2_s[k],     t2_s[k]),     0.f);
            float x1 = fmaxf(fmaf(f0.y, s2_s[k + 1], t2_s[k + 1]), 0.f);
            float x2 = fmaxf(fmaf(f1.x, s2_s[k + 2], t2_s[k + 2]), 0.f);
            float x3 = fmaxf(fmaf(f1.y, s2_s[k + 3], t2_s[k + 3]), 0.f);
            aU[i].x = f16pk(x0, x1);
            aU[i].y = f16pk(x2, x3);
        }
    }
}

template <int AMODE, bool OUT16>
__global__ void __launch_bounds__(256, 2)
gemm_mma(const void* __restrict__ A, const uint32_t* __restrict__ Bpk,
         const float* __restrict__ bias, void* __restrict__ OutP) {
    extern __shared__ uint32_t sm[];
    float* fx     = (float*)(sm + SOFF_FX);
    float* bias_s = fx + FX_BIAS;
    float* s2_s   = fx + FX_S2;
    float* t2_s   = fx + FX_T2;

    int tid = threadIdx.x;
    int rowBase = blockIdx.x * 128;

    bias_s[tid] = bias[tid];
    if (AMODE == AMODE_F16BN) {
        s2_s[tid] = g_s2[tid];
        t2_s[tid] = g_t2[tid];
    }
    __syncthreads();

    uint32_t smemB_addr = smem_u32(sm + SOFF_B);
    const uint32_t* BpkNb = Bpk + (size_t)blockIdx.y * 16384;

    auto cp_b = [&](int stage, int c) {
        const uint32_t* src = BpkNb + c * 2048;
        uint32_t dstb = smemB_addr + (uint32_t)stage * 8192u;
#pragma unroll
        for (int i = 0; i < 2; i++) {
            int e = tid + i * 256;
            cp16(dstb + (uint32_t)e * 16u, src + e * 4);
        }
        cp_commit();
    };
    auto sts_a = [&](int stage, const uint2* aU) {
        uint32_t* dst = sm + stage * 2048;
#pragma unroll
        for (int i = 0; i < 4; i++) {
            int f = tid + i * 256, row = f >> 3, kq = f & 7;
            int p0 = 2 * kq;
            dst[pkidx(row, p0)]     = aU[i].x;
            dst[pkidx(row, p0 + 1)] = aU[i].y;
        }
    };

    cp_b(0, 0);
    cp_b(1, 1);
    uint2 aU[4];
    load_aU<AMODE>(tid, rowBase, 0, A, s2_s, t2_s, aU);
    sts_a(0, aU);
    cp_wait<0>();
    __syncthreads();

    int lane = tid & 31, w = tid >> 5;
    int wm = w & 1, wn = w >> 1;
    int la3 = lane & 3, lg = lane >> 2;
    int axor = 4 * (la3 ^ (lg & 3));

    float acc[4][4][4];
#pragma unroll
    for (int mt = 0; mt < 4; mt++)
#pragma unroll
        for (int nt = 0; nt < 4; nt++)
#pragma unroll
            for (int r = 0; r < 4; r++) acc[mt][nt][r] = 0.f;

    const int aBase = (wm * 64 + lg) * 16 + axor;
    const int bBase = (wn * 32 + lg) * 16 + axor;

    for (int c = 0; c < 8; c++) {
        int st = c & 1;
        if (c < 7)
            load_aU<AMODE>(tid, rowBase, (c + 1) * 32, A, s2_s, t2_s, aU);
        const uint32_t* As = sm + st * 2048;
        const uint32_t* Bs = sm + SOFF_B + st * 2048;

        uint4 Vb[4];
#pragma unroll
        for (int nt = 0; nt < 4; nt++)
            Vb[nt] = *(const uint4*)&Bs[bBase + nt * 128];
#pragma unroll
        for (int mt = 0; mt < 4; mt++) {
            uint4 U0 = *(const uint4*)&As[aBase + mt * 256];
            uint4 U1 = *(const uint4*)&As[aBase + mt * 256 + 128];
            uint32_t a0[4] = {U0.x, U1.x, U0.y, U1.y};
            uint32_t a1[4] = {U0.z, U1.z, U0.w, U1.w};
#pragma unroll
            for (int nt = 0; nt < 4; nt++)
                mma_f16(acc[mt][nt], a0, Vb[nt].x, Vb[nt].y);
#pragma unroll
            for (int nt = 0; nt < 4; nt++)
                mma_f16(acc[mt][nt], a1, Vb[nt].z, Vb[nt].w);
        }
        if (c < 7) sts_a(st ^ 1, aU);
        cp_wait<0>();
        __syncthreads();
        if (c + 2 < 8) cp_b(st, c + 2);
    }

    int nOff = blockIdx.y * 128;
#pragma unroll
    for (int mt = 0; mt < 4; mt++) {
        int row0 = rowBase + wm * 64 + mt * 16 + lg;
#pragma unroll
        for (int nt = 0; nt < 4; nt++) {
            int col = nOff + wn * 32 + nt * 8 + 2 * la3;
            float b0 = bias_s[col];
            float b1 = bias_s[col + 1];
            float v00 = acc[mt][nt][0] + b0, v01 = acc[mt][nt][1] + b1;
            float v10 = acc[mt][nt][2] + b0, v11 = acc[mt][nt][3] + b1;
            if (OUT16) {
                uint32_t* O16 = (uint32_t*)OutP;
                O16[(size_t)row0 * 128 + (col >> 1)]       = f16pk(v00, v01);
                O16[(size_t)(row0 + 8) * 128 + (col >> 1)] = f16pk(v10, v11);
            } else {
                float* Out = (float*)OutP;
                *(float2*)&Out[(size_t)row0 * 256 + col]       = make_float2(v00, v01);
                *(float2*)&Out[(size_t)(row0 + 8) * 256 + col] = make_float2(v10, v11);
            }
        }
    }
}

// ----------------------- fused produce+attention kernel ---------------------
// EPI: 0 = qk = q - k ; 1 = va = dm*qk ; 2 = va += db ; 3 = we = omega*v
template <int EPI, bool ANF>
__device__ __noinline__ void run_subpass(
    uint32_t* sm, int tid, int rowBase, int nb,
    const uint32_t* __restrict__ Bmat,
    const float* bias_s, const float* w1f_s, const float* b1f_s,
    const float* diff_s, int blockId) {

    uint32_t smemB_addr = smem_u32(sm + FS_BSTG);
    auto cp_b = [&](int stage, int c) {
        const uint32_t* src = Bmat + (size_t)(nb * 8 + c) * 2048;
        uint32_t dstb = smemB_addr + (uint32_t)stage * 8192u;
#pragma unroll
        for (int i = 0; i < 2; i++) {
            int e = tid + i * 256;
            cp16(dstb + (uint32_t)e * 16u, src + e * 4);
        }
        cp_commit();
    };

    uint2 aU[4];
    auto load_pos = [&](int kb) {
#pragma unroll
        for (int i = 0; i < 4; i++) {
            int f = tid + i * 256, row = f >> 3, kq = f & 7;
            float d0 = diff_s[row * 4], d1 = diff_s[row * 4 + 1], d2 = diff_s[row * 4 + 2];
            float t[4];
#pragma unroll
            for (int j = 0; j < 4; j++) {
                int k = kb + kq * 4 + j;
                float h = fmaf(d0, w1f_s[k * 3],
                          fmaf(d1, w1f_s[k * 3 + 1],
                          fmaf(d2, w1f_s[k * 3 + 2], b1f_s[k])));
                t[j] = fmaxf(h, 0.f);
            }
            aU[i].x = f16pk(t[0], t[1]);
            aU[i].y = f16pk(t[2], t[3]);
        }
    };
    auto sts_a = [&](int stage) {
        uint32_t* dst = sm + FS_ASTG + stage * 2048;
#pragma unroll
        for (int i = 0; i < 4; i++) {
            int f = tid + i * 256, row = f >> 3, kq = f & 7;
            dst[pkidx(row, 2 * kq)]     = aU[i].x;
            dst[pkidx(row, 2 * kq + 1)] = aU[i].y;
        }
    };

    cp_b(0, 0);
    cp_b(1, 1);
    if (!ANF) { load_pos(0); sts_a(0); }
    cp_wait<0>();
    __syncthreads();

    int lane = tid & 31, w = tid >> 5;
    int wm = w & 1, wn = w >> 1;
    int la3 = lane & 3, lg = lane >> 2;
    int axor = 4 * (la3 ^ (lg & 3));
    const int aOff = (wm * 64 + lg) * 16 + axor;
    const int bOff = (wn * 32 + lg) * 16 + axor;

    float acc[4][4][4];
#pragma unroll
    for (int mt = 0; mt < 4; mt++)
#pragma unroll
        for (int nt = 0; nt < 4; nt++)
#pragma unroll
            for (int r = 0; r < 4; r++) acc[mt][nt][r] = 0.f;

    for (int c = 0; c < 8; c++) {
        int st = c & 1;
        if (!ANF && c < 7) load_pos((c + 1) * 32);
        const uint32_t* As = ANF ? (sm + FS_ANF + c * 2048)
                                 : (sm + FS_ASTG + st * 2048);
        const uint32_t* Bs = sm + FS_BSTG + st * 2048;

        uint4 Vb[4];
#pragma unroll
        for (int nt = 0; nt < 4; nt++)
            Vb[nt] = *(const uint4*)&Bs[bOff + nt * 128];
#pragma unroll
        for (int mt = 0; mt < 4; mt++) {
            uint4 U0 = *(const uint4*)&As[aOff + mt * 256];
            uint4 U1 = *(const uint4*)&As[aOff + mt * 256 + 128];
            uint32_t a0[4] = {U0.x, U1.x, U0.y, U1.y};
            uint32_t a1[4] = {U0.z, U1.z, U0.w, U1.w};
#pragma unroll
            for (int nt = 0; nt < 4; nt++)
                mma_f16(acc[mt][nt], a0, Vb[nt].x, Vb[nt].y);
#pragma unroll
            for (int nt = 0; nt < 4; nt++)
                mma_f16(acc[mt][nt], a1, Vb[nt].z, Vb[nt].w);
        }
        if (!ANF && c < 7) sts_a(st ^ 1);
        cp_wait<0>();
        __syncthreads();
        if (c + 2 < 8) cp_b(st, c + 2);
    }

    // ---- epilogue ----
    float csum[8], csq[8];
#pragma unroll
    for (int j = 0; j < 8; j++) { csum[j] = 0.f; csq[j] = 0.f; }

#pragma unroll
    for (int mt = 0; mt < 4; mt++) {
        int row0 = wm * 64 + mt * 16 + lg;
#pragma unroll
        for (int nt = 0; nt < 4; nt++) {
            int col = nb * 128 + wn * 32 + nt * 8 + 2 * la3;
            float b0 = bias_s[col], b1 = bias_s[col + 1];
            int vi0 = row0 * 132 + (col >> 1);
            int vi1 = (row0 + 8) * 132 + (col >> 1);
            float a0 = acc[mt][nt][0] + b0, a1 = acc[mt][nt][1] + b1;
            float a2 = acc[mt][nt][2] + b0, a3 = acc[mt][nt][3] + b1;
            if (EPI == 0) {
                float2 qv = upk(sm[FS_Q + (wm * 4 + mt) * 128 + (col >> 1)]);
                sm[FS_VA + vi0] = f16pk(qv.x - a0, qv.y - a1);
                sm[FS_VA + vi1] = f16pk(qv.x - a2, qv.y - a3);
            } else if (EPI == 1) {
                float2 u0 = upk(sm[FS_VA + vi0]), u1 = upk(sm[FS_VA + vi1]);
                sm[FS_VA + vi0] = f16pk(a0 * u0.x, a1 * u0.y);
                sm[FS_VA + vi1] = f16pk(a2 * u1.x, a3 * u1.y);
            } else if (EPI == 2) {
                float2 u0 = upk(sm[FS_VA + vi0]), u1 = upk(sm[FS_VA + vi1]);
                sm[FS_VA + vi0] = f16pk(u0.x + a0, u0.y + a1);
                sm[FS_VA + vi1] = f16pk(u1.x + a2, u1.y + a3);
            } else {
                const float* om = (const float*)(sm + FS_OM);
                float o0 = om[row0 * 36 + (col >> 3)];
                float o1 = om[(row0 + 8) * 36 + (col >> 3)];
                float w00 = o0 * a0, w01 = o0 * a1;
                float w10 = o1 * a2, w11 = o1 * a3;
                g_we16[(size_t)(rowBase + row0) * 128 + (col >> 1)]     = f16pk(w00, w01);
                g_we16[(size_t)(rowBase + row0 + 8) * 128 + (col >> 1)] = f16pk(w10, w11);
                csum[nt * 2]     += w00 + w10;
                csum[nt * 2 + 1] += w01 + w11;
                csq[nt * 2]      += w00 * w00 + w10 * w10;
                csq[nt * 2 + 1]  += w01 * w01 + w11 * w11;
            }
        }
    }
    if (EPI == 3) {
        // deterministic reduce over lg (lane bits 2..4)
#pragma unroll
        for (int j = 0; j < 8; j++) {
#pragma unroll
            for (int off = 4; off < 32; off <<= 1) {
                csum[j] += __shfl_xor_sync(0xffffffffu, csum[j], off);
                csq[j]  += __shfl_xor_sync(0xffffffffu, csq[j],  off);
            }
        }
        float* red = (float*)(sm + FS_FX) + FXF_RED;
        if (lg == 0) {
#pragma unroll
            for (int u = 0; u < 8; u++) {
                int nt = u >> 1, uu = u & 1;
                int lc = nt * 8 + 2 * la3 + uu;
                red[w * 64 + lc]      = csum[u];
                red[w * 64 + 32 + lc] = csq[u];
            }
        }
        __syncthreads();
        if (tid < 128) {
            int lc = tid, wn2 = lc >> 5, idx = lc & 31;
            float s  = red[(wn2 * 2) * 64 + idx]      + red[(wn2 * 2 + 1) * 64 + idx];
            float sq = red[(wn2 * 2) * 64 + 32 + idx] + red[(wn2 * 2 + 1) * 64 + 32 + idx];
            g_part2[(size_t)blockId * 512 + nb * 128 + lc]       = s;
            g_part2[(size_t)blockId * 512 + 256 + nb * 128 + lc] = sq;
        }
        __syncthreads();
    } else {
        __syncthreads();
    }
}

__global__ void __launch_bounds__(256, 1)
fused_kernel(const float* __restrict__ nf, const float* __restrict__ pts,
             const float* __restrict__ nbr,
             const float* __restrict__ k_b, const float* __restrict__ dm_b2,
             const float* __restrict__ db_b2, const float* __restrict__ v_b,
             const float* __restrict__ convw) {
    extern __shared__ uint32_t sm[];
    float* fx = (float*)(sm + FS_FX);
    int tid = threadIdx.x;
    int rowBase = blockIdx.x * 128;

    fx[FXF_KB + tid]  = k_b[tid];
    fx[FXF_DMB + tid] = dm_b2[tid];
    fx[FXF_DBB + tid] = db_b2[tid];
    fx[FXF_VB + tid]  = v_b[tid];
    for (int i = tid; i < 1024; i += 256) fx[FXF_CW + i] = convw[i];
    for (int i = tid; i < 768; i += 256) {
        fx[FXF_W1F + i]       = g_w1f[0][i];
        fx[FXF_W1F + 768 + i] = g_w1f[1][i];
    }
    fx[FXF_B1F + tid]       = g_b1f[0][tid];
    fx[FXF_B1F + 256 + tid] = g_b1f[1][tid];
    if (tid < 128) {
        int r = rowBase + tid, bn = r >> 4;
        fx[FXF_DIFF + tid * 4 + 0] = pts[bn * 3 + 0] - nbr[(size_t)r * 3 + 0];
        fx[FXF_DIFF + tid * 4 + 1] = pts[bn * 3 + 1] - nbr[(size_t)r * 3 + 1];
        fx[FXF_DIFF + tid * 4 + 2] = pts[bn * 3 + 2] - nbr[(size_t)r * 3 + 2];
    }
    {
        int bnb = rowBase >> 4;
        for (int i = tid; i < 1024; i += 256) sm[FS_Q + i] = g_q16[bnb * 128 + i];
    }
    // stage nf as packed fp16 (reused by k and v passes)
    for (int c = 0; c < 8; c++) {
#pragma unroll
        for (int i = 0; i < 4; i++) {
            int f = tid + i * 256, row = f >> 3, kq = f & 7;
            float4 v = *(const float4*)&nf[(size_t)(rowBase + row) * 256 + c * 32 + kq * 4];
            uint32_t* dst = sm + FS_ANF + c * 2048;
            dst[pkidx(row, 2 * kq)]     = f16pk(v.x, v.y);
            dst[pkidx(row, 2 * kq + 1)] = f16pk(v.z, v.w);
        }
    }
    __syncthreads();

    const uint32_t* BK  = g_Bpk + 1 * 32768;
    const uint32_t* BV  = g_Bpk + 2 * 32768;
    const uint32_t* BDM = g_Bpk + 3 * 32768;
    const uint32_t* BDB = g_Bpk + 4 * 32768;
    const float* diff_s = fx + FXF_DIFF;

    run_subpass<0, true >(sm, tid, rowBase, 0, BK,  fx + FXF_KB,  nullptr, nullptr, diff_s, blockIdx.x);
    run_subpass<0, true >(sm, tid, rowBase, 1, BK,  fx + FXF_KB,  nullptr, nullptr, diff_s, blockIdx.x);
    run_subpass<1, false>(sm, tid, rowBase, 0, BDM, fx + FXF_DMB, fx + FXF_W1F,       fx + FXF_B1F,       diff_s, blockIdx.x);
    run_subpass<1, false>(sm, tid, rowBase, 1, BDM, fx + FXF_DMB, fx + FXF_W1F,       fx + FXF_B1F,       diff_s, blockIdx.x);
    run_subpass<2, false>(sm, tid, rowBase, 0, BDB, fx + FXF_DBB, fx + FXF_W1F + 768, fx + FXF_B1F + 256, diff_s, blockIdx.x);
    run_subpass<2, false>(sm, tid, rowBase, 1, BDB, fx + FXF_DBB, fx + FXF_W1F + 768, fx + FXF_B1F + 256, diff_s, blockIdx.x);

    // ---- attention: va -> omega ----
    __syncthreads();
    {
        int l = tid & 31, w = tid >> 5;
        float cwr[32];
#pragma unroll
        for (int i = 0; i < 32; i++)
            cwr[i] = fx[FXF_CW + (l >> 2) * 128 + (l & 3) * 32 + i];
        float* om = (float*)(sm + FS_OM);
        int gb = (l >> 2) * 16;
        for (int it = 0; it < 16; it++) {
            int row = w * 16 + it;
            const uint32_t* vrow = sm + FS_VA + row * 132;
            float acc = 0.f;
#pragma unroll
            for (int t = 0; t < 16; t += 2) {
                uint2 u = *(const uint2*)&vrow[gb + t];
                float2 f0 = upk(u.x), f1 = upk(u.y);
                int i0 = t * 2;
                acc = fmaf(f0.x, cwr[i0], acc);
                acc = fmaf(f0.y, cwr[i0 + 1], acc);
                acc = fmaf(f1.x, cwr[i0 + 2], acc);
                acc = fmaf(f1.y, cwr[i0 + 3], acc);
            }
            float mx = acc;
#pragma unroll
            for (int off = 16; off > 0; off >>= 1)
                mx = fmaxf(mx, __shfl_xor_sync(0xffffffffu, mx, off));
            float e = expf(acc - mx);
            float ss = e;
#pragma unroll
            for (int off = 16; off > 0; off >>= 1)
                ss += __shfl_xor_sync(0xffffffffu, ss, off);
            om[row * 36 + l] = e / ss;
        }
    }
    __syncthreads();

    run_subpass<3, true>(sm, tid, rowBase, 0, BV, fx + FXF_VB, nullptr, nullptr, diff_s, blockIdx.x);
    run_subpass<3, true>(sm, tid, rowBase, 1, BV, fx + FXF_VB, nullptr, nullptr, diff_s, blockIdx.x);
}

// --------------------------- BN2 reductions --------------------------------
__global__ void reduce_part2() {          // grid 64, block 256
    int b = blockIdx.x, tid = threadIdx.x;
    for (int c = tid; c < 512; c += 256) {
        float s = 0.f;
#pragma unroll 8
        for (int i = 0; i < 32; i++)
            s += g_part2[(size_t)(b * 32 + i) * 512 + c];
        g_part2r[b * 512 + c] = s;
    }
}

__global__ void finalize2_kernel(const float* __restrict__ bn_g,
                                 const float* __restrict__ bn_b) {
    int c = threadIdx.x;
    float s = 0.f, sq = 0.f;
    for (int b = 0; b < 64; b++) {
        s  += g_part2r[b * 512 + c];
        sq += g_part2r[b * 512 + 256 + c];
    }
    float mean = s / (float)R_;
    float var = sq / (float)R_ - mean * mean;
    float sc = bn_g[c] * rsqrtf(var + EPSV);
    g_s2[c] = sc;
    g_t2[c] = bn_b[c] - mean * sc;
}

// ------------------------------- launch -------------------------------------
extern "C" void kernel_launch(void* const* d_in, const int* in_sizes, int n_in,
                              void* d_out, int out_size) {
    const float* pts   = (const float*)d_in[0];
    const float* pf    = (const float*)d_in[1];
    const float* nbr   = (const float*)d_in[2];
    const float* nf    = (const float*)d_in[3];
    const float* dm_w1 = (const float*)d_in[4];
    const float* dm_b1 = (const float*)d_in[5];
    const float* dm_w2 = (const float*)d_in[6];
    const float* dm_b2 = (const float*)d_in[7];
    const float* dm_g  = (const float*)d_in[8];
    const float* dm_be = (const float*)d_in[9];
    const float* db_w1 = (const float*)d_in[10];
    const float* db_b1 = (const float*)d_in[11];
    const float* db_w2 = (const float*)d_in[12];
    const float* db_b2 = (const float*)d_in[13];
    const float* db_g  = (const float*)d_in[14];
    const float* db_be = (const float*)d_in[15];
    const float* q_w   = (const float*)d_in[16];
    const float* q_b   = (const float*)d_in[17];
    const float* k_b   = (const float*)d_in[19];
    const float* v_b   = (const float*)d_in[21];
    const float* convw = (const float*)d_in[22];
    const float* bn_g  = (const float*)d_in[23];
    const float* bn_b  = (const float*)d_in[24];
    const float* lin_b = (const float*)d_in[26];
    const float* k_w   = (const float*)d_in[18];
    const float* v_w   = (const float*)d_in[20];
    const float* lin_w = (const float*)d_in[25];
    float* out = (float*)d_out;

    void *p_q, *p_we, *p_bpk;
    cudaGetSymbolAddress(&p_q,   g_q16);
    cudaGetSymbolAddress(&p_we,  g_we16);
    cudaGetSymbolAddress(&p_bpk, g_Bpk);
    const uint32_t* Bpk = (const uint32_t*)p_bpk;

    cudaFuncSetAttribute(gemm_mma<AMODE_DIRECT, true>,
                         cudaFuncAttributeMaxDynamicSharedMemorySize, DYN_SMEM);
    cudaFuncSetAttribute(gemm_mma<AMODE_F16BN, false>,
                         cudaFuncAttributeMaxDynamicSharedMemorySize, DYN_SMEM);
    cudaFuncSetAttribute(fused_kernel,
                         cudaFuncAttributeMaxDynamicSharedMemorySize, FUSED_SMEM);

    prep_weights<<<dim3(8, 2, 6), 256>>>(q_w, k_w, v_w, dm_w2, db_w2, lin_w);
    diffstats_kernel<<<STAT_BLOCKS, 256>>>(pts, nbr);
    fold_kernel<<<1, 256>>>(dm_w1, dm_b1, dm_g, dm_be, db_w1, db_b1, db_g, db_be);

    gemm_mma<AMODE_DIRECT, true><<<dim3(BNp / 128, 2), 256, DYN_SMEM>>>(
        pf, Bpk + 0 * 32768, q_b, p_q);

    fused_kernel<<<NTILES, 256, FUSED_SMEM>>>(nf, pts, nbr,
                                              k_b, dm_b2, db_b2, v_b, convw);

    reduce_part2<<<64, 256>>>();
    finalize2_kernel<<<1, 256>>>(bn_g, bn_b);

    gemm_mma<AMODE_F16BN, false><<<dim3(NTILES, 2), 256, DYN_SMEM>>>(
        p_we, Bpk + 5 * 32768, lin_b, out);
}

// round 8
// speedup vs baseline: 2.4316x; 1.1653x over previous
#include <cuda_runtime.h>
#include <cstdint>

// ---------------------------------------------------------------------------
// GroupVectorAttention — fused produce+attention kernel, 512-thread CTA,
// full-256-col subpasses (k -> qk, dm -> va, db -> va+, softmax, v -> we).
// 16 warps (2x8), one pos-enc A build per matrix, half the barriers of R7.
// ---------------------------------------------------------------------------

#define EPSV 1e-5f

static constexpr int Bb = 4, Nn = 4096, Mm = 16, Cd = 256;
static constexpr int R_ = Bb * Nn * Mm;       // 262144
static constexpr int BNp = Bb * Nn;           // 16384
static constexpr int STAT_BLOCKS = 256;
static constexpr int NTILES = R_ / 128;       // 2048

// ---- gemm_mma (q / final) smem layout (u32 units) ----
static constexpr int SOFF_B  = 4096;
static constexpr int SOFF_FX = 8192;
static constexpr int FX_BIAS = 0, FX_S2 = 1280, FX_T2 = 1536;
static constexpr int DYN_SMEM = (8192 + 2304) * 4;

// ---- fused kernel smem layout (u32 units) ----
static constexpr int FS_ASTG = 0;                 // 2*2048
static constexpr int FS_BSTG = 4096;              // 2*4096
static constexpr int FS_VA   = 12288;             // 128*132
static constexpr int FS_Q    = 29184;             // 1024
static constexpr int FS_OM   = 30208;             // 128*36 fp32
static constexpr int FS_FX   = 34816;             // floats below
static constexpr int FXF_KB = 0, FXF_DMB = 256, FXF_DBB = 512, FXF_VB = 768,
                     FXF_CW = 1024, FXF_W1F = 2048, FXF_B1F = 3584,
                     FXF_DIFF = 4096, FXF_RED = 4608;    // 1024
static constexpr int FUSED_SMEM = (34816 + 5632) * 4;     // 161792 B

// ------------------------- device scratch (static) -------------------------
__device__ float g_part1[STAT_BLOCKS * 12];
__device__ float g_w1f[2][Cd * 3];
__device__ float g_b1f[2][Cd];
__device__ uint32_t g_q16[BNp * 128];
__device__ uint32_t g_we16[(size_t)R_ * 128];
__device__ float g_part2[(size_t)NTILES * 512];
__device__ float g_part2r[64 * 512];
__device__ float g_s2[Cd], g_t2[Cd];
// packed fp16 weight images: [mat(6)][nb(2)][chunk(8)][2048 u32]
__device__ uint32_t g_Bpk[6 * 2 * 8 * 2048];

// ----------------------------- PTX helpers ---------------------------------
__device__ __forceinline__ uint32_t smem_u32(const void* p) {
    uint32_t a;
    asm("{ .reg .u64 t; cvta.to.shared.u64 t, %1; cvt.u32.u64 %0, t; }"
        : "=r"(a) : "l"(p));
    return a;
}
__device__ __forceinline__ void cp16(uint32_t dst, const void* src) {
    asm volatile("cp.async.cg.shared.global [%0], [%1], 16;"
                 :: "r"(dst), "l"(src) : "memory");
}
__device__ __forceinline__ void cp_commit() {
    asm volatile("cp.async.commit_group;" ::: "memory");
}
template <int N>
__device__ __forceinline__ void cp_wait() {
    asm volatile("cp.async.wait_group %0;" :: "n"(N) : "memory");
}
__device__ __forceinline__ void mma_f16(float* c, const uint32_t* a,
                                        uint32_t b0, uint32_t b1) {
    asm volatile("mma.sync.aligned.m16n8k16.row.col.f32.f16.f16.f32 "
                 "{%0,%1,%2,%3}, {%4,%5,%6,%7}, {%8,%9}, {%0,%1,%2,%3};"
                 : "+f"(c[0]), "+f"(c[1]), "+f"(c[2]), "+f"(c[3])
                 : "r"(a[0]), "r"(a[1]), "r"(a[2]), "r"(a[3]),
                   "r"(b0), "r"(b1));
}
__device__ __forceinline__ uint32_t f16pk(float lo, float hi) {
    uint32_t r;
    asm("cvt.rn.f16x2.f32 %0, %1, %2;" : "=r"(r) : "f"(hi), "f"(lo));
    return r;
}
__device__ __forceinline__ float2 upk(uint32_t u) {
    float2 f;
    asm("{ .reg .b16 lo, hi; mov.b32 {lo, hi}, %2; "
        "cvt.f32.f16 %0, lo; cvt.f32.f16 %1, hi; }"
        : "=f"(f.x), "=f"(f.y) : "r"(u));
    return f;
}
__device__ __forceinline__ int pkidx(int n, int p) {
    return n * 16 + 4 * ((p & 3) ^ (n & 3)) + 2 * (p >> 3) + ((p >> 2) & 1);
}

// ------------------------------- K1: stats --------------------------------
__global__ void diffstats_kernel(const float* __restrict__ pts,
                                 const float* __restrict__ nbr) {
    float s[12];
#pragma unroll
    for (int i = 0; i < 12; i++) s[i] = 0.f;
    int tid = threadIdx.x;
    for (int r = blockIdx.x * blockDim.x + tid; r < R_; r += gridDim.x * blockDim.x) {
        int bn = r >> 4;
        float d[3];
#pragma unroll
        for (int j = 0; j < 3; j++) d[j] = pts[bn * 3 + j] - nbr[(size_t)r * 3 + j];
#pragma unroll
        for (int j = 0; j < 3; j++) s[j] += d[j];
#pragma unroll
        for (int j = 0; j < 3; j++)
#pragma unroll
            for (int k = 0; k < 3; k++) s[3 + j * 3 + k] += d[j] * d[k];
    }
    __shared__ float red[256];
    for (int comp = 0; comp < 12; comp++) {
        red[tid] = s[comp];
        __syncthreads();
        for (int off = 128; off > 0; off >>= 1) {
            if (tid < off) red[tid] += red[tid + off];
            __syncthreads();
        }
        if (tid == 0) g_part1[blockIdx.x * 12 + comp] = red[0];
        __syncthreads();
    }
}

// ------------------------------ K2: BN1 fold -------------------------------
__global__ void fold_kernel(const float* __restrict__ dm_w1, const float* __restrict__ dm_b1,
                            const float* __restrict__ dm_g,  const float* __restrict__ dm_be,
                            const float* __restrict__ db_w1, const float* __restrict__ db_b1,
                            const float* __restrict__ db_g,  const float* __restrict__ db_be) {
    __shared__ float st[12];
    __shared__ float mu[3], cov[9];
    int tid = threadIdx.x;
    if (tid < 12) {
        float a = 0.f;
        for (int b = 0; b < STAT_BLOCKS; b++) a += g_part1[b * 12 + tid];
        st[tid] = a / (float)R_;
    }
    __syncthreads();
    if (tid < 3) mu[tid] = st[tid];
    if (tid < 9) {
        int j = tid / 3, k = tid % 3;
        cov[tid] = st[3 + tid] - st[j] * st[k];
    }
    __syncthreads();
    int c = tid;
    for (int which = 0; which < 2; which++) {
        const float* w1 = which ? db_w1 : dm_w1;
        const float* b1 = which ? db_b1 : dm_b1;
        const float* gg = which ? db_g  : dm_g;
        const float* be = which ? db_be : dm_be;
        float w0 = w1[c * 3], w1v = w1[c * 3 + 1], w2v = w1[c * 3 + 2];
        float var = w0 * w0 * cov[0] + w1v * w1v * cov[4] + w2v * w2v * cov[8]
                  + 2.f * (w0 * w1v * cov[1] + w0 * w2v * cov[2] + w1v * w2v * cov[5]);
        float mdot = w0 * mu[0] + w1v * mu[1] + w2v * mu[2];
        float m = mdot + b1[c];
        float s = gg[c] * rsqrtf(var + EPSV);
        g_w1f[which][c * 3]     = w0 * s;
        g_w1f[which][c * 3 + 1] = w1v * s;
        g_w1f[which][c * 3 + 2] = w2v * s;
        g_b1f[which][c] = be[c] + s * (b1[c] - m);
    }
}

// ----------------------- weight prep: fp32 -> packed fp16 -------------------
__global__ void prep_weights(const float* __restrict__ q_w, const float* __restrict__ k_w,
                             const float* __restrict__ v_w, const float* __restrict__ dm_w2,
                             const float* __restrict__ db_w2, const float* __restrict__ lin_w) {
    int c = blockIdx.x, nb = blockIdx.y, mat = blockIdx.z;
    const float* W = mat == 0 ? q_w : mat == 1 ? k_w : mat == 2 ? v_w :
                     mat == 3 ? dm_w2 : mat == 4 ? db_w2 : lin_w;
    uint32_t* dst = g_Bpk + (((size_t)mat * 2 + nb) * 8 + c) * 2048;
    int tid = threadIdx.x;
    int n = tid >> 1, q = tid & 1;
    const float* src = W + (size_t)(nb * 128 + n) * 256 + c * 32 + q * 16;
    float cc[16];
#pragma unroll
    for (int j = 0; j < 16; j += 4) {
        float4 v = *(const float4*)&src[j];
        cc[j] = v.x; cc[j + 1] = v.y; cc[j + 2] = v.z; cc[j + 3] = v.w;
    }
#pragma unroll
    for (int t = 0; t < 4; t++)
#pragma unroll
        for (int u = 0; u < 2; u++) {
            int p = 8 * q + t + 4 * u;
            dst[pkidx(n, p)] = f16pk(cc[2 * t + 8 * u], cc[2 * t + 8 * u + 1]);
        }
}

// ----------------------- standalone GEMM (q + final) ------------------------
enum { AMODE_DIRECT = 0, AMODE_F16BN = 2 };

template <int AMODE>
__device__ __forceinline__ void load_aU(
    int tid, int rowBase, int kb, const void* __restrict__ Ap,
    const float* s2_s, const float* t2_s, uint2 aU[4]) {
#pragma unroll
    for (int i = 0; i < 4; i++) {
        int f = tid + i * 256, row = f >> 3, kq = f & 7;
        if (AMODE == AMODE_DIRECT) {
            const float* A = (const float*)Ap;
            float4 v = *(const float4*)&A[(size_t)(rowBase + row) * 256 + kb + kq * 4];
            aU[i].x = f16pk(v.x, v.y);
            aU[i].y = f16pk(v.z, v.w);
        } else {
            const uint32_t* A16 = (const uint32_t*)Ap;
            uint2 u = *(const uint2*)&A16[(size_t)(rowBase + row) * 128 + (kb >> 1) + kq * 2];
            float2 f0 = upk(u.x), f1 = upk(u.y);
            int k = kb + kq * 4;
            float x0 = fmaxf(fmaf(f0.x, s2_s[k],     t2_s[k]),     0.f);
            float x1 = fmaxf(fmaf(f0.y, s2_s[k + 1], t2_s[k + 1]), 0.f);
            float x2 = fmaxf(fmaf(f1.x, s2_s[k + 2], t2_s[k + 2]), 0.f);
            float x3 = fmaxf(fmaf(f1.y, s2_s[k + 3], t2_s[k + 3]), 0.f);
            aU[i].x = f16pk(x0, x1);
            aU[i].y = f16pk(x2, x3);
        }
    }
}

template <int AMODE, bool OUT16>
__global__ void __launch_bounds__(256, 2)
gemm_mma(const void* __restrict__ A, const uint32_t* __restrict__ Bpk,
         const float* __restrict__ bias, void* __restrict__ OutP) {
    extern __shared__ uint32_t sm[];
    float* fx     = (float*)(sm + SOFF_FX);
    float* bias_s = fx + FX_BIAS;
    float* s2_s   = fx + FX_S2;
    float* t2_s   = fx + FX_T2;

    int tid = threadIdx.x;
    int rowBase = blockIdx.x * 128;

    bias_s[tid] = bias[tid];
    if (AMODE == AMODE_F16BN) {
        s2_s[tid] = g_s2[tid];
        t2_s[tid] = g_t2[tid];
    }
    __syncthreads();

    uint32_t smemB_addr = smem_u32(sm + SOFF_B);
    const uint32_t* BpkNb = Bpk + (size_t)blockIdx.y * 16384;

    auto cp_b = [&](int stage, int c) {
        const uint32_t* src = BpkNb + c * 2048;
        uint32_t dstb = smemB_addr + (uint32_t)stage * 8192u;
#pragma unroll
        for (int i = 0; i < 2; i++) {
            int e = tid + i * 256;
            cp16(dstb + (uint32_t)e * 16u, src + e * 4);
        }
        cp_commit();
    };
    auto sts_a = [&](int stage, const uint2* aU) {
        uint32_t* dst = sm + stage * 2048;
#pragma unroll
        for (int i = 0; i < 4; i++) {
            int f = tid + i * 256, row = f >> 3, kq = f & 7;
            dst[pkidx(row, 2 * kq)]     = aU[i].x;
            dst[pkidx(row, 2 * kq + 1)] = aU[i].y;
        }
    };

    cp_b(0, 0);
    cp_b(1, 1);
    uint2 aU[4];
    load_aU<AMODE>(tid, rowBase, 0, A, s2_s, t2_s, aU);
    sts_a(0, aU);
    cp_wait<0>();
    __syncthreads();

    int lane = tid & 31, w = tid >> 5;
    int wm = w & 1, wn = w >> 1;
    int la3 = lane & 3, lg = lane >> 2;
    int axor = 4 * (la3 ^ (lg & 3));

    float acc[4][4][4];
#pragma unroll
    for (int mt = 0; mt < 4; mt++)
#pragma unroll
        for (int nt = 0; nt < 4; nt++)
#pragma unroll
            for (int r = 0; r < 4; r++) acc[mt][nt][r] = 0.f;

    const int aBase = (wm * 64 + lg) * 16 + axor;
    const int bBase = (wn * 32 + lg) * 16 + axor;

    for (int c = 0; c < 8; c++) {
        int st = c & 1;
        if (c < 7)
            load_aU<AMODE>(tid, rowBase, (c + 1) * 32, A, s2_s, t2_s, aU);
        const uint32_t* As = sm + st * 2048;
        const uint32_t* Bs = sm + SOFF_B + st * 2048;

        uint4 Vb[4];
#pragma unroll
        for (int nt = 0; nt < 4; nt++)
            Vb[nt] = *(const uint4*)&Bs[bBase + nt * 128];
#pragma unroll
        for (int mt = 0; mt < 4; mt++) {
            uint4 U0 = *(const uint4*)&As[aBase + mt * 256];
            uint4 U1 = *(const uint4*)&As[aBase + mt * 256 + 128];
            uint32_t a0[4] = {U0.x, U1.x, U0.y, U1.y};
            uint32_t a1[4] = {U0.z, U1.z, U0.w, U1.w};
#pragma unroll
            for (int nt = 0; nt < 4; nt++)
                mma_f16(acc[mt][nt], a0, Vb[nt].x, Vb[nt].y);
#pragma unroll
            for (int nt = 0; nt < 4; nt++)
                mma_f16(acc[mt][nt], a1, Vb[nt].z, Vb[nt].w);
        }
        if (c < 7) sts_a(st ^ 1, aU);
        cp_wait<0>();
        __syncthreads();
        if (c + 2 < 8) cp_b(st, c + 2);
    }

    int nOff = blockIdx.y * 128;
#pragma unroll
    for (int mt = 0; mt < 4; mt++) {
        int row0 = rowBase + wm * 64 + mt * 16 + lg;
#pragma unroll
        for (int nt = 0; nt < 4; nt++) {
            int col = nOff + wn * 32 + nt * 8 + 2 * la3;
            float b0 = bias_s[col];
            float b1 = bias_s[col + 1];
            float v00 = acc[mt][nt][0] + b0, v01 = acc[mt][nt][1] + b1;
            float v10 = acc[mt][nt][2] + b0, v11 = acc[mt][nt][3] + b1;
            if (OUT16) {
                uint32_t* O16 = (uint32_t*)OutP;
                O16[(size_t)row0 * 128 + (col >> 1)]       = f16pk(v00, v01);
                O16[(size_t)(row0 + 8) * 128 + (col >> 1)] = f16pk(v10, v11);
            } else {
                float* Out = (float*)OutP;
                *(float2*)&Out[(size_t)row0 * 256 + col]       = make_float2(v00, v01);
                *(float2*)&Out[(size_t)(row0 + 8) * 256 + col] = make_float2(v10, v11);
            }
        }
    }
}

// ----------------------- fused produce+attention kernel ---------------------
// 512 threads, 16 warps (2 row x 8 col). Full 256 cols per subpass.
// EPI: 0 = qk = q - k ; 1 = va = dm*qk ; 2 = va += db ; 3 = we = omega*v
template <int EPI, bool POS>
__device__ __noinline__ void run_subpass(
    uint32_t* sm, int tid, int rowBase,
    const float* __restrict__ nf,
    const uint32_t* __restrict__ Bmat,
    const float* bias_s, const float* w1f_s, const float* b1f_s,
    const float* diff_s, int blockId) {

    uint32_t smemB_addr = smem_u32(sm + FS_BSTG);
    auto cp_b = [&](int stage, int c) {
        const uint32_t* src0 = Bmat + (size_t)c * 2048;           // nb=0
        const uint32_t* src1 = Bmat + (size_t)(8 + c) * 2048;     // nb=1
        uint32_t dstb = smemB_addr + (uint32_t)stage * 16384u;
        {
            int e = tid;                 // 0..511 -> nb0 rows
            cp16(dstb + (uint32_t)e * 16u, src0 + e * 4);
            cp16(dstb + 8192u + (uint32_t)e * 16u, src1 + e * 4);
        }
        cp_commit();
    };

    uint2 aU[2];
    auto load_a = [&](int kb) {
#pragma unroll
        for (int i = 0; i < 2; i++) {
            int f = tid + i * 512, row = f >> 3, kq = f & 7;
            if (POS) {
                float d0 = diff_s[row * 4], d1 = diff_s[row * 4 + 1], d2 = diff_s[row * 4 + 2];
                float t[4];
#pragma unroll
                for (int j = 0; j < 4; j++) {
                    int k = kb + kq * 4 + j;
                    float h = fmaf(d0, w1f_s[k * 3],
                              fmaf(d1, w1f_s[k * 3 + 1],
                              fmaf(d2, w1f_s[k * 3 + 2], b1f_s[k])));
                    t[j] = fmaxf(h, 0.f);
                }
                aU[i].x = f16pk(t[0], t[1]);
                aU[i].y = f16pk(t[2], t[3]);
            } else {
                float4 v = *(const float4*)&nf[(size_t)(rowBase + row) * 256 + kb + kq * 4];
                aU[i].x = f16pk(v.x, v.y);
                aU[i].y = f16pk(v.z, v.w);
            }
        }
    };
    auto sts_a = [&](int stage) {
        uint32_t* dst = sm + FS_ASTG + stage * 2048;
#pragma unroll
        for (int i = 0; i < 2; i++) {
            int f = tid + i * 512, row = f >> 3, kq = f & 7;
            dst[pkidx(row, 2 * kq)]     = aU[i].x;
            dst[pkidx(row, 2 * kq + 1)] = aU[i].y;
        }
    };

    cp_b(0, 0);
    cp_b(1, 1);
    load_a(0);
    sts_a(0);
    cp_wait<0>();
    __syncthreads();

    int lane = tid & 31, w = tid >> 5;
    int wm = w & 1, wn = w >> 1;        // wn 0..7
    int la3 = lane & 3, lg = lane >> 2;
    int axor = 4 * (la3 ^ (lg & 3));
    const int aOff = (wm * 64 + lg) * 16 + axor;
    const int bOff = (wn * 32 + lg) * 16 + axor;

    float acc[4][4][4];
#pragma unroll
    for (int mt = 0; mt < 4; mt++)
#pragma unroll
        for (int nt = 0; nt < 4; nt++)
#pragma unroll
            for (int r = 0; r < 4; r++) acc[mt][nt][r] = 0.f;

    for (int c = 0; c < 8; c++) {
        int st = c & 1;
        if (c < 7) load_a((c + 1) * 32);
        const uint32_t* As = sm + FS_ASTG + st * 2048;
        const uint32_t* Bs = sm + FS_BSTG + st * 4096;

        uint4 Vb[4];
#pragma unroll
        for (int nt = 0; nt < 4; nt++)
            Vb[nt] = *(const uint4*)&Bs[bOff + nt * 128];
#pragma unroll
        for (int mt = 0; mt < 4; mt++) {
            uint4 U0 = *(const uint4*)&As[aOff + mt * 256];
            uint4 U1 = *(const uint4*)&As[aOff + mt * 256 + 128];
            uint32_t a0[4] = {U0.x, U1.x, U0.y, U1.y};
            uint32_t a1[4] = {U0.z, U1.z, U0.w, U1.w};
#pragma unroll
            for (int nt = 0; nt < 4; nt++)
                mma_f16(acc[mt][nt], a0, Vb[nt].x, Vb[nt].y);
#pragma unroll
            for (int nt = 0; nt < 4; nt++)
                mma_f16(acc[mt][nt], a1, Vb[nt].z, Vb[nt].w);
        }
        if (c < 7) sts_a(st ^ 1);
        cp_wait<0>();
        __syncthreads();
        if (c + 2 < 8) cp_b(st, c + 2);
    }

    // ---- epilogue ----
    float csum[8], csq[8];
#pragma unroll
    for (int j = 0; j < 8; j++) { csum[j] = 0.f; csq[j] = 0.f; }

#pragma unroll
    for (int mt = 0; mt < 4; mt++) {
        int row0 = wm * 64 + mt * 16 + lg;
#pragma unroll
        for (int nt = 0; nt < 4; nt++) {
            int col = wn * 32 + nt * 8 + 2 * la3;
            float b0 = bias_s[col], b1 = bias_s[col + 1];
            int vi0 = row0 * 132 + (col >> 1);
            int vi1 = (row0 + 8) * 132 + (col >> 1);
            float a0 = acc[mt][nt][0] + b0, a1 = acc[mt][nt][1] + b1;
            float a2 = acc[mt][nt][2] + b0, a3 = acc[mt][nt][3] + b1;
            if (EPI == 0) {
                float2 qv = upk(sm[FS_Q + (wm * 4 + mt) * 128 + (col >> 1)]);
                sm[FS_VA + vi0] = f16pk(qv.x - a0, qv.y - a1);
                sm[FS_VA + vi1] = f16pk(qv.x - a2, qv.y - a3);
            } else if (EPI == 1) {
                float2 u0 = upk(sm[FS_VA + vi0]), u1 = upk(sm[FS_VA + vi1]);
                sm[FS_VA + vi0] = f16pk(a0 * u0.x, a1 * u0.y);
                sm[FS_VA + vi1] = f16pk(a2 * u1.x, a3 * u1.y);
            } else if (EPI == 2) {
                float2 u0 = upk(sm[FS_VA + vi0]), u1 = upk(sm[FS_VA + vi1]);
                sm[FS_VA + vi0] = f16pk(u0.x + a0, u0.y + a1);
                sm[FS_VA + vi1] = f16pk(u1.x + a2, u1.y + a3);
            } else {
                const float* om = (const float*)(sm + FS_OM);
                float o0 = om[row0 * 36 + (col >> 3)];
                float o1 = om[(row0 + 8) * 36 + (col >> 3)];
                float w00 = o0 * a0, w01 = o0 * a1;
                float w10 = o1 * a2, w11 = o1 * a3;
                g_we16[(size_t)(rowBase + row0) * 128 + (col >> 1)]     = f16pk(w00, w01);
                g_we16[(size_t)(rowBase + row0 + 8) * 128 + (col >> 1)] = f16pk(w10, w11);
                csum[nt * 2]     += w00 + w10;
                csum[nt * 2 + 1] += w01 + w11;
                csq[nt * 2]      += w00 * w00 + w10 * w10;
                csq[nt * 2 + 1]  += w01 * w01 + w11 * w11;
            }
        }
    }
    if (EPI == 3) {
#pragma unroll
        for (int j = 0; j < 8; j++) {
#pragma unroll
            for (int off = 4; off < 32; off <<= 1) {
                csum[j] += __shfl_xor_sync(0xffffffffu, csum[j], off);
                csq[j]  += __shfl_xor_sync(0xffffffffu, csq[j],  off);
            }
        }
        float* red = (float*)(sm + FS_FX) + FXF_RED;
        if (lg == 0) {
#pragma unroll
            for (int u = 0; u < 8; u++) {
                int nt = u >> 1, uu = u & 1;
                int lc = nt * 8 + 2 * la3 + uu;           // 0..31 in warp col group
                red[w * 32 + lc]       = csum[u];
                red[512 + w * 32 + lc] = csq[u];
            }
        }
        __syncthreads();
        if (tid < 256) {
            int c2 = tid, wg = c2 >> 5, idx = c2 & 31;
            float s  = red[(2 * wg) * 32 + idx]       + red[(2 * wg + 1) * 32 + idx];
            float sq = red[512 + (2 * wg) * 32 + idx] + red[512 + (2 * wg + 1) * 32 + idx];
            g_part2[(size_t)blockId * 512 + c2]       = s;
            g_part2[(size_t)blockId * 512 + 256 + c2] = sq;
        }
        __syncthreads();
    } else {
        __syncthreads();
    }
}

__global__ void __launch_bounds__(512, 1)
fused_kernel(const float* __restrict__ nf, const float* __restrict__ pts,
             const float* __restrict__ nbr,
             const float* __restrict__ k_b, const float* __restrict__ dm_b2,
             const float* __restrict__ db_b2, const float* __restrict__ v_b,
             const float* __restrict__ convw) {
    extern __shared__ uint32_t sm[];
    float* fx = (float*)(sm + FS_FX);
    int tid = threadIdx.x;
    int rowBase = blockIdx.x * 128;

    if (tid < 256) {
        fx[FXF_KB + tid]  = k_b[tid];
        fx[FXF_DMB + tid] = dm_b2[tid];
        fx[FXF_DBB + tid] = db_b2[tid];
        fx[FXF_VB + tid]  = v_b[tid];
        fx[FXF_B1F + tid]       = g_b1f[0][tid];
        fx[FXF_B1F + 256 + tid] = g_b1f[1][tid];
    }
    for (int i = tid; i < 1024; i += 512) fx[FXF_CW + i] = convw[i];
    for (int i = tid; i < 768; i += 512) {
        fx[FXF_W1F + i]       = g_w1f[0][i];
        fx[FXF_W1F + 768 + i] = g_w1f[1][i];
    }
    if (tid < 128) {
        int r = rowBase + tid, bn = r >> 4;
        fx[FXF_DIFF + tid * 4 + 0] = pts[bn * 3 + 0] - nbr[(size_t)r * 3 + 0];
        fx[FXF_DIFF + tid * 4 + 1] = pts[bn * 3 + 1] - nbr[(size_t)r * 3 + 1];
        fx[FXF_DIFF + tid * 4 + 2] = pts[bn * 3 + 2] - nbr[(size_t)r * 3 + 2];
    }
    {
        int bnb = rowBase >> 4;
        for (int i = tid; i < 1024; i += 512) sm[FS_Q + i] = g_q16[bnb * 128 + i];
    }
    __syncthreads();

    const uint32_t* BK  = g_Bpk + 1 * 32768;
    const uint32_t* BV  = g_Bpk + 2 * 32768;
    const uint32_t* BDM = g_Bpk + 3 * 32768;
    const uint32_t* BDB = g_Bpk + 4 * 32768;
    const float* diff_s = fx + FXF_DIFF;

    run_subpass<0, false>(sm, tid, rowBase, nf, BK,  fx + FXF_KB,  nullptr, nullptr, diff_s, blockIdx.x);
    run_subpass<1, true >(sm, tid, rowBase, nf, BDM, fx + FXF_DMB, fx + FXF_W1F,       fx + FXF_B1F,       diff_s, blockIdx.x);
    run_subpass<2, true >(sm, tid, rowBase, nf, BDB, fx + FXF_DBB, fx + FXF_W1F + 768, fx + FXF_B1F + 256, diff_s, blockIdx.x);

    // ---- attention: va -> omega ----
    __syncthreads();
    {
        int l = tid & 31, w = tid >> 5;
        float cwr[32];
#pragma unroll
        for (int i = 0; i < 32; i++)
            cwr[i] = fx[FXF_CW + (l >> 2) * 128 + (l & 3) * 32 + i];
        float* om = (float*)(sm + FS_OM);
        int gb = (l >> 2) * 16;
        for (int it = 0; it < 8; it++) {
            int row = w * 8 + it;
            const uint32_t* vrow = sm + FS_VA + row * 132;
            float acc = 0.f;
#pragma unroll
            for (int t = 0; t < 16; t += 2) {
                uint2 u = *(const uint2*)&vrow[gb + t];
                float2 f0 = upk(u.x), f1 = upk(u.y);
                int i0 = t * 2;
                acc = fmaf(f0.x, cwr[i0], acc);
                acc = fmaf(f0.y, cwr[i0 + 1], acc);
                acc = fmaf(f1.x, cwr[i0 + 2], acc);
                acc = fmaf(f1.y, cwr[i0 + 3], acc);
            }
            float mx = acc;
#pragma unroll
            for (int off = 16; off > 0; off >>= 1)
                mx = fmaxf(mx, __shfl_xor_sync(0xffffffffu, mx, off));
            float e = expf(acc - mx);
            float ss = e;
#pragma unroll
            for (int off = 16; off > 0; off >>= 1)
                ss += __shfl_xor_sync(0xffffffffu, ss, off);
            om[row * 36 + l] = e / ss;
        }
    }
    __syncthreads();

    run_subpass<3, false>(sm, tid, rowBase, nf, BV, fx + FXF_VB, nullptr, nullptr, diff_s, blockIdx.x);
}

// --------------------------- BN2 reductions --------------------------------
__global__ void reduce_part2() {          // grid 64, block 256
    int b = blockIdx.x, tid = threadIdx.x;
    for (int c = tid; c < 512; c += 256) {
        float s = 0.f;
#pragma unroll 8
        for (int i = 0; i < 32; i++)
            s += g_part2[(size_t)(b * 32 + i) * 512 + c];
        g_part2r[b * 512 + c] = s;
    }
}

__global__ void finalize2_kernel(const float* __restrict__ bn_g,
                                 const float* __restrict__ bn_b) {
    int c = threadIdx.x;
    float s = 0.f, sq = 0.f;
    for (int b = 0; b < 64; b++) {
        s  += g_part2r[b * 512 + c];
        sq += g_part2r[b * 512 + 256 + c];
    }
    float mean = s / (float)R_;
    float var = sq / (float)R_ - mean * mean;
    float sc = bn_g[c] * rsqrtf(var + EPSV);
    g_s2[c] = sc;
    g_t2[c] = bn_b[c] - mean * sc;
}

// ------------------------------- launch -------------------------------------
extern "C" void kernel_launch(void* const* d_in, const int* in_sizes, int n_in,
                              void* d_out, int out_size) {
    const float* pts   = (const float*)d_in[0];
    const float* pf    = (const float*)d_in[1];
    const float* nbr   = (const float*)d_in[2];
    const float* nf    = (const float*)d_in[3];
    const float* dm_w1 = (const float*)d_in[4];
    const float* dm_b1 = (const float*)d_in[5];
    const float* dm_w2 = (const float*)d_in[6];
    const float* dm_b2 = (const float*)d_in[7];
    const float* dm_g  = (const float*)d_in[8];
    const float* dm_be = (const float*)d_in[9];
    const float* db_w1 = (const float*)d_in[10];
    const float* db_b1 = (const float*)d_in[11];
    const float* db_w2 = (const float*)d_in[12];
    const float* db_b2 = (const float*)d_in[13];
    const float* db_g  = (const float*)d_in[14];
    const float* db_be = (const float*)d_in[15];
    const float* q_w   = (const float*)d_in[16];
    const float* q_b   = (const float*)d_in[17];
    const float* k_w   = (const float*)d_in[18];
    const float* k_b   = (const float*)d_in[19];
    const float* v_w   = (const float*)d_in[20];
    const float* v_b   = (const float*)d_in[21];
    const float* convw = (const float*)d_in[22];
    const float* bn_g  = (const float*)d_in[23];
    const float* bn_b  = (const float*)d_in[24];
    const float* lin_w = (const float*)d_in[25];
    const float* lin_b = (const float*)d_in[26];
    float* out = (float*)d_out;

    void *p_q, *p_we, *p_bpk;
    cudaGetSymbolAddress(&p_q,   g_q16);
    cudaGetSymbolAddress(&p_we,  g_we16);
    cudaGetSymbolAddress(&p_bpk, g_Bpk);
    const uint32_t* Bpk = (const uint32_t*)p_bpk;

    cudaFuncSetAttribute(gemm_mma<AMODE_DIRECT, true>,
                         cudaFuncAttributeMaxDynamicSharedMemorySize, DYN_SMEM);
    cudaFuncSetAttribute(gemm_mma<AMODE_F16BN, false>,
                         cudaFuncAttributeMaxDynamicSharedMemorySize, DYN_SMEM);
    cudaFuncSetAttribute(fused_kernel,
                         cudaFuncAttributeMaxDynamicSharedMemorySize, FUSED_SMEM);

    prep_weights<<<dim3(8, 2, 6), 256>>>(q_w, k_w, v_w, dm_w2, db_w2, lin_w);
    diffstats_kernel<<<STAT_BLOCKS, 256>>>(pts, nbr);
    fold_kernel<<<1, 256>>>(dm_w1, dm_b1, dm_g, dm_be, db_w1, db_b1, db_g, db_be);

    gemm_mma<AMODE_DIRECT, true><<<dim3(BNp / 128, 2), 256, DYN_SMEM>>>(
        pf, Bpk + 0 * 32768, q_b, p_q);

    fused_kernel<<<NTILES, 512, FUSED_SMEM>>>(nf, pts, nbr,
                                              k_b, dm_b2, db_b2, v_b, convw);

    reduce_part2<<<64, 256>>>();
    finalize2_kernel<<<1, 256>>>(bn_g, bn_b);

    gemm_mma<AMODE_F16BN, false><<<dim3(NTILES, 2), 256, DYN_SMEM>>>(
        p_we, Bpk + 5 * 32768, lin_b, out);
}

// round 9
// speedup vs baseline: 2.5127x; 1.0334x over previous
#include <cuda_runtime.h>
#include <cstdint>

// ---------------------------------------------------------------------------
// GroupVectorAttention — fused produce+attention (512 thr, ANF smem cache for
// the v-pass) + 64-row full-N GEMMs (A read/converted once per row, occ 2).
// ---------------------------------------------------------------------------

#define EPSV 1e-5f

static constexpr int Bb = 4, Nn = 4096, Mm = 16, Cd = 256;
static constexpr int R_ = Bb * Nn * Mm;       // 262144
static constexpr int BNp = Bb * Nn;           // 16384
static constexpr int STAT_BLOCKS = 256;
static constexpr int NTILES = R_ / 128;       // 2048

// ---- standalone GEMM smem layout (u32 units): A 2x1024 | B 2x4096 | fx ----
static constexpr int G_SOFF_B  = 2048;
static constexpr int G_SOFF_FX = 10240;
static constexpr int G_FX_BIAS = 0, G_FX_S2 = 256, G_FX_T2 = 512;
static constexpr int G_DYN_SMEM = (10240 + 768) * 4;     // 44032 B

// ---- fused kernel smem layout (u32 units) ----
static constexpr int FS_ASTG = 0;                 // 2*2048
static constexpr int FS_BSTG = 4096;              // 2*4096
static constexpr int FS_ANF  = 12288;             // 8*2048 (nf fp16 cache)
static constexpr int FS_VA   = 28672;             // 128*132
static constexpr int FS_Q    = 45568;             // 1024
static constexpr int FS_OM   = 46592;             // 128*36 fp32
static constexpr int FS_FX   = 51200;             // floats below (5632)
static constexpr int FXF_KB = 0, FXF_DMB = 256, FXF_DBB = 512, FXF_VB = 768,
                     FXF_CW = 1024, FXF_W1F = 2048, FXF_B1F = 3584,
                     FXF_DIFF = 4096, FXF_RED = 4608;     // 1024
static constexpr int FUSED_SMEM = (51200 + 5632) * 4;     // 227328 B

// ------------------------- device scratch (static) -------------------------
__device__ float g_part1[STAT_BLOCKS * 12];
__device__ float g_w1f[2][Cd * 3];
__device__ float g_b1f[2][Cd];
__device__ uint32_t g_q16[BNp * 128];
__device__ uint32_t g_we16[(size_t)R_ * 128];
__device__ float g_part2[(size_t)NTILES * 512];
__device__ float g_part2r[64 * 512];
__device__ float g_s2[Cd], g_t2[Cd];
// packed fp16 weight images: [mat(6)][nb(2)][chunk(8)][2048 u32]
__device__ uint32_t g_Bpk[6 * 2 * 8 * 2048];

// ----------------------------- PTX helpers ---------------------------------
__device__ __forceinline__ uint32_t smem_u32(const void* p) {
    uint32_t a;
    asm("{ .reg .u64 t; cvta.to.shared.u64 t, %1; cvt.u32.u64 %0, t; }"
        : "=r"(a) : "l"(p));
    return a;
}
__device__ __forceinline__ void cp16(uint32_t dst, const void* src) {
    asm volatile("cp.async.cg.shared.global [%0], [%1], 16;"
                 :: "r"(dst), "l"(src) : "memory");
}
__device__ __forceinline__ void cp_commit() {
    asm volatile("cp.async.commit_group;" ::: "memory");
}
template <int N>
__device__ __forceinline__ void cp_wait() {
    asm volatile("cp.async.wait_group %0;" :: "n"(N) : "memory");
}
__device__ __forceinline__ void mma_f16(float* c, const uint32_t* a,
                                        uint32_t b0, uint32_t b1) {
    asm volatile("mma.sync.aligned.m16n8k16.row.col.f32.f16.f16.f32 "
                 "{%0,%1,%2,%3}, {%4,%5,%6,%7}, {%8,%9}, {%0,%1,%2,%3};"
                 : "+f"(c[0]), "+f"(c[1]), "+f"(c[2]), "+f"(c[3])
                 : "r"(a[0]), "r"(a[1]), "r"(a[2]), "r"(a[3]),
                   "r"(b0), "r"(b1));
}
__device__ __forceinline__ uint32_t f16pk(float lo, float hi) {
    uint32_t r;
    asm("cvt.rn.f16x2.f32 %0, %1, %2;" : "=r"(r) : "f"(hi), "f"(lo));
    return r;
}
__device__ __forceinline__ float2 upk(uint32_t u) {
    float2 f;
    asm("{ .reg .b16 lo, hi; mov.b32 {lo, hi}, %2; "
        "cvt.f32.f16 %0, lo; cvt.f32.f16 %1, hi; }"
        : "=f"(f.x), "=f"(f.y) : "r"(u));
    return f;
}
__device__ __forceinline__ int pkidx(int n, int p) {
    return n * 16 + 4 * ((p & 3) ^ (n & 3)) + 2 * (p >> 3) + ((p >> 2) & 1);
}

// ------------------------------- K1: stats --------------------------------
__global__ void diffstats_kernel(const float* __restrict__ pts,
                                 const float* __restrict__ nbr) {
    float s[12];
#pragma unroll
    for (int i = 0; i < 12; i++) s[i] = 0.f;
    int tid = threadIdx.x;
    for (int r = blockIdx.x * blockDim.x + tid; r < R_; r += gridDim.x * blockDim.x) {
        int bn = r >> 4;
        float d[3];
#pragma unroll
        for (int j = 0; j < 3; j++) d[j] = pts[bn * 3 + j] - nbr[(size_t)r * 3 + j];
#pragma unroll
        for (int j = 0; j < 3; j++) s[j] += d[j];
#pragma unroll
        for (int j = 0; j < 3; j++)
#pragma unroll
            for (int k = 0; k < 3; k++) s[3 + j * 3 + k] += d[j] * d[k];
    }
    __shared__ float red[256];
    for (int comp = 0; comp < 12; comp++) {
        red[tid] = s[comp];
        __syncthreads();
        for (int off = 128; off > 0; off >>= 1) {
            if (tid < off) red[tid] += red[tid + off];
            __syncthreads();
        }
        if (tid == 0) g_part1[blockIdx.x * 12 + comp] = red[0];
        __syncthreads();
    }
}

// ------------------------------ K2: BN1 fold -------------------------------
__global__ void fold_kernel(const float* __restrict__ dm_w1, const float* __restrict__ dm_b1,
                            const float* __restrict__ dm_g,  const float* __restrict__ dm_be,
                            const float* __restrict__ db_w1, const float* __restrict__ db_b1,
                            const float* __restrict__ db_g,  const float* __restrict__ db_be) {
    __shared__ float st[12];
    __shared__ float mu[3], cov[9];
    int tid = threadIdx.x;
    if (tid < 12) {
        float a = 0.f;
        for (int b = 0; b < STAT_BLOCKS; b++) a += g_part1[b * 12 + tid];
        st[tid] = a / (float)R_;
    }
    __syncthreads();
    if (tid < 3) mu[tid] = st[tid];
    if (tid < 9) {
        int j = tid / 3, k = tid % 3;
        cov[tid] = st[3 + tid] - st[j] * st[k];
    }
    __syncthreads();
    int c = tid;
    for (int which = 0; which < 2; which++) {
        const float* w1 = which ? db_w1 : dm_w1;
        const float* b1 = which ? db_b1 : dm_b1;
        const float* gg = which ? db_g  : dm_g;
        const float* be = which ? db_be : dm_be;
        float w0 = w1[c * 3], w1v = w1[c * 3 + 1], w2v = w1[c * 3 + 2];
        float var = w0 * w0 * cov[0] + w1v * w1v * cov[4] + w2v * w2v * cov[8]
                  + 2.f * (w0 * w1v * cov[1] + w0 * w2v * cov[2] + w1v * w2v * cov[5]);
        float mdot = w0 * mu[0] + w1v * mu[1] + w2v * mu[2];
        float m = mdot + b1[c];
        float s = gg[c] * rsqrtf(var + EPSV);
        g_w1f[which][c * 3]     = w0 * s;
        g_w1f[which][c * 3 + 1] = w1v * s;
        g_w1f[which][c * 3 + 2] = w2v * s;
        g_b1f[which][c] = be[c] + s * (b1[c] - m);
    }
}

// ----------------------- weight prep: fp32 -> packed fp16 -------------------
__global__ void prep_weights(const float* __restrict__ q_w, const float* __restrict__ k_w,
                             const float* __restrict__ v_w, const float* __restrict__ dm_w2,
                             const float* __restrict__ db_w2, const float* __restrict__ lin_w) {
    int c = blockIdx.x, nb = blockIdx.y, mat = blockIdx.z;
    const float* W = mat == 0 ? q_w : mat == 1 ? k_w : mat == 2 ? v_w :
                     mat == 3 ? dm_w2 : mat == 4 ? db_w2 : lin_w;
    uint32_t* dst = g_Bpk + (((size_t)mat * 2 + nb) * 8 + c) * 2048;
    int tid = threadIdx.x;
    int n = tid >> 1, q = tid & 1;
    const float* src = W + (size_t)(nb * 128 + n) * 256 + c * 32 + q * 16;
    float cc[16];
#pragma unroll
    for (int j = 0; j < 16; j += 4) {
        float4 v = *(const float4*)&src[j];
        cc[j] = v.x; cc[j + 1] = v.y; cc[j + 2] = v.z; cc[j + 3] = v.w;
    }
#pragma unroll
    for (int t = 0; t < 4; t++)
#pragma unroll
        for (int u = 0; u < 2; u++) {
            int p = 8 * q + t + 4 * u;
            dst[pkidx(n, p)] = f16pk(cc[2 * t + 8 * u], cc[2 * t + 8 * u + 1]);
        }
}

// ----------------- standalone GEMM: 64-row tiles, full N=256 ----------------
enum { AMODE_DIRECT = 0, AMODE_F16BN = 2 };

template <int AMODE>
__device__ __forceinline__ void load_aU(
    int tid, int rowBase, int kb, const void* __restrict__ Ap,
    const float* s2_s, const float* t2_s, uint2 aU[2]) {
#pragma unroll
    for (int i = 0; i < 2; i++) {
        int f = tid + i * 256, row = f >> 3, kq = f & 7;
        if (AMODE == AMODE_DIRECT) {
            const float* A = (const float*)Ap;
            float4 v = *(const float4*)&A[(size_t)(rowBase + row) * 256 + kb + kq * 4];
            aU[i].x = f16pk(v.x, v.y);
            aU[i].y = f16pk(v.z, v.w);
        } else {
            const uint32_t* A16 = (const uint32_t*)Ap;
            uint2 u = *(const uint2*)&A16[(size_t)(rowBase + row) * 128 + (kb >> 1) + kq * 2];
            float2 f0 = upk(u.x), f1 = upk(u.y);
            int k = kb + kq * 4;
            float x0 = fmaxf(fmaf(f0.x, s2_s[k],     t2_s[k]),     0.f);
            float x1 = fmaxf(fmaf(f0.y, s2_s[k + 1], t2_s[k + 1]), 0.f);
            float x2 = fmaxf(fmaf(f1.x, s2_s[k + 2], t2_s[k + 2]), 0.f);
            float x3 = fmaxf(fmaf(f1.y, s2_s[k + 3], t2_s[k + 3]), 0.f);
            aU[i].x = f16pk(x0, x1);
            aU[i].y = f16pk(x2, x3);
        }
    }
}

template <int AMODE, bool OUT16>
__global__ void __launch_bounds__(256, 2)
gemm_mma(const void* __restrict__ A, const uint32_t* __restrict__ Bpk,
         const float* __restrict__ bias, void* __restrict__ OutP) {
    extern __shared__ uint32_t sm[];
    float* fx     = (float*)(sm + G_SOFF_FX);
    float* bias_s = fx + G_FX_BIAS;
    float* s2_s   = fx + G_FX_S2;
    float* t2_s   = fx + G_FX_T2;

    int tid = threadIdx.x;
    int rowBase = blockIdx.x * 64;

    bias_s[tid] = bias[tid];
    if (AMODE == AMODE_F16BN) {
        s2_s[tid] = g_s2[tid];
        t2_s[tid] = g_t2[tid];
    }
    __syncthreads();

    uint32_t smemB_addr = smem_u32(sm + G_SOFF_B);

    auto cp_b = [&](int stage, int c) {
        uint32_t dstb = smemB_addr + (uint32_t)stage * 16384u;
#pragma unroll
        for (int i = 0; i < 4; i++) {
            int off = (tid + i * 256) * 4;      // u32 offset 0..4095
            const uint32_t* src = (off < 2048)
                ? Bpk + (size_t)c * 2048 + off
                : Bpk + (size_t)(8 + c) * 2048 + (off - 2048);
            cp16(dstb + (uint32_t)off * 4u, src);
        }
        cp_commit();
    };
    auto sts_a = [&](int stage, const uint2* aU) {
        uint32_t* dst = sm + stage * 1024;
#pragma unroll
        for (int i = 0; i < 2; i++) {
            int f = tid + i * 256, row = f >> 3, kq = f & 7;
            dst[pkidx(row, 2 * kq)]     = aU[i].x;
            dst[pkidx(row, 2 * kq + 1)] = aU[i].y;
        }
    };

    cp_b(0, 0);
    cp_b(1, 1);
    uint2 aU[2];
    load_aU<AMODE>(tid, rowBase, 0, A, s2_s, t2_s, aU);
    sts_a(0, aU);
    cp_wait<0>();
    __syncthreads();

    int lane = tid & 31, w = tid >> 5;     // w = column group 0..7
    int la3 = lane & 3, lg = lane >> 2;
    int axor = 4 * (la3 ^ (lg & 3));
    const int aOff = lg * 16 + axor;
    const int bOff = (w * 32 + lg) * 16 + axor;

    float acc[4][4][4];
#pragma unroll
    for (int mt = 0; mt < 4; mt++)
#pragma unroll
        for (int nt = 0; nt < 4; nt++)
#pragma unroll
            for (int r = 0; r < 4; r++) acc[mt][nt][r] = 0.f;

    for (int c = 0; c < 8; c++) {
        int st = c & 1;
        const uint32_t* As = sm + st * 1024;
        const uint32_t* Bs = sm + G_SOFF_B + st * 4096;

        uint4 Vb[4];
#pragma unroll
        for (int nt = 0; nt < 4; nt++)
            Vb[nt] = *(const uint4*)&Bs[bOff + nt * 128];
#pragma unroll
        for (int mt = 0; mt < 2; mt++) {
            uint4 U0 = *(const uint4*)&As[aOff + mt * 256];
            uint4 U1 = *(const uint4*)&As[aOff + mt * 256 + 128];
            uint32_t a0[4] = {U0.x, U1.x, U0.y, U1.y};
            uint32_t a1[4] = {U0.z, U1.z, U0.w, U1.w};
#pragma unroll
            for (int nt = 0; nt < 4; nt++)
                mma_f16(acc[mt][nt], a0, Vb[nt].x, Vb[nt].y);
#pragma unroll
            for (int nt = 0; nt < 4; nt++)
                mma_f16(acc[mt][nt], a1, Vb[nt].z, Vb[nt].w);
        }
        if (c < 7)
            load_aU<AMODE>(tid, rowBase, (c + 1) * 32, A, s2_s, t2_s, aU);
#pragma unroll
        for (int mt = 2; mt < 4; mt++) {
            uint4 U0 = *(const uint4*)&As[aOff + mt * 256];
            uint4 U1 = *(const uint4*)&As[aOff + mt * 256 + 128];
            uint32_t a0[4] = {U0.x, U1.x, U0.y, U1.y};
            uint32_t a1[4] = {U0.z, U1.z, U0.w, U1.w};
#pragma unroll
            for (int nt = 0; nt < 4; nt++)
                mma_f16(acc[mt][nt], a0, Vb[nt].x, Vb[nt].y);
#pragma unroll
            for (int nt = 0; nt < 4; nt++)
                mma_f16(acc[mt][nt], a1, Vb[nt].z, Vb[nt].w);
        }
        if (c < 7) sts_a(st ^ 1, aU);
        cp_wait<0>();
        __syncthreads();
        if (c + 2 < 8) cp_b(st, c + 2);
    }

#pragma unroll
    for (int mt = 0; mt < 4; mt++) {
        int row0 = rowBase + mt * 16 + lg;
#pragma unroll
        for (int nt = 0; nt < 4; nt++) {
            int col = w * 32 + nt * 8 + 2 * la3;
            float b0 = bias_s[col];
            float b1 = bias_s[col + 1];
            float v00 = acc[mt][nt][0] + b0, v01 = acc[mt][nt][1] + b1;
            float v10 = acc[mt][nt][2] + b0, v11 = acc[mt][nt][3] + b1;
            if (OUT16) {
                uint32_t* O16 = (uint32_t*)OutP;
                O16[(size_t)row0 * 128 + (col >> 1)]       = f16pk(v00, v01);
                O16[(size_t)(row0 + 8) * 128 + (col >> 1)] = f16pk(v10, v11);
            } else {
                float* Out = (float*)OutP;
                *(float2*)&Out[(size_t)row0 * 256 + col]       = make_float2(v00, v01);
                *(float2*)&Out[(size_t)(row0 + 8) * 256 + col] = make_float2(v10, v11);
            }
        }
    }
}

// ----------------------- fused produce+attention kernel ---------------------
// 512 threads, 16 warps (2 row x 8 col), full 256 cols per subpass.
// EPI: 0 = qk = q-k ; 1 = va = dm*qk ; 2 = va += db ; 3 = we = omega*v
// ASRC: 0 = pos-enc build (double-buffer) ; 1 = nf build into ANF ; 2 = read ANF
template <int EPI, int ASRC>
__device__ __noinline__ void run_subpass(
    uint32_t* sm, int tid, int rowBase,
    const float* __restrict__ nf,
    const uint32_t* __restrict__ Bmat,
    const float* bias_s, const float* w1f_s, const float* b1f_s,
    const float* diff_s, int blockId) {

    uint32_t smemB_addr = smem_u32(sm + FS_BSTG);
    auto cp_b = [&](int stage, int c) {
        const uint32_t* src0 = Bmat + (size_t)c * 2048;
        const uint32_t* src1 = Bmat + (size_t)(8 + c) * 2048;
        uint32_t dstb = smemB_addr + (uint32_t)stage * 16384u;
        int e = tid;
        cp16(dstb + (uint32_t)e * 16u, src0 + e * 4);
        cp16(dstb + 8192u + (uint32_t)e * 16u, src1 + e * 4);
        cp_commit();
    };

    uint2 aU[2];
    auto load_a = [&](int kb) {
#pragma unroll
        for (int i = 0; i < 2; i++) {
            int f = tid + i * 512, row = f >> 3, kq = f & 7;
            if (ASRC == 0) {
                float d0 = diff_s[row * 4], d1 = diff_s[row * 4 + 1], d2 = diff_s[row * 4 + 2];
                float t[4];
#pragma unroll
                for (int j = 0; j < 4; j++) {
                    int k = kb + kq * 4 + j;
                    float h = fmaf(d0, w1f_s[k * 3],
                              fmaf(d1, w1f_s[k * 3 + 1],
                              fmaf(d2, w1f_s[k * 3 + 2], b1f_s[k])));
                    t[j] = fmaxf(h, 0.f);
                }
                aU[i].x = f16pk(t[0], t[1]);
                aU[i].y = f16pk(t[2], t[3]);
            } else {
                float4 v = *(const float4*)&nf[(size_t)(rowBase + row) * 256 + kb + kq * 4];
                aU[i].x = f16pk(v.x, v.y);
                aU[i].y = f16pk(v.z, v.w);
            }
        }
    };
    auto sts_a = [&](uint32_t* dst) {
#pragma unroll
        for (int i = 0; i < 2; i++) {
            int f = tid + i * 512, row = f >> 3, kq = f & 7;
            dst[pkidx(row, 2 * kq)]     = aU[i].x;
            dst[pkidx(row, 2 * kq + 1)] = aU[i].y;
        }
    };

    cp_b(0, 0);
    cp_b(1, 1);
    if (ASRC == 0) { load_a(0); sts_a(sm + FS_ASTG); }
    if (ASRC == 1) { load_a(0); sts_a(sm + FS_ANF); }
    cp_wait<0>();
    __syncthreads();

    int lane = tid & 31, w = tid >> 5;
    int wm = w & 1, wn = w >> 1;
    int la3 = lane & 3, lg = lane >> 2;
    int axor = 4 * (la3 ^ (lg & 3));
    const int aOff = (wm * 64 + lg) * 16 + axor;
    const int bOff = (wn * 32 + lg) * 16 + axor;

    float acc[4][4][4];
#pragma unroll
    for (int mt = 0; mt < 4; mt++)
#pragma unroll
        for (int nt = 0; nt < 4; nt++)
#pragma unroll
            for (int r = 0; r < 4; r++) acc[mt][nt][r] = 0.f;

    for (int c = 0; c < 8; c++) {
        int st = c & 1;
        const uint32_t* As = (ASRC == 0) ? (sm + FS_ASTG + st * 2048)
                                         : (sm + FS_ANF + c * 2048);
        const uint32_t* Bs = sm + FS_BSTG + st * 4096;

        uint4 Vb[4];
#pragma unroll
        for (int nt = 0; nt < 4; nt++)
            Vb[nt] = *(const uint4*)&Bs[bOff + nt * 128];
#pragma unroll
        for (int mt = 0; mt < 2; mt++) {
            uint4 U0 = *(const uint4*)&As[aOff + mt * 256];
            uint4 U1 = *(const uint4*)&As[aOff + mt * 256 + 128];
            uint32_t a0[4] = {U0.x, U1.x, U0.y, U1.y};
            uint32_t a1[4] = {U0.z, U1.z, U0.w, U1.w};
#pragma unroll
            for (int nt = 0; nt < 4; nt++)
                mma_f16(acc[mt][nt], a0, Vb[nt].x, Vb[nt].y);
#pragma unroll
            for (int nt = 0; nt < 4; nt++)
                mma_f16(acc[mt][nt], a1, Vb[nt].z, Vb[nt].w);
        }
        if (ASRC != 2 && c < 7) load_a((c + 1) * 32);
#pragma unroll
        for (int mt = 2; mt < 4; mt++) {
            uint4 U0 = *(const uint4*)&As[aOff + mt * 256];
            uint4 U1 = *(const uint4*)&As[aOff + mt * 256 + 128];
            uint32_t a0[4] = {U0.x, U1.x, U0.y, U1.y};
            uint32_t a1[4] = {U0.z, U1.z, U0.w, U1.w};
#pragma unroll
            for (int nt = 0; nt < 4; nt++)
                mma_f16(acc[mt][nt], a0, Vb[nt].x, Vb[nt].y);
#pragma unroll
            for (int nt = 0; nt < 4; nt++)
                mma_f16(acc[mt][nt], a1, Vb[nt].z, Vb[nt].w);
        }
        if (c < 7) {
            if (ASRC == 0) sts_a(sm + FS_ASTG + (st ^ 1) * 2048);
            if (ASRC == 1) sts_a(sm + FS_ANF + (c + 1) * 2048);
        }
        cp_wait<0>();
        __syncthreads();
        if (c + 2 < 8) cp_b(st, c + 2);
    }

    // ---- epilogue ----
    float csum[8], csq[8];
#pragma unroll
    for (int j = 0; j < 8; j++) { csum[j] = 0.f; csq[j] = 0.f; }

#pragma unroll
    for (int mt = 0; mt < 4; mt++) {
        int row0 = wm * 64 + mt * 16 + lg;
#pragma unroll
        for (int nt = 0; nt < 4; nt++) {
            int col = wn * 32 + nt * 8 + 2 * la3;
            float b0 = bias_s[col], b1 = bias_s[col + 1];
            int vi0 = row0 * 132 + (col >> 1);
            int vi1 = (row0 + 8) * 132 + (col >> 1);
            float a0 = acc[mt][nt][0] + b0, a1 = acc[mt][nt][1] + b1;
            float a2 = acc[mt][nt][2] + b0, a3 = acc[mt][nt][3] + b1;
            if (EPI == 0) {
                float2 qv = upk(sm[FS_Q + (wm * 4 + mt) * 128 + (col >> 1)]);
                sm[FS_VA + vi0] = f16pk(qv.x - a0, qv.y - a1);
                sm[FS_VA + vi1] = f16pk(qv.x - a2, qv.y - a3);
            } else if (EPI == 1) {
                float2 u0 = upk(sm[FS_VA + vi0]), u1 = upk(sm[FS_VA + vi1]);
                sm[FS_VA + vi0] = f16pk(a0 * u0.x, a1 * u0.y);
                sm[FS_VA + vi1] = f16pk(a2 * u1.x, a3 * u1.y);
            } else if (EPI == 2) {
                float2 u0 = upk(sm[FS_VA + vi0]), u1 = upk(sm[FS_VA + vi1]);
                sm[FS_VA + vi0] = f16pk(u0.x + a0, u0.y + a1);
                sm[FS_VA + vi1] = f16pk(u1.x + a2, u1.y + a3);
            } else {
                const float* om = (const float*)(sm + FS_OM);
                float o0 = om[row0 * 36 + (col >> 3)];
                float o1 = om[(row0 + 8) * 36 + (col >> 3)];
                float w00 = o0 * a0, w01 = o0 * a1;
                float w10 = o1 * a2, w11 = o1 * a3;
                g_we16[(size_t)(rowBase + row0) * 128 + (col >> 1)]     = f16pk(w00, w01);
                g_we16[(size_t)(rowBase + row0 + 8) * 128 + (col >> 1)] = f16pk(w10, w11);
                csum[nt * 2]     += w00 + w10;
                csum[nt * 2 + 1] += w01 + w11;
                csq[nt * 2]      += w00 * w00 + w10 * w10;
                csq[nt * 2 + 1]  += w01 * w01 + w11 * w11;
            }
        }
    }
    if (EPI == 3) {
#pragma unroll
        for (int j = 0; j < 8; j++) {
#pragma unroll
            for (int off = 4; off < 32; off <<= 1) {
                csum[j] += __shfl_xor_sync(0xffffffffu, csum[j], off);
                csq[j]  += __shfl_xor_sync(0xffffffffu, csq[j],  off);
            }
        }
        float* red = (float*)(sm + FS_FX) + FXF_RED;
        if (lg == 0) {
#pragma unroll
            for (int u = 0; u < 8; u++) {
                int nt = u >> 1, uu = u & 1;
                int lc = nt * 8 + 2 * la3 + uu;
                red[w * 32 + lc]       = csum[u];
                red[512 + w * 32 + lc] = csq[u];
            }
        }
        __syncthreads();
        if (tid < 256) {
            int c2 = tid, wg = c2 >> 5, idx = c2 & 31;
            float s  = red[(2 * wg) * 32 + idx]       + red[(2 * wg + 1) * 32 + idx];
            float sq = red[512 + (2 * wg) * 32 + idx] + red[512 + (2 * wg + 1) * 32 + idx];
            g_part2[(size_t)blockId * 512 + c2]       = s;
            g_part2[(size_t)blockId * 512 + 256 + c2] = sq;
        }
        __syncthreads();
    } else {
        __syncthreads();
    }
}

__global__ void __launch_bounds__(512, 1)
fused_kernel(const float* __restrict__ nf, const float* __restrict__ pts,
             const float* __restrict__ nbr,
             const float* __restrict__ k_b, const float* __restrict__ dm_b2,
             const float* __restrict__ db_b2, const float* __restrict__ v_b,
             const float* __restrict__ convw) {
    extern __shared__ uint32_t sm[];
    float* fx = (float*)(sm + FS_FX);
    int tid = threadIdx.x;
    int rowBase = blockIdx.x * 128;

    if (tid < 256) {
        fx[FXF_KB + tid]  = k_b[tid];
        fx[FXF_DMB + tid] = dm_b2[tid];
        fx[FXF_DBB + tid] = db_b2[tid];
        fx[FXF_VB + tid]  = v_b[tid];
        fx[FXF_B1F + tid]       = g_b1f[0][tid];
        fx[FXF_B1F + 256 + tid] = g_b1f[1][tid];
    }
    for (int i = tid; i < 1024; i += 512) fx[FXF_CW + i] = convw[i];
    for (int i = tid; i < 768; i += 512) {
        fx[FXF_W1F + i]       = g_w1f[0][i];
        fx[FXF_W1F + 768 + i] = g_w1f[1][i];
    }
    if (tid < 128) {
        int r = rowBase + tid, bn = r >> 4;
        fx[FXF_DIFF + tid * 4 + 0] = pts[bn * 3 + 0] - nbr[(size_t)r * 3 + 0];
        fx[FXF_DIFF + tid * 4 + 1] = pts[bn * 3 + 1] - nbr[(size_t)r * 3 + 1];
        fx[FXF_DIFF + tid * 4 + 2] = pts[bn * 3 + 2] - nbr[(size_t)r * 3 + 2];
    }
    {
        int bnb = rowBase >> 4;
        for (int i = tid; i < 1024; i += 512) sm[FS_Q + i] = g_q16[bnb * 128 + i];
    }
    __syncthreads();

    const uint32_t* BK  = g_Bpk + 1 * 32768;
    const uint32_t* BV  = g_Bpk + 2 * 32768;
    const uint32_t* BDM = g_Bpk + 3 * 32768;
    const uint32_t* BDB = g_Bpk + 4 * 32768;
    const float* diff_s = fx + FXF_DIFF;

    run_subpass<0, 1>(sm, tid, rowBase, nf, BK,  fx + FXF_KB,  nullptr, nullptr, diff_s, blockIdx.x);
    run_subpass<1, 0>(sm, tid, rowBase, nf, BDM, fx + FXF_DMB, fx + FXF_W1F,       fx + FXF_B1F,       diff_s, blockIdx.x);
    run_subpass<2, 0>(sm, tid, rowBase, nf, BDB, fx + FXF_DBB, fx + FXF_W1F + 768, fx + FXF_B1F + 256, diff_s, blockIdx.x);

    // ---- attention: va -> omega ----
    __syncthreads();
    {
        int l = tid & 31, w = tid >> 5;
        float cwr[32];
#pragma unroll
        for (int i = 0; i < 32; i++)
            cwr[i] = fx[FXF_CW + (l >> 2) * 128 + (l & 3) * 32 + i];
        float* om = (float*)(sm + FS_OM);
        int gb = (l >> 2) * 16;
        for (int it = 0; it < 8; it++) {
            int row = w * 8 + it;
            const uint32_t* vrow = sm + FS_VA + row * 132;
            float acc = 0.f;
#pragma unroll
            for (int t = 0; t < 16; t += 2) {
                uint2 u = *(const uint2*)&vrow[gb + t];
                float2 f0 = upk(u.x), f1 = upk(u.y);
                int i0 = t * 2;
                acc = fmaf(f0.x, cwr[i0], acc);
                acc = fmaf(f0.y, cwr[i0 + 1], acc);
                acc = fmaf(f1.x, cwr[i0 + 2], acc);
                acc = fmaf(f1.y, cwr[i0 + 3], acc);
            }
            float mx = acc;
#pragma unroll
            for (int off = 16; off > 0; off >>= 1)
                mx = fmaxf(mx, __shfl_xor_sync(0xffffffffu, mx, off));
            float e = expf(acc - mx);
            float ss = e;
#pragma unroll
            for (int off = 16; off > 0; off >>= 1)
                ss += __shfl_xor_sync(0xffffffffu, ss, off);
            om[row * 36 + l] = e / ss;
        }
    }
    __syncthreads();

    run_subpass<3, 2>(sm, tid, rowBase, nf, BV, fx + FXF_VB, nullptr, nullptr, diff_s, blockIdx.x);
}

// --------------------------- BN2 reductions --------------------------------
__global__ void reduce_part2() {          // grid 64, block 256
    int b = blockIdx.x, tid = threadIdx.x;
    for (int c = tid; c < 512; c += 256) {
        float s = 0.f;
#pragma unroll 8
        for (int i = 0; i < 32; i++)
            s += g_part2[(size_t)(b * 32 + i) * 512 + c];
        g_part2r[b * 512 + c] = s;
    }
}

__global__ void finalize2_kernel(const float* __restrict__ bn_g,
                                 const float* __restrict__ bn_b) {
    int c = threadIdx.x;
    float s = 0.f, sq = 0.f;
    for (int b = 0; b < 64; b++) {
        s  += g_part2r[b * 512 + c];
        sq += g_part2r[b * 512 + 256 + c];
    }
    float mean = s / (float)R_;
    float var = sq / (float)R_ - mean * mean;
    float sc = bn_g[c] * rsqrtf(var + EPSV);
    g_s2[c] = sc;
    g_t2[c] = bn_b[c] - mean * sc;
}

// ------------------------------- launch -------------------------------------
extern "C" void kernel_launch(void* const* d_in, const int* in_sizes, int n_in,
                              void* d_out, int out_size) {
    const float* pts   = (const float*)d_in[0];
    const float* pf    = (const float*)d_in[1];
    const float* nbr   = (const float*)d_in[2];
    const float* nf    = (const float*)d_in[3];
    const float* dm_w1 = (const float*)d_in[4];
    const float* dm_b1 = (const float*)d_in[5];
    const float* dm_w2 = (const float*)d_in[6];
    const float* dm_b2 = (const float*)d_in[7];
    const float* dm_g  = (const float*)d_in[8];
    const float* dm_be = (const float*)d_in[9];
    const float* db_w1 = (const float*)d_in[10];
    const float* db_b1 = (const float*)d_in[11];
    const float* db_w2 = (const float*)d_in[12];
    const float* db_b2 = (const float*)d_in[13];
    const float* db_g  = (const float*)d_in[14];
    const float* db_be = (const float*)d_in[15];
    const float* q_w   = (const float*)d_in[16];
    const float* q_b   = (const float*)d_in[17];
    const float* k_w   = (const float*)d_in[18];
    const float* k_b   = (const float*)d_in[19];
    const float* v_w   = (const float*)d_in[20];
    const float* v_b   = (const float*)d_in[21];
    const float* convw = (const float*)d_in[22];
    const float* bn_g  = (const float*)d_in[23];
    const float* bn_b  = (const float*)d_in[24];
    const float* lin_w = (const float*)d_in[25];
    const float* lin_b = (const float*)d_in[26];
    float* out = (float*)d_out;

    void *p_q, *p_we, *p_bpk;
    cudaGetSymbolAddress(&p_q,   g_q16);
    cudaGetSymbolAddress(&p_we,  g_we16);
    cudaGetSymbolAddress(&p_bpk, g_Bpk);
    const uint32_t* Bpk = (const uint32_t*)p_bpk;

    cudaFuncSetAttribute(gemm_mma<AMODE_DIRECT, true>,
                         cudaFuncAttributeMaxDynamicSharedMemorySize, G_DYN_SMEM);
    cudaFuncSetAttribute(gemm_mma<AMODE_F16BN, false>,
                         cudaFuncAttributeMaxDynamicSharedMemorySize, G_DYN_SMEM);
    cudaFuncSetAttribute(fused_kernel,
                         cudaFuncAttributeMaxDynamicSharedMemorySize, FUSED_SMEM);

    prep_weights<<<dim3(8, 2, 6), 256>>>(q_w, k_w, v_w, dm_w2, db_w2, lin_w);
    diffstats_kernel<<<STAT_BLOCKS, 256>>>(pts, nbr);
    fold_kernel<<<1, 256>>>(dm_w1, dm_b1, dm_g, dm_be, db_w1, db_b1, db_g, db_be);

    gemm_mma<AMODE_DIRECT, true><<<BNp / 64, 256, G_DYN_SMEM>>>(
        pf, Bpk + 0 * 32768, q_b, p_q);

    fused_kernel<<<NTILES, 512, FUSED_SMEM>>>(nf, pts, nbr,
                                              k_b, dm_b2, db_b2, v_b, convw);

    reduce_part2<<<64, 256>>>();
    finalize2_kernel<<<1, 256>>>(bn_g, bn_b);

    gemm_mma<AMODE_F16BN, false><<<R_ / 64, 256, G_DYN_SMEM>>>(
        p_we, Bpk + 5 * 32768, lin_b, out);
}

// round 10
// speedup vs baseline: 2.6562x; 1.0571x over previous
#include <cuda_runtime.h>
#include <cstdint>

// ---------------------------------------------------------------------------
// GroupVectorAttention — fused produce+attention at OCCUPANCY 2:
// 64-row tiles, 256 threads, ~103KB smem -> two CTAs per SM hide each
// other's barrier/cp stalls. Subpasses: k->qk, dm->va, db->va+, softmax,
// v->we(+BN2 partials). Standalone 64-row GEMMs for q and the final linear.
// ---------------------------------------------------------------------------

#define EPSV 1e-5f

static constexpr int Bb = 4, Nn = 4096, Mm = 16, Cd = 256;
static constexpr int R_ = Bb * Nn * Mm;       // 262144
static constexpr int BNp = Bb * Nn;           // 16384
static constexpr int STAT_BLOCKS = 256;
static constexpr int NTILES = R_ / 64;        // 4096 fused tiles

// ---- standalone GEMM smem layout (u32 units): A 2x1024 | B 2x4096 | fx ----
static constexpr int G_SOFF_B  = 2048;
static constexpr int G_SOFF_FX = 10240;
static constexpr int G_FX_BIAS = 0, G_FX_S2 = 256, G_FX_T2 = 512;
static constexpr int G_DYN_SMEM = (10240 + 768) * 4;     // 44032 B

// ---- fused kernel smem layout (u32 units), 64-row tile ----
static constexpr int FS_ASTG = 0;                 // 2*1024
static constexpr int FS_BSTG = 2048;              // 2*4096
static constexpr int FS_VA   = 10240;             // 64*132
static constexpr int FS_Q    = 18688;             // 512
static constexpr int FS_OM   = 19200;             // 64*36 fp32
static constexpr int FS_FX   = 21504;             // floats below (4352)
static constexpr int FXF_KB = 0, FXF_DMB = 256, FXF_DBB = 512, FXF_VB = 768,
                     FXF_CW = 1024, FXF_W1F = 2048, FXF_B1F = 3584,
                     FXF_DIFF = 4096;             // 256
static constexpr int FUSED_SMEM = (21504 + 4352) * 4;    // 103424 B

// ------------------------- device scratch (static) -------------------------
__device__ float g_part1[STAT_BLOCKS * 12];
__device__ float g_w1f[2][Cd * 3];
__device__ float g_b1f[2][Cd];
__device__ uint32_t g_q16[BNp * 128];
__device__ uint32_t g_we16[(size_t)R_ * 128];
__device__ float g_part2[(size_t)NTILES * 512];
__device__ float g_part2r[64 * 512];
__device__ float g_s2[Cd], g_t2[Cd];
// packed fp16 weight images: [mat(6)][nb(2)][chunk(8)][2048 u32]
__device__ uint32_t g_Bpk[6 * 2 * 8 * 2048];

// ----------------------------- PTX helpers ---------------------------------
__device__ __forceinline__ uint32_t smem_u32(const void* p) {
    uint32_t a;
    asm("{ .reg .u64 t; cvta.to.shared.u64 t, %1; cvt.u32.u64 %0, t; }"
        : "=r"(a) : "l"(p));
    return a;
}
__device__ __forceinline__ void cp16(uint32_t dst, const void* src) {
    asm volatile("cp.async.cg.shared.global [%0], [%1], 16;"
                 :: "r"(dst), "l"(src) : "memory");
}
__device__ __forceinline__ void cp_commit() {
    asm volatile("cp.async.commit_group;" ::: "memory");
}
template <int N>
__device__ __forceinline__ void cp_wait() {
    asm volatile("cp.async.wait_group %0;" :: "n"(N) : "memory");
}
__device__ __forceinline__ void mma_f16(float* c, const uint32_t* a,
                                        uint32_t b0, uint32_t b1) {
    asm volatile("mma.sync.aligned.m16n8k16.row.col.f32.f16.f16.f32 "
                 "{%0,%1,%2,%3}, {%4,%5,%6,%7}, {%8,%9}, {%0,%1,%2,%3};"
                 : "+f"(c[0]), "+f"(c[1]), "+f"(c[2]), "+f"(c[3])
                 : "r"(a[0]), "r"(a[1]), "r"(a[2]), "r"(a[3]),
                   "r"(b0), "r"(b1));
}
__device__ __forceinline__ uint32_t f16pk(float lo, float hi) {
    uint32_t r;
    asm("cvt.rn.f16x2.f32 %0, %1, %2;" : "=r"(r) : "f"(hi), "f"(lo));
    return r;
}
__device__ __forceinline__ float2 upk(uint32_t u) {
    float2 f;
    asm("{ .reg .b16 lo, hi; mov.b32 {lo, hi}, %2; "
        "cvt.f32.f16 %0, lo; cvt.f32.f16 %1, hi; }"
        : "=f"(f.x), "=f"(f.y) : "r"(u));
    return f;
}
__device__ __forceinline__ int pkidx(int n, int p) {
    return n * 16 + 4 * ((p & 3) ^ (n & 3)) + 2 * (p >> 3) + ((p >> 2) & 1);
}

// ------------------------------- K1: stats --------------------------------
__global__ void diffstats_kernel(const float* __restrict__ pts,
                                 const float* __restrict__ nbr) {
    float s[12];
#pragma unroll
    for (int i = 0; i < 12; i++) s[i] = 0.f;
    int tid = threadIdx.x;
    for (int r = blockIdx.x * blockDim.x + tid; r < R_; r += gridDim.x * blockDim.x) {
        int bn = r >> 4;
        float d[3];
#pragma unroll
        for (int j = 0; j < 3; j++) d[j] = pts[bn * 3 + j] - nbr[(size_t)r * 3 + j];
#pragma unroll
        for (int j = 0; j < 3; j++) s[j] += d[j];
#pragma unroll
        for (int j = 0; j < 3; j++)
#pragma unroll
            for (int k = 0; k < 3; k++) s[3 + j * 3 + k] += d[j] * d[k];
    }
    __shared__ float red[256];
    for (int comp = 0; comp < 12; comp++) {
        red[tid] = s[comp];
        __syncthreads();
        for (int off = 128; off > 0; off >>= 1) {
            if (tid < off) red[tid] += red[tid + off];
            __syncthreads();
        }
        if (tid == 0) g_part1[blockIdx.x * 12 + comp] = red[0];
        __syncthreads();
    }
}

// ------------------------------ K2: BN1 fold -------------------------------
__global__ void fold_kernel(const float* __restrict__ dm_w1, const float* __restrict__ dm_b1,
                            const float* __restrict__ dm_g,  const float* __restrict__ dm_be,
                            const float* __restrict__ db_w1, const float* __restrict__ db_b1,
                            const float* __restrict__ db_g,  const float* __restrict__ db_be) {
    __shared__ float st[12];
    __shared__ float mu[3], cov[9];
    int tid = threadIdx.x;
    if (tid < 12) {
        float a = 0.f;
        for (int b = 0; b < STAT_BLOCKS; b++) a += g_part1[b * 12 + tid];
        st[tid] = a / (float)R_;
    }
    __syncthreads();
    if (tid < 3) mu[tid] = st[tid];
    if (tid < 9) {
        int j = tid / 3, k = tid % 3;
        cov[tid] = st[3 + tid] - st[j] * st[k];
    }
    __syncthreads();
    int c = tid;
    for (int which = 0; which < 2; which++) {
        const float* w1 = which ? db_w1 : dm_w1;
        const float* b1 = which ? db_b1 : dm_b1;
        const float* gg = which ? db_g  : dm_g;
        const float* be = which ? db_be : dm_be;
        float w0 = w1[c * 3], w1v = w1[c * 3 + 1], w2v = w1[c * 3 + 2];
        float var = w0 * w0 * cov[0] + w1v * w1v * cov[4] + w2v * w2v * cov[8]
                  + 2.f * (w0 * w1v * cov[1] + w0 * w2v * cov[2] + w1v * w2v * cov[5]);
        float mdot = w0 * mu[0] + w1v * mu[1] + w2v * mu[2];
        float m = mdot + b1[c];
        float s = gg[c] * rsqrtf(var + EPSV);
        g_w1f[which][c * 3]     = w0 * s;
        g_w1f[which][c * 3 + 1] = w1v * s;
        g_w1f[which][c * 3 + 2] = w2v * s;
        g_b1f[which][c] = be[c] + s * (b1[c] - m);
    }
}

// ----------------------- weight prep: fp32 -> packed fp16 -------------------
__global__ void prep_weights(const float* __restrict__ q_w, const float* __restrict__ k_w,
                             const float* __restrict__ v_w, const float* __restrict__ dm_w2,
                             const float* __restrict__ db_w2, const float* __restrict__ lin_w) {
    int c = blockIdx.x, nb = blockIdx.y, mat = blockIdx.z;
    const float* W = mat == 0 ? q_w : mat == 1 ? k_w : mat == 2 ? v_w :
                     mat == 3 ? dm_w2 : mat == 4 ? db_w2 : lin_w;
    uint32_t* dst = g_Bpk + (((size_t)mat * 2 + nb) * 8 + c) * 2048;
    int tid = threadIdx.x;
    int n = tid >> 1, q = tid & 1;
    const float* src = W + (size_t)(nb * 128 + n) * 256 + c * 32 + q * 16;
    float cc[16];
#pragma unroll
    for (int j = 0; j < 16; j += 4) {
        float4 v = *(const float4*)&src[j];
        cc[j] = v.x; cc[j + 1] = v.y; cc[j + 2] = v.z; cc[j + 3] = v.w;
    }
#pragma unroll
    for (int t = 0; t < 4; t++)
#pragma unroll
        for (int u = 0; u < 2; u++) {
            int p = 8 * q + t + 4 * u;
            dst[pkidx(n, p)] = f16pk(cc[2 * t + 8 * u], cc[2 * t + 8 * u + 1]);
        }
}

// ----------------- standalone GEMM: 64-row tiles, full N=256 ----------------
enum { AMODE_DIRECT = 0, AMODE_F16BN = 2 };

template <int AMODE>
__device__ __forceinline__ void load_aU(
    int tid, int rowBase, int kb, const void* __restrict__ Ap,
    const float* s2_s, const float* t2_s, uint2 aU[2]) {
#pragma unroll
    for (int i = 0; i < 2; i++) {
        int f = tid + i * 256, row = f >> 3, kq = f & 7;
        if (AMODE == AMODE_DIRECT) {
            const float* A = (const float*)Ap;
            float4 v = *(const float4*)&A[(size_t)(rowBase + row) * 256 + kb + kq * 4];
            aU[i].x = f16pk(v.x, v.y);
            aU[i].y = f16pk(v.z, v.w);
        } else {
            const uint32_t* A16 = (const uint32_t*)Ap;
            uint2 u = *(const uint2*)&A16[(size_t)(rowBase + row) * 128 + (kb >> 1) + kq * 2];
            float2 f0 = upk(u.x), f1 = upk(u.y);
            int k = kb + kq * 4;
            float x0 = fmaxf(fmaf(f0.x, s2_s[k],     t2_s[k]),     0.f);
            float x1 = fmaxf(fmaf(f0.y, s2_s[k + 1], t2_s[k + 1]), 0.f);
            float x2 = fmaxf(fmaf(f1.x, s2_s[k + 2], t2_s[k + 2]), 0.f);
            float x3 = fmaxf(fmaf(f1.y, s2_s[k + 3], t2_s[k + 3]), 0.f);
            aU[i].x = f16pk(x0, x1);
            aU[i].y = f16pk(x2, x3);
        }
    }
}

template <int AMODE, bool OUT16>
__global__ void __launch_bounds__(256, 2)
gemm_mma(const void* __restrict__ A, const uint32_t* __restrict__ Bpk,
         const float* __restrict__ bias, void* __restrict__ OutP) {
    extern __shared__ uint32_t sm[];
    float* fx     = (float*)(sm + G_SOFF_FX);
    float* bias_s = fx + G_FX_BIAS;
    float* s2_s   = fx + G_FX_S2;
    float* t2_s   = fx + G_FX_T2;

    int tid = threadIdx.x;
    int rowBase = blockIdx.x * 64;

    bias_s[tid] = bias[tid];
    if (AMODE == AMODE_F16BN) {
        s2_s[tid] = g_s2[tid];
        t2_s[tid] = g_t2[tid];
    }
    __syncthreads();

    uint32_t smemB_addr = smem_u32(sm + G_SOFF_B);

    auto cp_b = [&](int stage, int c) {
        uint32_t dstb = smemB_addr + (uint32_t)stage * 16384u;
#pragma unroll
        for (int i = 0; i < 4; i++) {
            int off = (tid + i * 256) * 4;
            const uint32_t* src = (off < 2048)
                ? Bpk + (size_t)c * 2048 + off
                : Bpk + (size_t)(8 + c) * 2048 + (off - 2048);
            cp16(dstb + (uint32_t)off * 4u, src);
        }
        cp_commit();
    };
    auto sts_a = [&](int stage, const uint2* aU) {
        uint32_t* dst = sm + stage * 1024;
#pragma unroll
        for (int i = 0; i < 2; i++) {
            int f = tid + i * 256, row = f >> 3, kq = f & 7;
            dst[pkidx(row, 2 * kq)]     = aU[i].x;
            dst[pkidx(row, 2 * kq + 1)] = aU[i].y;
        }
    };

    cp_b(0, 0);
    cp_b(1, 1);
    uint2 aU[2];
    load_aU<AMODE>(tid, rowBase, 0, A, s2_s, t2_s, aU);
    sts_a(0, aU);
    cp_wait<0>();
    __syncthreads();

    int lane = tid & 31, w = tid >> 5;
    int la3 = lane & 3, lg = lane >> 2;
    int axor = 4 * (la3 ^ (lg & 3));
    const int aOff = lg * 16 + axor;
    const int bOff = (w * 32 + lg) * 16 + axor;

    float acc[4][4][4];
#pragma unroll
    for (int mt = 0; mt < 4; mt++)
#pragma unroll
        for (int nt = 0; nt < 4; nt++)
#pragma unroll
            for (int r = 0; r < 4; r++) acc[mt][nt][r] = 0.f;

    for (int c = 0; c < 8; c++) {
        int st = c & 1;
        const uint32_t* As = sm + st * 1024;
        const uint32_t* Bs = sm + G_SOFF_B + st * 4096;

        uint4 Vb[4];
#pragma unroll
        for (int nt = 0; nt < 4; nt++)
            Vb[nt] = *(const uint4*)&Bs[bOff + nt * 128];
#pragma unroll
        for (int mt = 0; mt < 2; mt++) {
            uint4 U0 = *(const uint4*)&As[aOff + mt * 256];
            uint4 U1 = *(const uint4*)&As[aOff + mt * 256 + 128];
            uint32_t a0[4] = {U0.x, U1.x, U0.y, U1.y};
            uint32_t a1[4] = {U0.z, U1.z, U0.w, U1.w};
#pragma unroll
            for (int nt = 0; nt < 4; nt++)
                mma_f16(acc[mt][nt], a0, Vb[nt].x, Vb[nt].y);
#pragma unroll
            for (int nt = 0; nt < 4; nt++)
                mma_f16(acc[mt][nt], a1, Vb[nt].z, Vb[nt].w);
        }
        if (c < 7)
            load_aU<AMODE>(tid, rowBase, (c + 1) * 32, A, s2_s, t2_s, aU);
#pragma unroll
        for (int mt = 2; mt < 4; mt++) {
            uint4 U0 = *(const uint4*)&As[aOff + mt * 256];
            uint4 U1 = *(const uint4*)&As[aOff + mt * 256 + 128];
            uint32_t a0[4] = {U0.x, U1.x, U0.y, U1.y};
            uint32_t a1[4] = {U0.z, U1.z, U0.w, U1.w};
#pragma unroll
            for (int nt = 0; nt < 4; nt++)
                mma_f16(acc[mt][nt], a0, Vb[nt].x, Vb[nt].y);
#pragma unroll
            for (int nt = 0; nt < 4; nt++)
                mma_f16(acc[mt][nt], a1, Vb[nt].z, Vb[nt].w);
        }
        if (c < 7) sts_a(st ^ 1, aU);
        cp_wait<0>();
        __syncthreads();
        if (c + 2 < 8) cp_b(st, c + 2);
    }

#pragma unroll
    for (int mt = 0; mt < 4; mt++) {
        int row0 = rowBase + mt * 16 + lg;
#pragma unroll
        for (int nt = 0; nt < 4; nt++) {
            int col = w * 32 + nt * 8 + 2 * la3;
            float b0 = bias_s[col];
            float b1 = bias_s[col + 1];
            float v00 = acc[mt][nt][0] + b0, v01 = acc[mt][nt][1] + b1;
            float v10 = acc[mt][nt][2] + b0, v11 = acc[mt][nt][3] + b1;
            if (OUT16) {
                uint32_t* O16 = (uint32_t*)OutP;
                O16[(size_t)row0 * 128 + (col >> 1)]       = f16pk(v00, v01);
                O16[(size_t)(row0 + 8) * 128 + (col >> 1)] = f16pk(v10, v11);
            } else {
                float* Out = (float*)OutP;
                *(float2*)&Out[(size_t)row0 * 256 + col]       = make_float2(v00, v01);
                *(float2*)&Out[(size_t)(row0 + 8) * 256 + col] = make_float2(v10, v11);
            }
        }
    }
}

// ----------------------- fused produce+attention kernel ---------------------
// 256 threads, 8 col-warps, 64-row tile, occupancy 2.
// EPI: 0 = qk = q-k ; 1 = va = dm*qk ; 2 = va += db ; 3 = we = omega*v
template <int EPI, bool POS>
__device__ __noinline__ void run_subpass(
    uint32_t* sm, int tid, int rowBase,
    const float* __restrict__ nf,
    const uint32_t* __restrict__ Bmat,
    const float* bias_s, const float* w1f_s, const float* b1f_s,
    const float* diff_s, int blockId) {

    uint32_t smemB_addr = smem_u32(sm + FS_BSTG);
    auto cp_b = [&](int stage, int c) {
        uint32_t dstb = smemB_addr + (uint32_t)stage * 16384u;
#pragma unroll
        for (int i = 0; i < 4; i++) {
            int off = (tid + i * 256) * 4;
            const uint32_t* src = (off < 2048)
                ? Bmat + (size_t)c * 2048 + off
                : Bmat + (size_t)(8 + c) * 2048 + (off - 2048);
            cp16(dstb + (uint32_t)off * 4u, src);
        }
        cp_commit();
    };

    uint2 aU[2];
    auto load_a = [&](int kb) {
#pragma unroll
        for (int i = 0; i < 2; i++) {
            int f = tid + i * 256, row = f >> 3, kq = f & 7;
            if (POS) {
                float d0 = diff_s[row * 4], d1 = diff_s[row * 4 + 1], d2 = diff_s[row * 4 + 2];
                float t[4];
#pragma unroll
                for (int j = 0; j < 4; j++) {
                    int k = kb + kq * 4 + j;
                    float h = fmaf(d0, w1f_s[k * 3],
                              fmaf(d1, w1f_s[k * 3 + 1],
                              fmaf(d2, w1f_s[k * 3 + 2], b1f_s[k])));
                    t[j] = fmaxf(h, 0.f);
                }
                aU[i].x = f16pk(t[0], t[1]);
                aU[i].y = f16pk(t[2], t[3]);
            } else {
                float4 v = *(const float4*)&nf[(size_t)(rowBase + row) * 256 + kb + kq * 4];
                aU[i].x = f16pk(v.x, v.y);
                aU[i].y = f16pk(v.z, v.w);
            }
        }
    };
    auto sts_a = [&](int stage) {
        uint32_t* dst = sm + FS_ASTG + stage * 1024;
#pragma unroll
        for (int i = 0; i < 2; i++) {
            int f = tid + i * 256, row = f >> 3, kq = f & 7;
            dst[pkidx(row, 2 * kq)]     = aU[i].x;
            dst[pkidx(row, 2 * kq + 1)] = aU[i].y;
        }
    };

    cp_b(0, 0);
    cp_b(1, 1);
    load_a(0);
    sts_a(0);
    cp_wait<0>();
    __syncthreads();

    int lane = tid & 31, w = tid >> 5;
    int la3 = lane & 3, lg = lane >> 2;
    int axor = 4 * (la3 ^ (lg & 3));
    const int aOff = lg * 16 + axor;
    const int bOff = (w * 32 + lg) * 16 + axor;

    float acc[4][4][4];
#pragma unroll
    for (int mt = 0; mt < 4; mt++)
#pragma unroll
        for (int nt = 0; nt < 4; nt++)
#pragma unroll
            for (int r = 0; r < 4; r++) acc[mt][nt][r] = 0.f;

    for (int c = 0; c < 8; c++) {
        int st = c & 1;
        const uint32_t* As = sm + FS_ASTG + st * 1024;
        const uint32_t* Bs = sm + FS_BSTG + st * 4096;

        uint4 Vb[4];
#pragma unroll
        for (int nt = 0; nt < 4; nt++)
            Vb[nt] = *(const uint4*)&Bs[bOff + nt * 128];
#pragma unroll
        for (int mt = 0; mt < 2; mt++) {
            uint4 U0 = *(const uint4*)&As[aOff + mt * 256];
            uint4 U1 = *(const uint4*)&As[aOff + mt * 256 + 128];
            uint32_t a0[4] = {U0.x, U1.x, U0.y, U1.y};
            uint32_t a1[4] = {U0.z, U1.z, U0.w, U1.w};
#pragma unroll
            for (int nt = 0; nt < 4; nt++)
                mma_f16(acc[mt][nt], a0, Vb[nt].x, Vb[nt].y);
#pragma unroll
            for (int nt = 0; nt < 4; nt++)
                mma_f16(acc[mt][nt], a1, Vb[nt].z, Vb[nt].w);
        }
        if (c < 7) load_a((c + 1) * 32);
#pragma unroll
        for (int mt = 2; mt < 4; mt++) {
            uint4 U0 = *(const uint4*)&As[aOff + mt * 256];
            uint4 U1 = *(const uint4*)&As[aOff + mt * 256 + 128];
            uint32_t a0[4] = {U0.x, U1.x, U0.y, U1.y};
            uint32_t a1[4] = {U0.z, U1.z, U0.w, U1.w};
#pragma unroll
            for (int nt = 0; nt < 4; nt++)
                mma_f16(acc[mt][nt], a0, Vb[nt].x, Vb[nt].y);
#pragma unroll
            for (int nt = 0; nt < 4; nt++)
                mma_f16(acc[mt][nt], a1, Vb[nt].z, Vb[nt].w);
        }
        if (c < 7) sts_a(st ^ 1);
        cp_wait<0>();
        __syncthreads();
        if (c + 2 < 8) cp_b(st, c + 2);
    }

    // ---- epilogue ----
    float csum[8], csq[8];
#pragma unroll
    for (int j = 0; j < 8; j++) { csum[j] = 0.f; csq[j] = 0.f; }

#pragma unroll
    for (int mt = 0; mt < 4; mt++) {
        int row0 = mt * 16 + lg;
#pragma unroll
        for (int nt = 0; nt < 4; nt++) {
            int col = w * 32 + nt * 8 + 2 * la3;
            float b0 = bias_s[col], b1 = bias_s[col + 1];
            int vi0 = row0 * 132 + (col >> 1);
            int vi1 = (row0 + 8) * 132 + (col >> 1);
            float a0 = acc[mt][nt][0] + b0, a1 = acc[mt][nt][1] + b1;
            float a2 = acc[mt][nt][2] + b0, a3 = acc[mt][nt][3] + b1;
            if (EPI == 0) {
                float2 qv = upk(sm[FS_Q + mt * 128 + (col >> 1)]);
                sm[FS_VA + vi0] = f16pk(qv.x - a0, qv.y - a1);
                sm[FS_VA + vi1] = f16pk(qv.x - a2, qv.y - a3);
            } else if (EPI == 1) {
                float2 u0 = upk(sm[FS_VA + vi0]), u1 = upk(sm[FS_VA + vi1]);
                sm[FS_VA + vi0] = f16pk(a0 * u0.x, a1 * u0.y);
                sm[FS_VA + vi1] = f16pk(a2 * u1.x, a3 * u1.y);
            } else if (EPI == 2) {
                float2 u0 = upk(sm[FS_VA + vi0]), u1 = upk(sm[FS_VA + vi1]);
                sm[FS_VA + vi0] = f16pk(u0.x + a0, u0.y + a1);
                sm[FS_VA + vi1] = f16pk(u1.x + a2, u1.y + a3);
            } else {
                const float* om = (const float*)(sm + FS_OM);
                float o0 = om[row0 * 36 + (col >> 3)];
                float o1 = om[(row0 + 8) * 36 + (col >> 3)];
                float w00 = o0 * a0, w01 = o0 * a1;
                float w10 = o1 * a2, w11 = o1 * a3;
                g_we16[(size_t)(rowBase + row0) * 128 + (col >> 1)]     = f16pk(w00, w01);
                g_we16[(size_t)(rowBase + row0 + 8) * 128 + (col >> 1)] = f16pk(w10, w11);
                csum[nt * 2]     += w00 + w10;
                csum[nt * 2 + 1] += w01 + w11;
                csq[nt * 2]      += w00 * w00 + w10 * w10;
                csq[nt * 2 + 1]  += w01 * w01 + w11 * w11;
            }
        }
    }
    if (EPI == 3) {
        // deterministic reduce over lg (lane bits 2..4); each warp owns
        // 32 distinct columns -> lane-group 0 writes partials directly.
#pragma unroll
        for (int j = 0; j < 8; j++) {
#pragma unroll
            for (int off = 4; off < 32; off <<= 1) {
                csum[j] += __shfl_xor_sync(0xffffffffu, csum[j], off);
                csq[j]  += __shfl_xor_sync(0xffffffffu, csq[j],  off);
            }
        }
        if (lg == 0) {
#pragma unroll
            for (int u = 0; u < 8; u++) {
                int nt = u >> 1, uu = u & 1;
                int col = w * 32 + nt * 8 + 2 * la3 + uu;
                g_part2[(size_t)blockId * 512 + col]       = csum[u];
                g_part2[(size_t)blockId * 512 + 256 + col] = csq[u];
            }
        }
        __syncthreads();
    } else {
        __syncthreads();
    }
}

__global__ void __launch_bounds__(256, 2)
fused_kernel(const float* __restrict__ nf, const float* __restrict__ pts,
             const float* __restrict__ nbr,
             const float* __restrict__ k_b, const float* __restrict__ dm_b2,
             const float* __restrict__ db_b2, const float* __restrict__ v_b,
             const float* __restrict__ convw) {
    extern __shared__ uint32_t sm[];
    float* fx = (float*)(sm + FS_FX);
    int tid = threadIdx.x;
    int rowBase = blockIdx.x * 64;

    fx[FXF_KB + tid]  = k_b[tid];
    fx[FXF_DMB + tid] = dm_b2[tid];
    fx[FXF_DBB + tid] = db_b2[tid];
    fx[FXF_VB + tid]  = v_b[tid];
    fx[FXF_B1F + tid]       = g_b1f[0][tid];
    fx[FXF_B1F + 256 + tid] = g_b1f[1][tid];
    for (int i = tid; i < 1024; i += 256) fx[FXF_CW + i] = convw[i];
    for (int i = tid; i < 768; i += 256) {
        fx[FXF_W1F + i]       = g_w1f[0][i];
        fx[FXF_W1F + 768 + i] = g_w1f[1][i];
    }
    if (tid < 64) {
        int r = rowBase + tid, bn = r >> 4;
        fx[FXF_DIFF + tid * 4 + 0] = pts[bn * 3 + 0] - nbr[(size_t)r * 3 + 0];
        fx[FXF_DIFF + tid * 4 + 1] = pts[bn * 3 + 1] - nbr[(size_t)r * 3 + 1];
        fx[FXF_DIFF + tid * 4 + 2] = pts[bn * 3 + 2] - nbr[(size_t)r * 3 + 2];
    }
    {
        int bnb = rowBase >> 4;
        for (int i = tid; i < 512; i += 256) sm[FS_Q + i] = g_q16[bnb * 128 + i];
    }
    __syncthreads();

    const uint32_t* BK  = g_Bpk + 1 * 32768;
    const uint32_t* BV  = g_Bpk + 2 * 32768;
    const uint32_t* BDM = g_Bpk + 3 * 32768;
    const uint32_t* BDB = g_Bpk + 4 * 32768;
    const float* diff_s = fx + FXF_DIFF;

    run_subpass<0, false>(sm, tid, rowBase, nf, BK,  fx + FXF_KB,  nullptr, nullptr, diff_s, blockIdx.x);
    run_subpass<1, true >(sm, tid, rowBase, nf, BDM, fx + FXF_DMB, fx + FXF_W1F,       fx + FXF_B1F,       diff_s, blockIdx.x);
    run_subpass<2, true >(sm, tid, rowBase, nf, BDB, fx + FXF_DBB, fx + FXF_W1F + 768, fx + FXF_B1F + 256, diff_s, blockIdx.x);

    // ---- attention: va -> omega ----
    __syncthreads();
    {
        int l = tid & 31, w = tid >> 5;
        float cwr[32];
#pragma unroll
        for (int i = 0; i < 32; i++)
            cwr[i] = fx[FXF_CW + (l >> 2) * 128 + (l & 3) * 32 + i];
        float* om = (float*)(sm + FS_OM);
        int gb = (l >> 2) * 16;
        for (int it = 0; it < 8; it++) {
            int row = w * 8 + it;
            const uint32_t* vrow = sm + FS_VA + row * 132;
            float acc = 0.f;
#pragma unroll
            for (int t = 0; t < 16; t += 2) {
                uint2 u = *(const uint2*)&vrow[gb + t];
                float2 f0 = upk(u.x), f1 = upk(u.y);
                int i0 = t * 2;
                acc = fmaf(f0.x, cwr[i0], acc);
                acc = fmaf(f0.y, cwr[i0 + 1], acc);
                acc = fmaf(f1.x, cwr[i0 + 2], acc);
                acc = fmaf(f1.y, cwr[i0 + 3], acc);
            }
            float mx = acc;
#pragma unroll
            for (int off = 16; off > 0; off >>= 1)
                mx = fmaxf(mx, __shfl_xor_sync(0xffffffffu, mx, off));
            float e = expf(acc - mx);
            float ss = e;
#pragma unroll
            for (int off = 16; off > 0; off >>= 1)
                ss += __shfl_xor_sync(0xffffffffu, ss, off);
            om[row * 36 + l] = e / ss;
        }
    }
    __syncthreads();

    run_subpass<3, false>(sm, tid, rowBase, nf, BV, fx + FXF_VB, nullptr, nullptr, diff_s, blockIdx.x);
}

// --------------------------- BN2 reductions --------------------------------
__global__ void reduce_part2() {          // grid 64, block 256
    int b = blockIdx.x, tid = threadIdx.x;
    for (int c = tid; c < 512; c += 256) {
        float s = 0.f;
#pragma unroll 8
        for (int i = 0; i < 64; i++)
            s += g_part2[(size_t)(b * 64 + i) * 512 + c];
        g_part2r[b * 512 + c] = s;
    }
}

__global__ void finalize2_kernel(const float* __restrict__ bn_g,
                                 const float* __restrict__ bn_b) {
    int c = threadIdx.x;
    float s = 0.f, sq = 0.f;
    for (int b = 0; b < 64; b++) {
        s  += g_part2r[b * 512 + c];
        sq += g_part2r[b * 512 + 256 + c];
    }
    float mean = s / (float)R_;
    float var = sq / (float)R_ - mean * mean;
    float sc = bn_g[c] * rsqrtf(var + EPSV);
    g_s2[c] = sc;
    g_t2[c] = bn_b[c] - mean * sc;
}

// ------------------------------- launch -------------------------------------
extern "C" void kernel_launch(void* const* d_in, const int* in_sizes, int n_in,
                              void* d_out, int out_size) {
    const float* pts   = (const float*)d_in[0];
    const float* pf    = (const float*)d_in[1];
    const float* nbr   = (const float*)d_in[2];
    const float* nf    = (const float*)d_in[3];
    const float* dm_w1 = (const float*)d_in[4];
    const float* dm_b1 = (const float*)d_in[5];
    const float* dm_w2 = (const float*)d_in[6];
    const float* dm_b2 = (const float*)d_in[7];
    const float* dm_g  = (const float*)d_in[8];
    const float* dm_be = (const float*)d_in[9];
    const float* db_w1 = (const float*)d_in[10];
    const float* db_b1 = (const float*)d_in[11];
    const float* db_w2 = (const float*)d_in[12];
    const float* db_b2 = (const float*)d_in[13];
    const float* db_g  = (const float*)d_in[14];
    const float* db_be = (const float*)d_in[15];
    const float* q_w   = (const float*)d_in[16];
    const float* q_b   = (const float*)d_in[17];
    const float* k_w   = (const float*)d_in[18];
    const float* k_b   = (const float*)d_in[19];
    const float* v_w   = (const float*)d_in[20];
    const float* v_b   = (const float*)d_in[21];
    const float* convw = (const float*)d_in[22];
    const float* bn_g  = (const float*)d_in[23];
    const float* bn_b  = (const float*)d_in[24];
    const float* lin_w = (const float*)d_in[25];
    const float* lin_b = (const float*)d_in[26];
    float* out = (float*)d_out;

    void *p_q, *p_we, *p_bpk;
    cudaGetSymbolAddress(&p_q,   g_q16);
    cudaGetSymbolAddress(&p_we,  g_we16);
    cudaGetSymbolAddress(&p_bpk, g_Bpk);
    const uint32_t* Bpk = (const uint32_t*)p_bpk;

    cudaFuncSetAttribute(gemm_mma<AMODE_DIRECT, true>,
                         cudaFuncAttributeMaxDynamicSharedMemorySize, G_DYN_SMEM);
    cudaFuncSetAttribute(gemm_mma<AMODE_F16BN, false>,
                         cudaFuncAttributeMaxDynamicSharedMemorySize, G_DYN_SMEM);
    cudaFuncSetAttribute(fused_kernel,
                         cudaFuncAttributeMaxDynamicSharedMemorySize, FUSED_SMEM);

    prep_weights<<<dim3(8, 2, 6), 256>>>(q_w, k_w, v_w, dm_w2, db_w2, lin_w);
    diffstats_kernel<<<STAT_BLOCKS, 256>>>(pts, nbr);
    fold_kernel<<<1, 256>>>(dm_w1, dm_b1, dm_g, dm_be, db_w1, db_b1, db_g, db_be);

    gemm_mma<AMODE_DIRECT, true><<<BNp / 64, 256, G_DYN_SMEM>>>(
        pf, Bpk + 0 * 32768, q_b, p_q);

    fused_kernel<<<NTILES, 256, FUSED_SMEM>>>(nf, pts, nbr,
                                              k_b, dm_b2, db_b2, v_b, convw);

    reduce_part2<<<64, 256>>>();
    finalize2_kernel<<<1, 256>>>(bn_g, bn_b);

    gemm_mma<AMODE_F16BN, false><<<R_ / 64, 256, G_DYN_SMEM>>>(
        p_we, Bpk + 5 * 32768, lin_b, out);
}

// round 11
// speedup vs baseline: 2.6746x; 1.0069x over previous
#include <cuda_runtime.h>
#include <cstdint>

// ---------------------------------------------------------------------------
// GroupVectorAttention — fused produce+attention (64-row tiles, occ 2) +
// PERSISTENT weight-stationary final GEMM: B resident in smem (loaded once
// per CTA), 128-row tiles, 2 syncs/tile, 128 back-to-back HMMAs per warp.
// ---------------------------------------------------------------------------

#define EPSV 1e-5f

static constexpr int Bb = 4, Nn = 4096, Mm = 16, Cd = 256;
static constexpr int R_ = Bb * Nn * Mm;       // 262144
static constexpr int BNp = Bb * Nn;           // 16384
static constexpr int STAT_BLOCKS = 256;
static constexpr int NTILES = R_ / 64;        // 4096 fused tiles
static constexpr int PGRID = 148;             // persistent final-GEMM CTAs

// ---- standalone GEMM smem layout (u32 units): A 2x1024 | B 2x4096 | fx ----
static constexpr int G_SOFF_B  = 2048;
static constexpr int G_SOFF_FX = 10240;
static constexpr int G_FX_BIAS = 0, G_FX_S2 = 256, G_FX_T2 = 512;
static constexpr int G_DYN_SMEM = (10240 + 768) * 4;     // 44032 B

// ---- persistent final GEMM smem (u32): B 32768 | A 16384 | fx 768 ----
static constexpr int P_SOFF_A  = 32768;
static constexpr int P_SOFF_FX = 49152;
static constexpr int P_DYN_SMEM = (49152 + 768) * 4;     // 199680 B

// ---- fused kernel smem layout (u32 units), 64-row tile ----
static constexpr int FS_ASTG = 0;                 // 2*1024
static constexpr int FS_BSTG = 2048;              // 2*4096
static constexpr int FS_VA   = 10240;             // 64*132
static constexpr int FS_Q    = 18688;             // 512
static constexpr int FS_OM   = 19200;             // 64*36 fp32
static constexpr int FS_FX   = 21504;             // floats below (4352)
static constexpr int FXF_KB = 0, FXF_DMB = 256, FXF_DBB = 512, FXF_VB = 768,
                     FXF_CW = 1024, FXF_W1F = 2048, FXF_B1F = 3584,
                     FXF_DIFF = 4096;             // 256
static constexpr int FUSED_SMEM = (21504 + 4352) * 4;    // 103424 B

// ------------------------- device scratch (static) -------------------------
__device__ float g_part1[STAT_BLOCKS * 12];
__device__ float g_w1f[2][Cd * 3];
__device__ float g_b1f[2][Cd];
__device__ uint32_t g_q16[BNp * 128];
__device__ uint32_t g_we16[(size_t)R_ * 128];
__device__ float g_part2[(size_t)NTILES * 512];
__device__ float g_part2r[64 * 512];
__device__ float g_s2[Cd], g_t2[Cd];
// packed fp16 weight images: [mat(6)][nb(2)][chunk(8)][2048 u32]
__device__ uint32_t g_Bpk[6 * 2 * 8 * 2048];

// ----------------------------- PTX helpers ---------------------------------
__device__ __forceinline__ uint32_t smem_u32(const void* p) {
    uint32_t a;
    asm("{ .reg .u64 t; cvta.to.shared.u64 t, %1; cvt.u32.u64 %0, t; }"
        : "=r"(a) : "l"(p));
    return a;
}
__device__ __forceinline__ void cp16(uint32_t dst, const void* src) {
    asm volatile("cp.async.cg.shared.global [%0], [%1], 16;"
                 :: "r"(dst), "l"(src) : "memory");
}
__device__ __forceinline__ void cp_commit() {
    asm volatile("cp.async.commit_group;" ::: "memory");
}
template <int N>
__device__ __forceinline__ void cp_wait() {
    asm volatile("cp.async.wait_group %0;" :: "n"(N) : "memory");
}
__device__ __forceinline__ void mma_f16(float* c, const uint32_t* a,
                                        uint32_t b0, uint32_t b1) {
    asm volatile("mma.sync.aligned.m16n8k16.row.col.f32.f16.f16.f32 "
                 "{%0,%1,%2,%3}, {%4,%5,%6,%7}, {%8,%9}, {%0,%1,%2,%3};"
                 : "+f"(c[0]), "+f"(c[1]), "+f"(c[2]), "+f"(c[3])
                 : "r"(a[0]), "r"(a[1]), "r"(a[2]), "r"(a[3]),
                   "r"(b0), "r"(b1));
}
__device__ __forceinline__ uint32_t f16pk(float lo, float hi) {
    uint32_t r;
    asm("cvt.rn.f16x2.f32 %0, %1, %2;" : "=r"(r) : "f"(hi), "f"(lo));
    return r;
}
__device__ __forceinline__ float2 upk(uint32_t u) {
    float2 f;
    asm("{ .reg .b16 lo, hi; mov.b32 {lo, hi}, %2; "
        "cvt.f32.f16 %0, lo; cvt.f32.f16 %1, hi; }"
        : "=f"(f.x), "=f"(f.y) : "r"(u));
    return f;
}
__device__ __forceinline__ int pkidx(int n, int p) {
    return n * 16 + 4 * ((p & 3) ^ (n & 3)) + 2 * (p >> 3) + ((p >> 2) & 1);
}

// ------------------------------- K1: stats --------------------------------
__global__ void diffstats_kernel(const float* __restrict__ pts,
                                 const float* __restrict__ nbr) {
    float s[12];
#pragma unroll
    for (int i = 0; i < 12; i++) s[i] = 0.f;
    int tid = threadIdx.x;
    for (int r = blockIdx.x * blockDim.x + tid; r < R_; r += gridDim.x * blockDim.x) {
        int bn = r >> 4;
        float d[3];
#pragma unroll
        for (int j = 0; j < 3; j++) d[j] = pts[bn * 3 + j] - nbr[(size_t)r * 3 + j];
#pragma unroll
        for (int j = 0; j < 3; j++) s[j] += d[j];
#pragma unroll
        for (int j = 0; j < 3; j++)
#pragma unroll
            for (int k = 0; k < 3; k++) s[3 + j * 3 + k] += d[j] * d[k];
    }
    __shared__ float red[256];
    for (int comp = 0; comp < 12; comp++) {
        red[tid] = s[comp];
        __syncthreads();
        for (int off = 128; off > 0; off >>= 1) {
            if (tid < off) red[tid] += red[tid + off];
            __syncthreads();
        }
        if (tid == 0) g_part1[blockIdx.x * 12 + comp] = red[0];
        __syncthreads();
    }
}

// ------------------------------ K2: BN1 fold -------------------------------
__global__ void fold_kernel(const float* __restrict__ dm_w1, const float* __restrict__ dm_b1,
                            const float* __restrict__ dm_g,  const float* __restrict__ dm_be,
                            const float* __restrict__ db_w1, const float* __restrict__ db_b1,
                            const float* __restrict__ db_g,  const float* __restrict__ db_be) {
    __shared__ float st[12];
    __shared__ float mu[3], cov[9];
    int tid = threadIdx.x;
    if (tid < 12) {
        float a = 0.f;
        for (int b = 0; b < STAT_BLOCKS; b++) a += g_part1[b * 12 + tid];
        st[tid] = a / (float)R_;
    }
    __syncthreads();
    if (tid < 3) mu[tid] = st[tid];
    if (tid < 9) {
        int j = tid / 3, k = tid % 3;
        cov[tid] = st[3 + tid] - st[j] * st[k];
    }
    __syncthreads();
    int c = tid;
    for (int which = 0; which < 2; which++) {
        const float* w1 = which ? db_w1 : dm_w1;
        const float* b1 = which ? db_b1 : dm_b1;
        const float* gg = which ? db_g  : dm_g;
        const float* be = which ? db_be : dm_be;
        float w0 = w1[c * 3], w1v = w1[c * 3 + 1], w2v = w1[c * 3 + 2];
        float var = w0 * w0 * cov[0] + w1v * w1v * cov[4] + w2v * w2v * cov[8]
                  + 2.f * (w0 * w1v * cov[1] + w0 * w2v * cov[2] + w1v * w2v * cov[5]);
        float mdot = w0 * mu[0] + w1v * mu[1] + w2v * mu[2];
        float m = mdot + b1[c];
        float s = gg[c] * rsqrtf(var + EPSV);
        g_w1f[which][c * 3]     = w0 * s;
        g_w1f[which][c * 3 + 1] = w1v * s;
        g_w1f[which][c * 3 + 2] = w2v * s;
        g_b1f[which][c] = be[c] + s * (b1[c] - m);
    }
}

// ----------------------- weight prep: fp32 -> packed fp16 -------------------
__global__ void prep_weights(const float* __restrict__ q_w, const float* __restrict__ k_w,
                             const float* __restrict__ v_w, const float* __restrict__ dm_w2,
                             const float* __restrict__ db_w2, const float* __restrict__ lin_w) {
    int c = blockIdx.x, nb = blockIdx.y, mat = blockIdx.z;
    const float* W = mat == 0 ? q_w : mat == 1 ? k_w : mat == 2 ? v_w :
                     mat == 3 ? dm_w2 : mat == 4 ? db_w2 : lin_w;
    uint32_t* dst = g_Bpk + (((size_t)mat * 2 + nb) * 8 + c) * 2048;
    int tid = threadIdx.x;
    int n = tid >> 1, q = tid & 1;
    const float* src = W + (size_t)(nb * 128 + n) * 256 + c * 32 + q * 16;
    float cc[16];
#pragma unroll
    for (int j = 0; j < 16; j += 4) {
        float4 v = *(const float4*)&src[j];
        cc[j] = v.x; cc[j + 1] = v.y; cc[j + 2] = v.z; cc[j + 3] = v.w;
    }
#pragma unroll
    for (int t = 0; t < 4; t++)
#pragma unroll
        for (int u = 0; u < 2; u++) {
            int p = 8 * q + t + 4 * u;
            dst[pkidx(n, p)] = f16pk(cc[2 * t + 8 * u], cc[2 * t + 8 * u + 1]);
        }
}

// ----------------- standalone GEMM (q): 64-row tiles, full N ----------------
__global__ void __launch_bounds__(256, 2)
gemm_q(const float* __restrict__ A, const uint32_t* __restrict__ Bpk,
       const float* __restrict__ bias, uint32_t* __restrict__ O16) {
    extern __shared__ uint32_t sm[];
    float* bias_s = (float*)(sm + G_SOFF_FX);

    int tid = threadIdx.x;
    int rowBase = blockIdx.x * 64;
    bias_s[tid] = bias[tid];
    __syncthreads();

    uint32_t smemB_addr = smem_u32(sm + G_SOFF_B);
    auto cp_b = [&](int stage, int c) {
        uint32_t dstb = smemB_addr + (uint32_t)stage * 16384u;
#pragma unroll
        for (int i = 0; i < 4; i++) {
            int off = (tid + i * 256) * 4;
            const uint32_t* src = (off < 2048)
                ? Bpk + (size_t)c * 2048 + off
                : Bpk + (size_t)(8 + c) * 2048 + (off - 2048);
            cp16(dstb + (uint32_t)off * 4u, src);
        }
        cp_commit();
    };
    uint2 aU[2];
    auto load_a = [&](int kb) {
#pragma unroll
        for (int i = 0; i < 2; i++) {
            int f = tid + i * 256, row = f >> 3, kq = f & 7;
            float4 v = *(const float4*)&A[(size_t)(rowBase + row) * 256 + kb + kq * 4];
            aU[i].x = f16pk(v.x, v.y);
            aU[i].y = f16pk(v.z, v.w);
        }
    };
    auto sts_a = [&](int stage) {
        uint32_t* dst = sm + stage * 1024;
#pragma unroll
        for (int i = 0; i < 2; i++) {
            int f = tid + i * 256, row = f >> 3, kq = f & 7;
            dst[pkidx(row, 2 * kq)]     = aU[i].x;
            dst[pkidx(row, 2 * kq + 1)] = aU[i].y;
        }
    };

    cp_b(0, 0);
    cp_b(1, 1);
    load_a(0);
    sts_a(0);
    cp_wait<0>();
    __syncthreads();

    int lane = tid & 31, w = tid >> 5;
    int la3 = lane & 3, lg = lane >> 2;
    int axor = 4 * (la3 ^ (lg & 3));
    const int aOff = lg * 16 + axor;
    const int bOff = (w * 32 + lg) * 16 + axor;

    float acc[4][4][4];
#pragma unroll
    for (int mt = 0; mt < 4; mt++)
#pragma unroll
        for (int nt = 0; nt < 4; nt++)
#pragma unroll
            for (int r = 0; r < 4; r++) acc[mt][nt][r] = 0.f;

    for (int c = 0; c < 8; c++) {
        int st = c & 1;
        const uint32_t* As = sm + st * 1024;
        const uint32_t* Bs = sm + G_SOFF_B + st * 4096;

        uint4 Vb[4];
#pragma unroll
        for (int nt = 0; nt < 4; nt++)
            Vb[nt] = *(const uint4*)&Bs[bOff + nt * 128];
#pragma unroll
        for (int mt = 0; mt < 2; mt++) {
            uint4 U0 = *(const uint4*)&As[aOff + mt * 256];
            uint4 U1 = *(const uint4*)&As[aOff + mt * 256 + 128];
            uint32_t a0[4] = {U0.x, U1.x, U0.y, U1.y};
            uint32_t a1[4] = {U0.z, U1.z, U0.w, U1.w};
#pragma unroll
            for (int nt = 0; nt < 4; nt++)
                mma_f16(acc[mt][nt], a0, Vb[nt].x, Vb[nt].y);
#pragma unroll
            for (int nt = 0; nt < 4; nt++)
                mma_f16(acc[mt][nt], a1, Vb[nt].z, Vb[nt].w);
        }
        if (c < 7) load_a((c + 1) * 32);
#pragma unroll
        for (int mt = 2; mt < 4; mt++) {
            uint4 U0 = *(const uint4*)&As[aOff + mt * 256];
            uint4 U1 = *(const uint4*)&As[aOff + mt * 256 + 128];
            uint32_t a0[4] = {U0.x, U1.x, U0.y, U1.y};
            uint32_t a1[4] = {U0.z, U1.z, U0.w, U1.w};
#pragma unroll
            for (int nt = 0; nt < 4; nt++)
                mma_f16(acc[mt][nt], a0, Vb[nt].x, Vb[nt].y);
#pragma unroll
            for (int nt = 0; nt < 4; nt++)
                mma_f16(acc[mt][nt], a1, Vb[nt].z, Vb[nt].w);
        }
        if (c < 7) sts_a(st ^ 1);
        cp_wait<0>();
        __syncthreads();
        if (c + 2 < 8) cp_b(st, c + 2);
    }

#pragma unroll
    for (int mt = 0; mt < 4; mt++) {
        int row0 = rowBase + mt * 16 + lg;
#pragma unroll
        for (int nt = 0; nt < 4; nt++) {
            int col = w * 32 + nt * 8 + 2 * la3;
            float b0 = bias_s[col], b1 = bias_s[col + 1];
            O16[(size_t)row0 * 128 + (col >> 1)] =
                f16pk(acc[mt][nt][0] + b0, acc[mt][nt][1] + b1);
            O16[(size_t)(row0 + 8) * 128 + (col >> 1)] =
                f16pk(acc[mt][nt][2] + b0, acc[mt][nt][3] + b1);
        }
    }
}

// --------------- persistent weight-stationary FINAL GEMM --------------------
// 148 CTAs x 512 threads, B (lin_w fp16, 128KB) resident; 128-row tiles,
// A = relu(we*s2+t2) built per tile; 2 syncs/tile; fp32 output.
__global__ void __launch_bounds__(512, 1)
gemm_final(const uint32_t* __restrict__ A16, const uint32_t* __restrict__ Bpk,
           const float* __restrict__ bias, float* __restrict__ Out) {
    extern __shared__ uint32_t sm[];
    float* fx = (float*)(sm + P_SOFF_FX);
    float* bias_s = fx;
    float* s2_s   = fx + 256;
    float* t2_s   = fx + 512;
    int tid = threadIdx.x;
    if (tid < 256) {
        bias_s[tid] = bias[tid];
        s2_s[tid]   = g_s2[tid];
        t2_s[tid]   = g_t2[tid];
    }
    // load B once: smem [chunk(8)][4096] = [nb0 2048 | nb1 2048]
    uint32_t smemB = smem_u32(sm);
#pragma unroll
    for (int i = 0; i < 16; i++) {
        int o = (tid + i * 512) * 4;
        int c = o >> 12, within = o & 4095;
        int nb = within >> 11, idx = within & 2047;
        cp16(smemB + (uint32_t)o * 4u,
             Bpk + (size_t)(nb * 8 + c) * 2048 + idx);
    }
    cp_commit();
    cp_wait<0>();
    __syncthreads();

    int lane = tid & 31, w = tid >> 5;
    int wm = w & 1, wn = w >> 1;
    int la3 = lane & 3, lg = lane >> 2;
    int axor = 4 * (la3 ^ (lg & 3));
    const int bOff = (wn * 32 + lg) * 16 + axor;
    const int aOff = (wm * 64 + lg) * 16 + axor;

    for (int t = blockIdx.x; t < R_ / 128; t += gridDim.x) {
        int rowBase = t * 128;
        // ---- A phase: we16 -> BN+ReLU -> fp16 smem (8 chunk blocks) ----
#pragma unroll
        for (int i = 0; i < 16; i++) {
            int f = tid + i * 512;
            int c = f >> 10, r = f & 1023, row = r >> 3, kq = r & 7;
            uint2 u = *(const uint2*)&A16[(size_t)(rowBase + row) * 128 + c * 16 + kq * 2];
            float2 f0 = upk(u.x), f1 = upk(u.y);
            int k = c * 32 + kq * 4;
            float x0 = fmaxf(fmaf(f0.x, s2_s[k],     t2_s[k]),     0.f);
            float x1 = fmaxf(fmaf(f0.y, s2_s[k + 1], t2_s[k + 1]), 0.f);
            float x2 = fmaxf(fmaf(f1.x, s2_s[k + 2], t2_s[k + 2]), 0.f);
            float x3 = fmaxf(fmaf(f1.y, s2_s[k + 3], t2_s[k + 3]), 0.f);
            uint32_t* dst = sm + P_SOFF_A + c * 2048;
            dst[pkidx(row, 2 * kq)]     = f16pk(x0, x1);
            dst[pkidx(row, 2 * kq + 1)] = f16pk(x2, x3);
        }
        __syncthreads();

        float acc[4][4][4];
#pragma unroll
        for (int mt = 0; mt < 4; mt++)
#pragma unroll
            for (int nt = 0; nt < 4; nt++)
#pragma unroll
                for (int r = 0; r < 4; r++) acc[mt][nt][r] = 0.f;

#pragma unroll
        for (int c = 0; c < 8; c++) {
            const uint32_t* As = sm + P_SOFF_A + c * 2048;
            const uint32_t* Bs = sm + c * 4096;
            uint4 Vb[4];
#pragma unroll
            for (int nt = 0; nt < 4; nt++)
                Vb[nt] = *(const uint4*)&Bs[bOff + nt * 128];
#pragma unroll
            for (int mt = 0; mt < 4; mt++) {
                uint4 U0 = *(const uint4*)&As[aOff + mt * 256];
                uint4 U1 = *(const uint4*)&As[aOff + mt * 256 + 128];
                uint32_t a0[4] = {U0.x, U1.x, U0.y, U1.y};
                uint32_t a1[4] = {U0.z, U1.z, U0.w, U1.w};
#pragma unroll
                for (int nt = 0; nt < 4; nt++)
                    mma_f16(acc[mt][nt], a0, Vb[nt].x, Vb[nt].y);
#pragma unroll
                for (int nt = 0; nt < 4; nt++)
                    mma_f16(acc[mt][nt], a1, Vb[nt].z, Vb[nt].w);
            }
        }
        __syncthreads();

#pragma unroll
        for (int mt = 0; mt < 4; mt++) {
            int row0 = rowBase + wm * 64 + mt * 16 + lg;
#pragma unroll
            for (int nt = 0; nt < 4; nt++) {
                int col = wn * 32 + nt * 8 + 2 * la3;
                float b0 = bias_s[col], b1 = bias_s[col + 1];
                *(float2*)&Out[(size_t)row0 * 256 + col] =
                    make_float2(acc[mt][nt][0] + b0, acc[mt][nt][1] + b1);
                *(float2*)&Out[(size_t)(row0 + 8) * 256 + col] =
                    make_float2(acc[mt][nt][2] + b0, acc[mt][nt][3] + b1);
            }
        }
    }
}

// ----------------------- fused produce+attention kernel ---------------------
// 256 threads, 8 col-warps, 64-row tile, occupancy 2.
// EPI: 0 = qk = q-k ; 1 = va = dm*qk ; 2 = va += db ; 3 = we = omega*v
template <int EPI, bool POS>
__device__ __noinline__ void run_subpass(
    uint32_t* sm, int tid, int rowBase,
    const float* __restrict__ nf,
    const uint32_t* __restrict__ Bmat,
    const float* bias_s, const float* w1f_s, const float* b1f_s,
    const float* diff_s, int blockId) {

    uint32_t smemB_addr = smem_u32(sm + FS_BSTG);
    auto cp_b = [&](int stage, int c) {
        uint32_t dstb = smemB_addr + (uint32_t)stage * 16384u;
#pragma unroll
        for (int i = 0; i < 4; i++) {
            int off = (tid + i * 256) * 4;
            const uint32_t* src = (off < 2048)
                ? Bmat + (size_t)c * 2048 + off
                : Bmat + (size_t)(8 + c) * 2048 + (off - 2048);
            cp16(dstb + (uint32_t)off * 4u, src);
        }
        cp_commit();
    };

    uint2 aU[2];
    auto load_a = [&](int kb) {
#pragma unroll
        for (int i = 0; i < 2; i++) {
            int f = tid + i * 256, row = f >> 3, kq = f & 7;
            if (POS) {
                float d0 = diff_s[row * 4], d1 = diff_s[row * 4 + 1], d2 = diff_s[row * 4 + 2];
                float t[4];
#pragma unroll
                for (int j = 0; j < 4; j++) {
                    int k = kb + kq * 4 + j;
                    float h = fmaf(d0, w1f_s[k * 3],
                              fmaf(d1, w1f_s[k * 3 + 1],
                              fmaf(d2, w1f_s[k * 3 + 2], b1f_s[k])));
                    t[j] = fmaxf(h, 0.f);
                }
                aU[i].x = f16pk(t[0], t[1]);
                aU[i].y = f16pk(t[2], t[3]);
            } else {
                float4 v = *(const float4*)&nf[(size_t)(rowBase + row) * 256 + kb + kq * 4];
                aU[i].x = f16pk(v.x, v.y);
                aU[i].y = f16pk(v.z, v.w);
            }
        }
    };
    auto sts_a = [&](int stage) {
        uint32_t* dst = sm + FS_ASTG + stage * 1024;
#pragma unroll
        for (int i = 0; i < 2; i++) {
            int f = tid + i * 256, row = f >> 3, kq = f & 7;
            dst[pkidx(row, 2 * kq)]     = aU[i].x;
            dst[pkidx(row, 2 * kq + 1)] = aU[i].y;
        }
    };

    cp_b(0, 0);
    cp_b(1, 1);
    load_a(0);
    sts_a(0);
    cp_wait<0>();
    __syncthreads();

    int lane = tid & 31, w = tid >> 5;
    int la3 = lane & 3, lg = lane >> 2;
    int axor = 4 * (la3 ^ (lg & 3));
    const int aOff = lg * 16 + axor;
    const int bOff = (w * 32 + lg) * 16 + axor;

    float acc[4][4][4];
#pragma unroll
    for (int mt = 0; mt < 4; mt++)
#pragma unroll
        for (int nt = 0; nt < 4; nt++)
#pragma unroll
            for (int r = 0; r < 4; r++) acc[mt][nt][r] = 0.f;

    for (int c = 0; c < 8; c++) {
        int st = c & 1;
        const uint32_t* As = sm + FS_ASTG + st * 1024;
        const uint32_t* Bs = sm + FS_BSTG + st * 4096;

        uint4 Vb[4];
#pragma unroll
        for (int nt = 0; nt < 4; nt++)
            Vb[nt] = *(const uint4*)&Bs[bOff + nt * 128];
#pragma unroll
        for (int mt = 0; mt < 2; mt++) {
            uint4 U0 = *(const uint4*)&As[aOff + mt * 256];
            uint4 U1 = *(const uint4*)&As[aOff + mt * 256 + 128];
            uint32_t a0[4] = {U0.x, U1.x, U0.y, U1.y};
            uint32_t a1[4] = {U0.z, U1.z, U0.w, U1.w};
#pragma unroll
            for (int nt = 0; nt < 4; nt++)
                mma_f16(acc[mt][nt], a0, Vb[nt].x, Vb[nt].y);
#pragma unroll
            for (int nt = 0; nt < 4; nt++)
                mma_f16(acc[mt][nt], a1, Vb[nt].z, Vb[nt].w);
        }
        if (c < 7) load_a((c + 1) * 32);
#pragma unroll
        for (int mt = 2; mt < 4; mt++) {
            uint4 U0 = *(const uint4*)&As[aOff + mt * 256];
            uint4 U1 = *(const uint4*)&As[aOff + mt * 256 + 128];
            uint32_t a0[4] = {U0.x, U1.x, U0.y, U1.y};
            uint32_t a1[4] = {U0.z, U1.z, U0.w, U1.w};
#pragma unroll
            for (int nt = 0; nt < 4; nt++)
                mma_f16(acc[mt][nt], a0, Vb[nt].x, Vb[nt].y);
#pragma unroll
            for (int nt = 0; nt < 4; nt++)
                mma_f16(acc[mt][nt], a1, Vb[nt].z, Vb[nt].w);
        }
        if (c < 7) sts_a(st ^ 1);
        cp_wait<0>();
        __syncthreads();
        if (c + 2 < 8) cp_b(st, c + 2);
    }

    // ---- epilogue ----
    float csum[8], csq[8];
#pragma unroll
    for (int j = 0; j < 8; j++) { csum[j] = 0.f; csq[j] = 0.f; }

#pragma unroll
    for (int mt = 0; mt < 4; mt++) {
        int row0 = mt * 16 + lg;
#pragma unroll
        for (int nt = 0; nt < 4; nt++) {
            int col = w * 32 + nt * 8 + 2 * la3;
            float b0 = bias_s[col], b1 = bias_s[col + 1];
            int vi0 = row0 * 132 + (col >> 1);
            int vi1 = (row0 + 8) * 132 + (col >> 1);
            float a0 = acc[mt][nt][0] + b0, a1 = acc[mt][nt][1] + b1;
            float a2 = acc[mt][nt][2] + b0, a3 = acc[mt][nt][3] + b1;
            if (EPI == 0) {
                float2 qv = upk(sm[FS_Q + mt * 128 + (col >> 1)]);
                sm[FS_VA + vi0] = f16pk(qv.x - a0, qv.y - a1);
                sm[FS_VA + vi1] = f16pk(qv.x - a2, qv.y - a3);
            } else if (EPI == 1) {
                float2 u0 = upk(sm[FS_VA + vi0]), u1 = upk(sm[FS_VA + vi1]);
                sm[FS_VA + vi0] = f16pk(a0 * u0.x, a1 * u0.y);
                sm[FS_VA + vi1] = f16pk(a2 * u1.x, a3 * u1.y);
            } else if (EPI == 2) {
                float2 u0 = upk(sm[FS_VA + vi0]), u1 = upk(sm[FS_VA + vi1]);
                sm[FS_VA + vi0] = f16pk(u0.x + a0, u0.y + a1);
                sm[FS_VA + vi1] = f16pk(u1.x + a2, u1.y + a3);
            } else {
                const float* om = (const float*)(sm + FS_OM);
                float o0 = om[row0 * 36 + (col >> 3)];
                float o1 = om[(row0 + 8) * 36 + (col >> 3)];
                float w00 = o0 * a0, w01 = o0 * a1;
                float w10 = o1 * a2, w11 = o1 * a3;
                g_we16[(size_t)(rowBase + row0) * 128 + (col >> 1)]     = f16pk(w00, w01);
                g_we16[(size_t)(rowBase + row0 + 8) * 128 + (col >> 1)] = f16pk(w10, w11);
                csum[nt * 2]     += w00 + w10;
                csum[nt * 2 + 1] += w01 + w11;
                csq[nt * 2]      += w00 * w00 + w10 * w10;
                csq[nt * 2 + 1]  += w01 * w01 + w11 * w11;
            }
        }
    }
    if (EPI == 3) {
#pragma unroll
        for (int j = 0; j < 8; j++) {
#pragma unroll
            for (int off = 4; off < 32; off <<= 1) {
                csum[j] += __shfl_xor_sync(0xffffffffu, csum[j], off);
                csq[j]  += __shfl_xor_sync(0xffffffffu, csq[j],  off);
            }
        }
        if (lg == 0) {
#pragma unroll
            for (int u = 0; u < 8; u++) {
                int nt = u >> 1, uu = u & 1;
                int col = w * 32 + nt * 8 + 2 * la3 + uu;
                g_part2[(size_t)blockId * 512 + col]       = csum[u];
                g_part2[(size_t)blockId * 512 + 256 + col] = csq[u];
            }
        }
        __syncthreads();
    } else {
        __syncthreads();
    }
}

__global__ void __launch_bounds__(256, 2)
fused_kernel(const float* __restrict__ nf, const float* __restrict__ pts,
             const float* __restrict__ nbr,
             const float* __restrict__ k_b, const float* __restrict__ dm_b2,
             const float* __restrict__ db_b2, const float* __restrict__ v_b,
             const float* __restrict__ convw) {
    extern __shared__ uint32_t sm[];
    float* fx = (float*)(sm + FS_FX);
    int tid = threadIdx.x;
    int rowBase = blockIdx.x * 64;

    fx[FXF_KB + tid]  = k_b[tid];
    fx[FXF_DMB + tid] = dm_b2[tid];
    fx[FXF_DBB + tid] = db_b2[tid];
    fx[FXF_VB + tid]  = v_b[tid];
    fx[FXF_B1F + tid]       = g_b1f[0][tid];
    fx[FXF_B1F + 256 + tid] = g_b1f[1][tid];
    for (int i = tid; i < 1024; i += 256) fx[FXF_CW + i] = convw[i];
    for (int i = tid; i < 768; i += 256) {
        fx[FXF_W1F + i]       = g_w1f[0][i];
        fx[FXF_W1F + 768 + i] = g_w1f[1][i];
    }
    if (tid < 64) {
        int r = rowBase + tid, bn = r >> 4;
        fx[FXF_DIFF + tid * 4 + 0] = pts[bn * 3 + 0] - nbr[(size_t)r * 3 + 0];
        fx[FXF_DIFF + tid * 4 + 1] = pts[bn * 3 + 1] - nbr[(size_t)r * 3 + 1];
        fx[FXF_DIFF + tid * 4 + 2] = pts[bn * 3 + 2] - nbr[(size_t)r * 3 + 2];
    }
    {
        int bnb = rowBase >> 4;
        for (int i = tid; i < 512; i += 256) sm[FS_Q + i] = g_q16[bnb * 128 + i];
    }
    __syncthreads();

    const uint32_t* BK  = g_Bpk + 1 * 32768;
    const uint32_t* BV  = g_Bpk + 2 * 32768;
    const uint32_t* BDM = g_Bpk + 3 * 32768;
    const uint32_t* BDB = g_Bpk + 4 * 32768;
    const float* diff_s = fx + FXF_DIFF;

    run_subpass<0, false>(sm, tid, rowBase, nf, BK,  fx + FXF_KB,  nullptr, nullptr, diff_s, blockIdx.x);
    run_subpass<1, true >(sm, tid, rowBase, nf, BDM, fx + FXF_DMB, fx + FXF_W1F,       fx + FXF_B1F,       diff_s, blockIdx.x);
    run_subpass<2, true >(sm, tid, rowBase, nf, BDB, fx + FXF_DBB, fx + FXF_W1F + 768, fx + FXF_B1F + 256, diff_s, blockIdx.x);

    // ---- attention: va -> omega ----
    __syncthreads();
    {
        int l = tid & 31, w = tid >> 5;
        float cwr[32];
#pragma unroll
        for (int i = 0; i < 32; i++)
            cwr[i] = fx[FXF_CW + (l >> 2) * 128 + (l & 3) * 32 + i];
        float* om = (float*)(sm + FS_OM);
        int gb = (l >> 2) * 16;
        for (int it = 0; it < 8; it++) {
            int row = w * 8 + it;
            const uint32_t* vrow = sm + FS_VA + row * 132;
            float acc = 0.f;
#pragma unroll
            for (int t = 0; t < 16; t += 2) {
                uint2 u = *(const uint2*)&vrow[gb + t];
                float2 f0 = upk(u.x), f1 = upk(u.y);
                int i0 = t * 2;
                acc = fmaf(f0.x, cwr[i0], acc);
                acc = fmaf(f0.y, cwr[i0 + 1], acc);
                acc = fmaf(f1.x, cwr[i0 + 2], acc);
                acc = fmaf(f1.y, cwr[i0 + 3], acc);
            }
            float mx = acc;
#pragma unroll
            for (int off = 16; off > 0; off >>= 1)
                mx = fmaxf(mx, __shfl_xor_sync(0xffffffffu, mx, off));
            float e = expf(acc - mx);
            float ss = e;
#pragma unroll
            for (int off = 16; off > 0; off >>= 1)
                ss += __shfl_xor_sync(0xffffffffu, ss, off);
            om[row * 36 + l] = e / ss;
        }
    }
    __syncthreads();

    run_subpass<3, false>(sm, tid, rowBase, nf, BV, fx + FXF_VB, nullptr, nullptr, diff_s, blockIdx.x);
}

// --------------------------- BN2 reductions --------------------------------
__global__ void reduce_part2() {          // grid 64, block 256
    int b = blockIdx.x, tid = threadIdx.x;
    for (int c = tid; c < 512; c += 256) {
        float s = 0.f;
#pragma unroll 8
        for (int i = 0; i < 64; i++)
            s += g_part2[(size_t)(b * 64 + i) * 512 + c];
        g_part2r[b * 512 + c] = s;
    }
}

__global__ void finalize2_kernel(const float* __restrict__ bn_g,
                                 const float* __restrict__ bn_b) {
    int c = threadIdx.x;
    float s = 0.f, sq = 0.f;
    for (int b = 0; b < 64; b++) {
        s  += g_part2r[b * 512 + c];
        sq += g_part2r[b * 512 + 256 + c];
    }
    float mean = s / (float)R_;
    float var = sq / (float)R_ - mean * mean;
    float sc = bn_g[c] * rsqrtf(var + EPSV);
    g_s2[c] = sc;
    g_t2[c] = bn_b[c] - mean * sc;
}

// ------------------------------- launch -------------------------------------
extern "C" void kernel_launch(void* const* d_in, const int* in_sizes, int n_in,
                              void* d_out, int out_size) {
    const float* pts   = (const float*)d_in[0];
    const float* pf    = (const float*)d_in[1];
    const float* nbr   = (const float*)d_in[2];
    const float* nf    = (const float*)d_in[3];
    const float* dm_w1 = (const float*)d_in[4];
    const float* dm_b1 = (const float*)d_in[5];
    const float* dm_w2 = (const float*)d_in[6];
    const float* dm_b2 = (const float*)d_in[7];
    const float* dm_g  = (const float*)d_in[8];
    const float* dm_be = (const float*)d_in[9];
    const float* db_w1 = (const float*)d_in[10];
    const float* db_b1 = (const float*)d_in[11];
    const float* db_w2 = (const float*)d_in[12];
    const float* db_b2 = (const float*)d_in[13];
    const float* db_g  = (const float*)d_in[14];
    const float* db_be = (const float*)d_in[15];
    const float* q_w   = (const float*)d_in[16];
    const float* q_b   = (const float*)d_in[17];
    const float* k_w   = (const float*)d_in[18];
    const float* k_b   = (const float*)d_in[19];
    const float* v_w   = (const float*)d_in[20];
    const float* v_b   = (const float*)d_in[21];
    const float* convw = (const float*)d_in[22];
    const float* bn_g  = (const float*)d_in[23];
    const float* bn_b  = (const float*)d_in[24];
    const float* lin_w = (const float*)d_in[25];
    const float* lin_b = (const float*)d_in[26];
    float* out = (float*)d_out;

    void *p_q, *p_we, *p_bpk;
    cudaGetSymbolAddress(&p_q,   g_q16);
    cudaGetSymbolAddress(&p_we,  g_we16);
    cudaGetSymbolAddress(&p_bpk, g_Bpk);
    const uint32_t* Bpk = (const uint32_t*)p_bpk;

    cudaFuncSetAttribute(gemm_q,
                         cudaFuncAttributeMaxDynamicSharedMemorySize, G_DYN_SMEM);
    cudaFuncSetAttribute(gemm_final,
                         cudaFuncAttributeMaxDynamicSharedMemorySize, P_DYN_SMEM);
    cudaFuncSetAttribute(fused_kernel,
                         cudaFuncAttributeMaxDynamicSharedMemorySize, FUSED_SMEM);

    prep_weights<<<dim3(8, 2, 6), 256>>>(q_w, k_w, v_w, dm_w2, db_w2, lin_w);
    diffstats_kernel<<<STAT_BLOCKS, 256>>>(pts, nbr);
    fold_kernel<<<1, 256>>>(dm_w1, dm_b1, dm_g, dm_be, db_w1, db_b1, db_g, db_be);

    gemm_q<<<BNp / 64, 256, G_DYN_SMEM>>>(pf, Bpk + 0 * 32768, q_b,
                                          (uint32_t*)p_q);

    fused_kernel<<<NTILES, 256, FUSED_SMEM>>>(nf, pts, nbr,
                                              k_b, dm_b2, db_b2, v_b, convw);

    reduce_part2<<<64, 256>>>();
    finalize2_kernel<<<1, 256>>>(bn_g, bn_b);

    gemm_final<<<PGRID, 512, P_DYN_SMEM>>>((const uint32_t*)p_we,
                                           Bpk + 5 * 32768, lin_b, out);
}